// round 10
// baseline (speedup 1.0000x reference)
#include <cuda_runtime.h>
#include <cuda_fp16.h>
#include <mma.h>
#include <math.h>

using namespace nvcuda;

#define NFEAT 16
#define EFEAT 8
#define HC    256
#define NCLS  4

static const int MAXN = 50000;
static const int NPAD = 50048;
static const int MAXE = 800000;

typedef wmma::fragment<wmma::matrix_a, 16, 16, 16, __half, wmma::row_major> HFragA;
typedef wmma::fragment<wmma::matrix_b, 16, 16, 16, __half, wmma::row_major> HFragB;
typedef wmma::fragment<wmma::accumulator, 16, 16, 16, float> HFragC;

// ---------------- scratch ----------------
__device__ float  g_x1  [MAXN * 64];
__device__ float  g_q   [NPAD * HC];
__device__ __half g_kh  [NPAD * HC];
__device__ __half g_vh  [NPAD * HC];
__device__ float  g_skip[NPAD * HC];
__device__ float  g_g   [MAXN * HC];
__device__ float  g_qb  [MAXN * 4];
__device__ __half g_eh  [MAXE * 64];
__device__ float  g_outv[MAXN * HC];
__device__ float  g_t   [MAXN * HC];
__device__ float  g_suma[MAXN * 4];
__device__ float  g_wtt [HC * 64];
__device__ int    g_deg [MAXN];
__device__ int    g_rowptr[MAXN + 1];
__device__ int    g_cursor[MAXN];
__device__ int    g_eid [MAXE];
__device__ int    g_src [MAXE];
__device__ int    g_part[256];
__device__ int    g_partoff[256];

// ---------------- CSR build ----------------
__global__ void k_zero_deg(int n) {
    int i = blockIdx.x * blockDim.x + threadIdx.x;
    if (i < n) g_deg[i] = 0;
}
__global__ void k_hist(const int* __restrict__ ei, int e) {
    int i = blockIdx.x * blockDim.x + threadIdx.x;
    if (i < e) atomicAdd(&g_deg[ei[e + i]], 1);
}
// parallel scan: block sums
__global__ void k_blocksum(int n) {
    __shared__ int sh[256];
    int tid = threadIdx.x;
    int i = blockIdx.x * 256 + tid;
    sh[tid] = (i < n) ? g_deg[i] : 0;
    __syncthreads();
    for (int off = 128; off; off >>= 1) {
        if (tid < off) sh[tid] += sh[tid + off];
        __syncthreads();
    }
    if (tid == 0) g_part[blockIdx.x] = sh[0];
}
// scan the partials (1 block; nb <= 256)
__global__ void k_scanpart(int nb) {
    __shared__ int sh[256];
    int tid = threadIdx.x;
    int v = (tid < nb) ? g_part[tid] : 0;
    sh[tid] = v;
    __syncthreads();
    for (int off = 1; off < 256; off <<= 1) {
        int y = (tid >= off) ? sh[tid - off] : 0;
        __syncthreads();
        sh[tid] += y;
        __syncthreads();
    }
    g_partoff[tid] = sh[tid] - v;
}
// per-block scan + offsets -> rowptr, cursor
__global__ void k_scanfinal(int n) {
    __shared__ int sh[256];
    int tid = threadIdx.x;
    int i = blockIdx.x * 256 + tid;
    int v = (i < n) ? g_deg[i] : 0;
    sh[tid] = v;
    __syncthreads();
    for (int off = 1; off < 256; off <<= 1) {
        int y = (tid >= off) ? sh[tid - off] : 0;
        __syncthreads();
        sh[tid] += y;
        __syncthreads();
    }
    int base = g_partoff[blockIdx.x];
    if (i < n) {
        int incl = base + sh[tid];
        g_rowptr[i + 1] = incl;
        g_cursor[i]     = incl - v;
    }
    if (i == 0) g_rowptr[0] = 0;
}
__global__ void k_scatter(const int* __restrict__ ei, int e) {
    int i = blockIdx.x * blockDim.x + threadIdx.x;
    if (i < e) {
        int dst = ei[e + i];
        int pos = atomicAdd(&g_cursor[dst], 1);
        g_eid[pos] = i;
        g_src[pos] = ei[i];
    }
}

// ---------------- wedge transpose (one-time, tiny) ----------------
__global__ void k_wtt(const float* __restrict__ wedge) {
    int idx = blockIdx.x * 256 + threadIdx.x;
    int cg = idx >> 6, ii = idx & 63;
    g_wtt[cg * 64 + ii] = wedge[ii * HC + cg];
}

// ---------------- node embed ----------------
__global__ void k_node_embed(const float* __restrict__ x,
                             const float* __restrict__ w00,
                             const float* __restrict__ b00, int n) {
    __shared__ float ws[NFEAT * 64];
    __shared__ float xs[64][NFEAT];
    int tid = threadIdx.x;
    for (int i = tid; i < NFEAT * 64; i += 256) ws[i] = w00[i];
    int nb = blockIdx.x * 64;
    for (int i = tid; i < 64 * NFEAT; i += 256) {
        int nn = nb + i / NFEAT;
        xs[i / NFEAT][i % NFEAT] = (nn < n) ? x[nn * NFEAT + (i % NFEAT)] : 0.f;
    }
    __syncthreads();
    int ln = tid >> 2;
    int node = nb + ln;
    int c0 = (tid & 3) * 16;
    if (node < n) {
        #pragma unroll
        for (int j = 0; j < 16; j++) {
            float acc = __ldg(&b00[c0 + j]);
            #pragma unroll
            for (int i = 0; i < NFEAT; i++) acc += xs[ln][i] * ws[i * 64 + c0 + j];
            g_x1[node * 64 + c0 + j] = fmaxf(acc, 0.f);
        }
    }
}

// ---------------- projections: fp16 wmma; k/v stored as fp16 --------------
__global__ void k_proj(const float* __restrict__ W0, const float* __restrict__ B0,
                       const float* __restrict__ W1, const float* __restrict__ B1,
                       const float* __restrict__ W2, const float* __restrict__ B2,
                       const float* __restrict__ W3, const float* __restrict__ B3,
                       int n) {
    int sel = blockIdx.y;
    const float* W = (sel == 0) ? W0 : (sel == 1) ? W1 : (sel == 2) ? W2 : W3;
    const float* B = (sel == 0) ? B0 : (sel == 1) ? B1 : (sel == 2) ? B2 : B3;
    bool half_out = (sel == 1 || sel == 2);
    float*  outf = (sel == 0) ? g_q : g_skip;
    __half* outh = (sel == 1) ? g_kh : g_vh;

    extern __shared__ __half smh[];
    __half* xsh = smh;            // [64][88]
    __half* wsh = smh + 5632;     // [80][264]
    __shared__ float fbp[8][256];

    int tid = threadIdx.x;
    int nb = blockIdx.x * 64;

    for (int i = tid; i < 64 * 88; i += 256) {
        int r = i / 88, c = i - r * 88;
        float v = 0.f;
        if (c < 64) {
            int node = nb + r;
            if (node < n) v = __ldg(&g_x1[node * 64 + c]);
        } else if (c == 64) v = 1.0f;
        xsh[i] = __float2half(v);
    }
    for (int i = tid; i < 80 * 264; i += 256) {
        int r = i / 264, c = i - r * 264;
        float v = 0.f;
        if (c < 256) {
            if (r < 64) v = __ldg(&W[r * 256 + c]);
            else if (r == 64) v = __ldg(&B[c]);
        }
        wsh[i] = __float2half(v);
    }
    __syncthreads();

    int w = tid >> 5, lane = tid & 31;
    int rt = w >> 1;
    int ch = w & 1;

    HFragA a[5];
    #pragma unroll
    for (int k = 0; k < 5; k++)
        wmma::load_matrix_sync(a[k], &xsh[rt * 16 * 88 + k * 16], 88);

    #pragma unroll
    for (int nf = 0; nf < 8; nf++) {
        int c0 = ch * 128 + nf * 16;
        HFragC acc;
        wmma::fill_fragment(acc, 0.f);
        #pragma unroll
        for (int k = 0; k < 5; k++) {
            HFragB b;
            wmma::load_matrix_sync(b, &wsh[k * 16 * 264 + c0], 264);
            wmma::mma_sync(acc, a[k], b, acc);
        }
        if (!half_out) {
            wmma::store_matrix_sync(&outf[(nb + rt * 16) * HC + c0], acc, HC, wmma::mem_row_major);
        } else {
            wmma::store_matrix_sync(&fbp[w][0], acc, 16, wmma::mem_row_major);
            __syncwarp();
            int r = lane >> 1, cf = (lane & 1) * 8;
            const float* src = &fbp[w][r * 16 + cf];
            __half hb[8];
            #pragma unroll
            for (int j = 0; j < 8; j++) hb[j] = __float2half(src[j]);
            *(uint4*)&outh[(nb + rt * 16 + r) * HC + c0 + cf] = *(uint4*)hb;
            __syncwarp();
        }
    }
}

// ---------------- g = per-head wedge^T @ q (coalesced via g_wtt) -----------
__global__ void k_g(const float* __restrict__ bedge, int n) {
    __shared__ float qs[32 * HC];
    int tid = threadIdx.x;
    int nb = blockIdx.x * 32;
    for (int i = tid; i < 2048; i += 256) {
        int row = i >> 6, q4 = i & 63;
        int node = nb + row;
        float4 v = make_float4(0.f, 0.f, 0.f, 0.f);
        if (node < n) v = *(const float4*)&g_q[node * HC + q4 * 4];
        *(float4*)&qs[row * HC + q4 * 4] = v;
    }
    __syncthreads();
    int h = tid >> 6, ii = tid & 63;
    float acc[32];
    #pragma unroll
    for (int m = 0; m < 32; m++) acc[m] = 0.f;
    for (int c = 0; c < 64; c++) {
        float w = __ldg(&g_wtt[(h * 64 + c) * 64 + ii]);
        #pragma unroll
        for (int m = 0; m < 32; m++) acc[m] += qs[m * HC + h * 64 + c] * w;
    }
    #pragma unroll
    for (int m = 0; m < 32; m++) {
        int nn = nb + m;
        if (nn < n) g_g[nn * HC + tid] = acc[m];
    }
    if (tid < 128) {
        int m = tid >> 2, h2 = tid & 3;
        int nn = nb + m;
        if (nn < n) {
            float s = 0.f;
            for (int c = 0; c < 64; c++) s += qs[m * HC + h2 * 64 + c] * __ldg(&bedge[h2 * 64 + c]);
            g_qb[nn * 4 + h2] = s;
        }
    }
}

// ---------------- edge MLP: 256 edges/block, per-warp pipeline, no syncs ---
// smem bytes: es [256][16] h      @0       8192
//             w1b [16][72] h      @8192    2304
//             w2b [80][72] h      @10496   11520
//             w3b [80][72] h      @22016   11520
//             per-warp (x8)       @33536   7424 each = { fb 16x72 f32 (4608) ; hb 16x88 h (2816) }
// total 92928 bytes
__global__ void k_edgemlp(const float* __restrict__ eattr,
                          const float* __restrict__ we1, const float* __restrict__ be1,
                          const float* __restrict__ we2, const float* __restrict__ be2,
                          const float* __restrict__ we3, const float* __restrict__ be3,
                          int e) {
    extern __shared__ __align__(16) char smc[];
    __half* es  = (__half*)smc;
    __half* w1b = (__half*)(smc + 8192);
    __half* w2b = (__half*)(smc + 10496);
    __half* w3b = (__half*)(smc + 22016);

    int tid = threadIdx.x, w = tid >> 5, lane = tid & 31;
    float*  fb = (float*)(smc + 33536 + w * 7424);
    __half* hb = (__half*)(smc + 33536 + w * 7424 + 4608);

    int pb = blockIdx.x * 256;

    for (int i = tid; i < 1152; i += 256) {
        int r = i / 72, c = i - r * 72;
        float v = 0.f;
        if (c < 64) v = (r < 8) ? __ldg(&we1[r * 64 + c]) : ((r == 8) ? __ldg(&be1[c]) : 0.f);
        w1b[i] = __float2half(v);
    }
    for (int i = tid; i < 5760; i += 256) {
        int r = i / 72, c = i - r * 72;
        float v2 = 0.f, v3 = 0.f;
        if (c < 64) {
            if (r < 64)      { v2 = __ldg(&we2[r * 64 + c]); v3 = __ldg(&we3[r * 64 + c]); }
            else if (r == 64){ v2 = __ldg(&be2[c]);          v3 = __ldg(&be3[c]); }
        }
        w2b[i] = __float2half(v2);
        w3b[i] = __float2half(v3);
    }
    for (int i = tid; i < 4096; i += 256) {
        int r = i >> 4, c = i & 15;
        float v = 0.f;
        if (c < 8) {
            int p = pb + r;
            if (p < e) v = __ldg(&eattr[g_eid[p] * 8 + c]);
        } else if (c == 8) v = 1.0f;
        es[i] = __float2half(v);
    }
    // per-warp: bias cols 64..87 of hb (persist across layers & tiles)
    for (int i = lane; i < 16 * 24; i += 32) {
        int r = i / 24, c = 64 + (i - (i / 24) * 24);
        hb[r * 88 + c] = __float2half((c == 64) ? 1.0f : 0.f);
    }
    __syncthreads();

    #pragma unroll
    for (int t = 0; t < 2; t++) {
        int rowbase = (w * 2 + t) * 16;   // block-local edge row

        // ---- layer 1 (k=16) ----
        {
            HFragA a;
            wmma::load_matrix_sync(a, &es[rowbase * 16], 16);
            #pragma unroll
            for (int nf = 0; nf < 4; nf++) {
                HFragC acc;
                wmma::fill_fragment(acc, 0.f);
                HFragB b;
                wmma::load_matrix_sync(b, &w1b[nf * 16], 72);
                wmma::mma_sync(acc, a, b, acc);
                wmma::store_matrix_sync(&fb[nf * 16], acc, 72, wmma::mem_row_major);
            }
        }
        __syncwarp();
        for (int i = lane; i < 1024; i += 32) {
            int r = i >> 6, c = i & 63;
            hb[r * 88 + c] = __float2half(fmaxf(fb[r * 72 + c], 0.f));
        }
        __syncwarp();

        // ---- layer 2 (k=80) ----
        {
            HFragA a[5];
            #pragma unroll
            for (int k = 0; k < 5; k++)
                wmma::load_matrix_sync(a[k], &hb[k * 16], 88);
            #pragma unroll
            for (int nf = 0; nf < 4; nf++) {
                HFragC acc;
                wmma::fill_fragment(acc, 0.f);
                #pragma unroll
                for (int k = 0; k < 5; k++) {
                    HFragB b;
                    wmma::load_matrix_sync(b, &w2b[k * 16 * 72 + nf * 16], 72);
                    wmma::mma_sync(acc, a[k], b, acc);
                }
                wmma::store_matrix_sync(&fb[nf * 16], acc, 72, wmma::mem_row_major);
            }
        }
        __syncwarp();
        for (int i = lane; i < 1024; i += 32) {
            int r = i >> 6, c = i & 63;
            hb[r * 88 + c] = __float2half(fmaxf(fb[r * 72 + c], 0.f));
        }
        __syncwarp();

        // ---- layer 3 (k=80) -> relu -> fp16 g_eh ----
        {
            HFragA a[5];
            #pragma unroll
            for (int k = 0; k < 5; k++)
                wmma::load_matrix_sync(a[k], &hb[k * 16], 88);
            #pragma unroll
            for (int nf = 0; nf < 4; nf++) {
                HFragC acc;
                wmma::fill_fragment(acc, 0.f);
                #pragma unroll
                for (int k = 0; k < 5; k++) {
                    HFragB b;
                    wmma::load_matrix_sync(b, &w3b[k * 16 * 72 + nf * 16], 72);
                    wmma::mma_sync(acc, a[k], b, acc);
                }
                wmma::store_matrix_sync(&fb[nf * 16], acc, 72, wmma::mem_row_major);
            }
        }
        __syncwarp();
        {
            int grow = pb + rowbase;
            for (int i = lane * 2; i < 1024; i += 64) {
                int r = i >> 6, c = i & 63;
                if (grow + r < e) {
                    __half2 hv = __floats2half2_rn(fmaxf(fb[r * 72 + c], 0.f),
                                                   fmaxf(fb[r * 72 + c + 1], 0.f));
                    *(__half2*)&g_eh[(grow + r) * 64 + c] = hv;
                }
            }
        }
        __syncwarp();
    }
}

// ---------------- attention: warp per node, 4-edge unroll, v prefetch ------
__device__ __forceinline__ float dot4(float4 a, float4 b) {
    return a.x * b.x + a.y * b.y + a.z * b.z + a.w * b.w;
}
__device__ __forceinline__ void ldh8(const __half* p, float4& a, float4& b) {
    uint4 u = *(const uint4*)p;
    float2 f0 = __half22float2(*(__half2*)&u.x);
    float2 f1 = __half22float2(*(__half2*)&u.y);
    float2 f2 = __half22float2(*(__half2*)&u.z);
    float2 f3 = __half22float2(*(__half2*)&u.w);
    a = make_float4(f0.x, f0.y, f1.x, f1.y);
    b = make_float4(f2.x, f2.y, f3.x, f3.y);
}

__global__ void __launch_bounds__(256) k_attn(int n) {
    int gw = (blockIdx.x * blockDim.x + threadIdx.x) >> 5;
    int lane = threadIdx.x & 31;
    if (gw >= n) return;
    int node = gw;
    int beg = g_rowptr[node], end = g_rowptr[node + 1];

    int h = lane >> 3;
    int c8 = (lane & 7) * 8;
    int chan = h * 64 + c8;

    float4 q0 = *(const float4*)&g_q[node * HC + chan];
    float4 q1 = *(const float4*)&g_q[node * HC + chan + 4];
    float4 gg0 = *(const float4*)&g_g[node * HC + chan];
    float4 gg1 = *(const float4*)&g_g[node * HC + chan + 4];
    float qb = g_qb[node * 4 + h];

    float s = 0.f;
    float4 av0 = {0,0,0,0}, av1 = {0,0,0,0};
    float4 at0 = {0,0,0,0}, at1 = {0,0,0,0};

    int p = beg;
    for (; p + 4 <= end; p += 4) {
        int src[4];
        #pragma unroll
        for (int u = 0; u < 4; u++) src[u] = g_src[p + u];

        float d[4];
        float4 e0[4], e1[4], v0[4], v1[4];
        #pragma unroll
        for (int u = 0; u < 4; u++) {
            float4 k0, k1;
            ldh8(&g_kh[src[u] * HC + chan], k0, k1);
            ldh8(&g_eh[(p + u) * 64 + c8], e0[u], e1[u]);
            ldh8(&g_vh[src[u] * HC + chan], v0[u], v1[u]);
            d[u] = dot4(q0, k0) + dot4(q1, k1) + dot4(gg0, e0[u]) + dot4(gg1, e1[u]);
        }
        #pragma unroll
        for (int off = 1; off < 8; off <<= 1) {
            #pragma unroll
            for (int u = 0; u < 4; u++)
                d[u] += __shfl_xor_sync(0xffffffffu, d[u], off);
        }
        float pe[4];
        #pragma unroll
        for (int u = 0; u < 4; u++) {
            pe[u] = __expf((d[u] + qb) * 0.125f);
            s += pe[u];
        }
        #pragma unroll
        for (int u = 0; u < 4; u++) {
            av0.x += pe[u] * v0[u].x;  av0.y += pe[u] * v0[u].y;
            av0.z += pe[u] * v0[u].z;  av0.w += pe[u] * v0[u].w;
            av1.x += pe[u] * v1[u].x;  av1.y += pe[u] * v1[u].y;
            av1.z += pe[u] * v1[u].z;  av1.w += pe[u] * v1[u].w;
            at0.x += pe[u] * e0[u].x;  at0.y += pe[u] * e0[u].y;
            at0.z += pe[u] * e0[u].z;  at0.w += pe[u] * e0[u].w;
            at1.x += pe[u] * e1[u].x;  at1.y += pe[u] * e1[u].y;
            at1.z += pe[u] * e1[u].z;  at1.w += pe[u] * e1[u].w;
        }
    }
    for (; p < end; p++) {
        int src = g_src[p];
        float4 k0, k1, e0, e1, v0, v1;
        ldh8(&g_kh[src * HC + chan], k0, k1);
        ldh8(&g_eh[p * 64 + c8],     e0, e1);
        ldh8(&g_vh[src * HC + chan], v0, v1);
        float d = dot4(q0, k0) + dot4(q1, k1) + dot4(gg0, e0) + dot4(gg1, e1);
        d += __shfl_xor_sync(0xffffffffu, d, 1);
        d += __shfl_xor_sync(0xffffffffu, d, 2);
        d += __shfl_xor_sync(0xffffffffu, d, 4);
        float pe = __expf((d + qb) * 0.125f);
        s += pe;
        av0.x += pe * v0.x; av0.y += pe * v0.y; av0.z += pe * v0.z; av0.w += pe * v0.w;
        av1.x += pe * v1.x; av1.y += pe * v1.y; av1.z += pe * v1.z; av1.w += pe * v1.w;
        at0.x += pe * e0.x; at0.y += pe * e0.y; at0.z += pe * e0.z; at0.w += pe * e0.w;
        at1.x += pe * e1.x; at1.y += pe * e1.y; at1.z += pe * e1.z; at1.w += pe * e1.w;
    }

    float sinv = 1.f / (s + 1e-16f);
    float4 o0 = {av0.x * sinv, av0.y * sinv, av0.z * sinv, av0.w * sinv};
    float4 o1 = {av1.x * sinv, av1.y * sinv, av1.z * sinv, av1.w * sinv};
    float4 t0 = {at0.x * sinv, at0.y * sinv, at0.z * sinv, at0.w * sinv};
    float4 t1 = {at1.x * sinv, at1.y * sinv, at1.z * sinv, at1.w * sinv};
    *(float4*)&g_outv[node * HC + chan]     = o0;
    *(float4*)&g_outv[node * HC + chan + 4] = o1;
    *(float4*)&g_t   [node * HC + chan]     = t0;
    *(float4*)&g_t   [node * HC + chan + 4] = t1;
    if ((lane & 7) == 0) g_suma[node * 4 + h] = s * sinv;
}

// ---------------- fused epilogue: 32 nodes/block, dynamic smem -------------
// dyn smem floats: ts[32*256] @0, os[32*256] @8192, hs[32*128] @16384 (20480 floats = 81920 B)
__global__ void k_posthead(const float* __restrict__ wedge, const float* __restrict__ bedge,
                           const float* __restrict__ ln_g, const float* __restrict__ ln_b,
                           const float* __restrict__ w1, const float* __restrict__ b1,
                           const float* __restrict__ w2, const float* __restrict__ b2,
                           float* __restrict__ out, int n) {
    extern __shared__ float smf[];
    float* ts = smf;           // [32][256]
    float* os = smf + 8192;    // [32][256]
    float* hs = smf + 16384;   // [32][128]
    __shared__ float ls[32][NCLS];

    int tid = threadIdx.x;
    int nb = blockIdx.x * 32;
    for (int i = tid; i < 32 * HC; i += 256) {
        int nn = nb + (i >> 8);
        ts[i] = (nn < n) ? g_t[nn * HC + (i & 255)] : 0.f;
    }
    __syncthreads();

    // t @ wedge (per-head) + combine
    int h = tid >> 6;
    float acc[32];
    #pragma unroll
    for (int m = 0; m < 32; m++) acc[m] = 0.f;
    for (int i = 0; i < 64; i++) {
        float w = __ldg(&wedge[i * HC + tid]);
        #pragma unroll
        for (int m = 0; m < 32; m++) acc[m] += ts[m * HC + h * 64 + i] * w;
    }
    float be = __ldg(&bedge[tid]);
    #pragma unroll
    for (int m = 0; m < 32; m++) {
        int nn = nb + m;
        if (nn < n) {
            os[m * HC + tid] = g_outv[nn * HC + tid] + g_suma[nn * 4 + h] * be
                             + g_skip[nn * HC + tid] + acc[m];
        }
    }
    __syncthreads();

    // LayerNorm + relu -> ts (reuse)
    int wid = tid >> 5, lane = tid & 31;
    for (int m = wid; m < 32; m += 8) {
        int nn = nb + m;
        if (nn >= n) continue;
        float sum = 0.f, sq = 0.f;
        #pragma unroll
        for (int u = 0; u < 8; u++) {
            float v = os[m * HC + u * 32 + lane];
            sum += v; sq += v * v;
        }
        #pragma unroll
        for (int off = 16; off; off >>= 1) {
            sum += __shfl_xor_sync(0xffffffffu, sum, off);
            sq  += __shfl_xor_sync(0xffffffffu, sq,  off);
        }
        float mu = sum * (1.f / 256.f);
        float var = sq * (1.f / 256.f) - mu * mu;
        float rs = rsqrtf(var + 1e-5f);
        #pragma unroll
        for (int u = 0; u < 8; u++) {
            int j = u * 32 + lane;
            float v = (os[m * HC + j] - mu) * rs * __ldg(&ln_g[j]) + __ldg(&ln_b[j]);
            ts[m * HC + j] = fmaxf(v, 0.f);
        }
    }
    __syncthreads();

    // head layer 1: [32 x 256] @ [256 x 128]
    {
        int col = tid & 127, rg = tid >> 7;   // rows rg*16 .. rg*16+15
        float a16[16];
        float bb = __ldg(&b1[col]);
        #pragma unroll
        for (int r = 0; r < 16; r++) a16[r] = bb;
        for (int i = 0; i < HC; i++) {
            float w = __ldg(&w1[i * 128 + col]);
            #pragma unroll
            for (int r = 0; r < 16; r++) a16[r] += ts[(rg * 16 + r) * HC + i] * w;
        }
        #pragma unroll
        for (int r = 0; r < 16; r++) hs[(rg * 16 + r) * 128 + col] = fmaxf(a16[r], 0.f);
    }
    __syncthreads();

    // head layer 2 + log_softmax
    if (tid < 128) {
        int m = tid >> 2, c = tid & 3;
        float a = __ldg(&b2[c]);
        for (int i = 0; i < 128; i++) a += hs[m * 128 + i] * __ldg(&w2[i * NCLS + c]);
        ls[m][c] = a;
    }
    __syncthreads();
    if (tid < 32) {
        int nn = nb + tid;
        if (nn < n) {
            float l0 = ls[tid][0], l1 = ls[tid][1], l2 = ls[tid][2], l3 = ls[tid][3];
            float mx = fmaxf(fmaxf(l0, l1), fmaxf(l2, l3));
            float se = expf(l0 - mx) + expf(l1 - mx) + expf(l2 - mx) + expf(l3 - mx);
            float lse = mx + logf(se);
            out[nn * NCLS + 0] = l0 - lse;
            out[nn * NCLS + 1] = l1 - lse;
            out[nn * NCLS + 2] = l2 - lse;
            out[nn * NCLS + 3] = l3 - lse;
        }
    }
}

// ---------------- launcher ----------------
extern "C" void kernel_launch(void* const* d_in, const int* in_sizes, int n_in,
                              void* d_out, int out_size) {
    const float* x     = (const float*)d_in[0];
    const int*   ei    = (const int*)  d_in[1];
    const float* eattr = (const float*)d_in[2];
    const float* w00   = (const float*)d_in[3];
    const float* b00   = (const float*)d_in[4];
    const float* we1   = (const float*)d_in[5];
    const float* be1   = (const float*)d_in[6];
    const float* we2   = (const float*)d_in[7];
    const float* be2   = (const float*)d_in[8];
    const float* we3   = (const float*)d_in[9];
    const float* be3   = (const float*)d_in[10];
    const float* wq    = (const float*)d_in[11];
    const float* bq    = (const float*)d_in[12];
    const float* wk    = (const float*)d_in[13];
    const float* bk    = (const float*)d_in[14];
    const float* wv    = (const float*)d_in[15];
    const float* bv    = (const float*)d_in[16];
    const float* wedge = (const float*)d_in[17];
    const float* bedge = (const float*)d_in[18];
    const float* wskip = (const float*)d_in[19];
    const float* bskip = (const float*)d_in[20];
    const float* ln_g  = (const float*)d_in[21];
    const float* ln_b  = (const float*)d_in[22];
    const float* w1    = (const float*)d_in[23];
    const float* b1    = (const float*)d_in[24];
    const float* w2    = (const float*)d_in[25];
    const float* b2    = (const float*)d_in[26];
    float* out = (float*)d_out;

    int n = in_sizes[0] / NFEAT;
    int e = in_sizes[1] / 2;
    int nb = (n + 255) / 256;

    static const int EDGE_SMEM = 92928;
    static const int PROJ_SMEM = (5632 + 21120) * 2;
    static const int POST_SMEM = 20480 * 4;
    cudaFuncSetAttribute(k_edgemlp,  cudaFuncAttributeMaxDynamicSharedMemorySize, EDGE_SMEM);
    cudaFuncSetAttribute(k_proj,     cudaFuncAttributeMaxDynamicSharedMemorySize, PROJ_SMEM);
    cudaFuncSetAttribute(k_posthead, cudaFuncAttributeMaxDynamicSharedMemorySize, POST_SMEM);

    k_zero_deg<<<(n + 255) / 256, 256>>>(n);
    k_hist<<<(e + 255) / 256, 256>>>(ei, e);
    k_blocksum<<<nb, 256>>>(n);
    k_scanpart<<<1, 256>>>(nb);
    k_scanfinal<<<nb, 256>>>(n);
    k_scatter<<<(e + 255) / 256, 256>>>(ei, e);
    k_wtt<<<64, 256>>>(wedge);

    k_node_embed<<<(n + 63) / 64, 256>>>(x, w00, b00, n);
    {
        dim3 grid((n + 63) / 64, 4);
        k_proj<<<grid, 256, PROJ_SMEM>>>(wq, bq, wk, bk, wv, bv, wskip, bskip, n);
    }
    k_g<<<(n + 31) / 32, 256>>>(bedge, n);

    k_edgemlp<<<(e + 255) / 256, 256, EDGE_SMEM>>>(eattr, we1, be1, we2, be2, we3, be3, e);

    k_attn<<<(n + 7) / 8, 256>>>(n);

    k_posthead<<<(n + 31) / 32, 256, POST_SMEM>>>(wedge, bedge, ln_g, ln_b, w1, b1, w2, b2, out, n);
}

// round 11
// speedup vs baseline: 1.0886x; 1.0886x over previous
#include <cuda_runtime.h>
#include <cuda_fp16.h>
#include <mma.h>
#include <math.h>

using namespace nvcuda;

#define NFEAT 16
#define EFEAT 8
#define HC    256
#define NCLS  4

static const int MAXN = 50000;
static const int NPAD = 50048;
static const int MAXE = 800000;

typedef wmma::fragment<wmma::matrix_a, 16, 16, 16, __half, wmma::row_major> HFragA;
typedef wmma::fragment<wmma::matrix_b, 16, 16, 16, __half, wmma::row_major> HFragB;
typedef wmma::fragment<wmma::accumulator, 16, 16, 16, float> HFragC;

// ---------------- scratch ----------------
__device__ float  g_x1  [MAXN * 64];
__device__ float  g_q   [NPAD * HC];
__device__ __half g_kh  [NPAD * HC];
__device__ __half g_vh  [NPAD * HC];
__device__ float  g_skip[NPAD * HC];
__device__ float  g_g   [MAXN * HC];
__device__ float  g_qb  [MAXN * 4];
__device__ __half g_eh  [MAXE * 64];
__device__ float  g_outv[MAXN * HC];
__device__ float  g_t   [MAXN * HC];
__device__ float  g_suma[MAXN * 4];
__device__ float  g_wtt [HC * 64];
__device__ int    g_deg [MAXN];
__device__ int    g_rowptr[MAXN + 1];
__device__ int    g_cursor[MAXN];
__device__ int    g_eid [MAXE];
__device__ int    g_src [MAXE];
__device__ int    g_part[256];
__device__ int    g_partoff[256];

// ---------------- CSR build ----------------
__global__ void k_zero_deg(int n) {
    int i = blockIdx.x * blockDim.x + threadIdx.x;
    if (i < n) g_deg[i] = 0;
}
__global__ void k_hist(const int* __restrict__ ei, int e) {
    int i = blockIdx.x * blockDim.x + threadIdx.x;
    if (i < e) atomicAdd(&g_deg[ei[e + i]], 1);
}
// parallel scan: block sums
__global__ void k_blocksum(int n) {
    __shared__ int sh[256];
    int tid = threadIdx.x;
    int i = blockIdx.x * 256 + tid;
    sh[tid] = (i < n) ? g_deg[i] : 0;
    __syncthreads();
    for (int off = 128; off; off >>= 1) {
        if (tid < off) sh[tid] += sh[tid + off];
        __syncthreads();
    }
    if (tid == 0) g_part[blockIdx.x] = sh[0];
}
// scan the partials (1 block; nb <= 256)
__global__ void k_scanpart(int nb) {
    __shared__ int sh[256];
    int tid = threadIdx.x;
    int v = (tid < nb) ? g_part[tid] : 0;
    sh[tid] = v;
    __syncthreads();
    for (int off = 1; off < 256; off <<= 1) {
        int y = (tid >= off) ? sh[tid - off] : 0;
        __syncthreads();
        sh[tid] += y;
        __syncthreads();
    }
    g_partoff[tid] = sh[tid] - v;
}
// per-block scan + offsets -> rowptr, cursor
__global__ void k_scanfinal(int n) {
    __shared__ int sh[256];
    int tid = threadIdx.x;
    int i = blockIdx.x * 256 + tid;
    int v = (i < n) ? g_deg[i] : 0;
    sh[tid] = v;
    __syncthreads();
    for (int off = 1; off < 256; off <<= 1) {
        int y = (tid >= off) ? sh[tid - off] : 0;
        __syncthreads();
        sh[tid] += y;
        __syncthreads();
    }
    int base = g_partoff[blockIdx.x];
    if (i < n) {
        int incl = base + sh[tid];
        g_rowptr[i + 1] = incl;
        g_cursor[i]     = incl - v;
    }
    if (i == 0) g_rowptr[0] = 0;
}
__global__ void k_scatter(const int* __restrict__ ei, int e) {
    int i = blockIdx.x * blockDim.x + threadIdx.x;
    if (i < e) {
        int dst = ei[e + i];
        int pos = atomicAdd(&g_cursor[dst], 1);
        g_eid[pos] = i;
        g_src[pos] = ei[i];
    }
}

// ---------------- wedge transpose (one-time, tiny) ----------------
__global__ void k_wtt(const float* __restrict__ wedge) {
    int idx = blockIdx.x * 256 + threadIdx.x;
    int cg = idx >> 6, ii = idx & 63;
    g_wtt[cg * 64 + ii] = wedge[ii * HC + cg];
}

// ---------------- node embed ----------------
__global__ void k_node_embed(const float* __restrict__ x,
                             const float* __restrict__ w00,
                             const float* __restrict__ b00, int n) {
    __shared__ float ws[NFEAT * 64];
    __shared__ float xs[64][NFEAT];
    int tid = threadIdx.x;
    for (int i = tid; i < NFEAT * 64; i += 256) ws[i] = w00[i];
    int nb = blockIdx.x * 64;
    for (int i = tid; i < 64 * NFEAT; i += 256) {
        int nn = nb + i / NFEAT;
        xs[i / NFEAT][i % NFEAT] = (nn < n) ? x[nn * NFEAT + (i % NFEAT)] : 0.f;
    }
    __syncthreads();
    int ln = tid >> 2;
    int node = nb + ln;
    int c0 = (tid & 3) * 16;
    if (node < n) {
        #pragma unroll
        for (int j = 0; j < 16; j++) {
            float acc = __ldg(&b00[c0 + j]);
            #pragma unroll
            for (int i = 0; i < NFEAT; i++) acc += xs[ln][i] * ws[i * 64 + c0 + j];
            g_x1[node * 64 + c0 + j] = fmaxf(acc, 0.f);
        }
    }
}

// ---------------- projections: fp16 wmma; k/v stored as fp16 --------------
__global__ void k_proj(const float* __restrict__ W0, const float* __restrict__ B0,
                       const float* __restrict__ W1, const float* __restrict__ B1,
                       const float* __restrict__ W2, const float* __restrict__ B2,
                       const float* __restrict__ W3, const float* __restrict__ B3,
                       int n) {
    int sel = blockIdx.y;
    const float* W = (sel == 0) ? W0 : (sel == 1) ? W1 : (sel == 2) ? W2 : W3;
    const float* B = (sel == 0) ? B0 : (sel == 1) ? B1 : (sel == 2) ? B2 : B3;
    bool half_out = (sel == 1 || sel == 2);
    float*  outf = (sel == 0) ? g_q : g_skip;
    __half* outh = (sel == 1) ? g_kh : g_vh;

    extern __shared__ __half smh[];
    __half* xsh = smh;            // [64][88]
    __half* wsh = smh + 5632;     // [80][264]
    __shared__ float fbp[8][256];

    int tid = threadIdx.x;
    int nb = blockIdx.x * 64;

    for (int i = tid; i < 64 * 88; i += 256) {
        int r = i / 88, c = i - r * 88;
        float v = 0.f;
        if (c < 64) {
            int node = nb + r;
            if (node < n) v = __ldg(&g_x1[node * 64 + c]);
        } else if (c == 64) v = 1.0f;
        xsh[i] = __float2half(v);
    }
    for (int i = tid; i < 80 * 264; i += 256) {
        int r = i / 264, c = i - r * 264;
        float v = 0.f;
        if (c < 256) {
            if (r < 64) v = __ldg(&W[r * 256 + c]);
            else if (r == 64) v = __ldg(&B[c]);
        }
        wsh[i] = __float2half(v);
    }
    __syncthreads();

    int w = tid >> 5, lane = tid & 31;
    int rt = w >> 1;
    int ch = w & 1;

    HFragA a[5];
    #pragma unroll
    for (int k = 0; k < 5; k++)
        wmma::load_matrix_sync(a[k], &xsh[rt * 16 * 88 + k * 16], 88);

    #pragma unroll
    for (int nf = 0; nf < 8; nf++) {
        int c0 = ch * 128 + nf * 16;
        HFragC acc;
        wmma::fill_fragment(acc, 0.f);
        #pragma unroll
        for (int k = 0; k < 5; k++) {
            HFragB b;
            wmma::load_matrix_sync(b, &wsh[k * 16 * 264 + c0], 264);
            wmma::mma_sync(acc, a[k], b, acc);
        }
        if (!half_out) {
            wmma::store_matrix_sync(&outf[(nb + rt * 16) * HC + c0], acc, HC, wmma::mem_row_major);
        } else {
            wmma::store_matrix_sync(&fbp[w][0], acc, 16, wmma::mem_row_major);
            __syncwarp();
            int r = lane >> 1, cf = (lane & 1) * 8;
            const float* src = &fbp[w][r * 16 + cf];
            __half hb[8];
            #pragma unroll
            for (int j = 0; j < 8; j++) hb[j] = __float2half(src[j]);
            *(uint4*)&outh[(nb + rt * 16 + r) * HC + c0 + cf] = *(uint4*)hb;
            __syncwarp();
        }
    }
}

// ---------------- g = per-head wedge^T @ q (coalesced via g_wtt) -----------
__global__ void k_g(const float* __restrict__ bedge, int n) {
    __shared__ float qs[32 * HC];
    int tid = threadIdx.x;
    int nb = blockIdx.x * 32;
    for (int i = tid; i < 2048; i += 256) {
        int row = i >> 6, q4 = i & 63;
        int node = nb + row;
        float4 v = make_float4(0.f, 0.f, 0.f, 0.f);
        if (node < n) v = *(const float4*)&g_q[node * HC + q4 * 4];
        *(float4*)&qs[row * HC + q4 * 4] = v;
    }
    __syncthreads();
    int h = tid >> 6, ii = tid & 63;
    float acc[32];
    #pragma unroll
    for (int m = 0; m < 32; m++) acc[m] = 0.f;
    for (int c = 0; c < 64; c++) {
        float w = __ldg(&g_wtt[(h * 64 + c) * 64 + ii]);
        #pragma unroll
        for (int m = 0; m < 32; m++) acc[m] += qs[m * HC + h * 64 + c] * w;
    }
    #pragma unroll
    for (int m = 0; m < 32; m++) {
        int nn = nb + m;
        if (nn < n) g_g[nn * HC + tid] = acc[m];
    }
    if (tid < 128) {
        int m = tid >> 2, h2 = tid & 3;
        int nn = nb + m;
        if (nn < n) {
            float s = 0.f;
            for (int c = 0; c < 64; c++) s += qs[m * HC + h2 * 64 + c] * __ldg(&bedge[h2 * 64 + c]);
            g_qb[nn * 4 + h2] = s;
        }
    }
}

// ---------------- edge MLP: fp16 wmma, 128 edges/block (R9 version) --------
__global__ void k_edgemlp(const float* __restrict__ eattr,
                          const float* __restrict__ we1, const float* __restrict__ be1,
                          const float* __restrict__ we2, const float* __restrict__ be2,
                          const float* __restrict__ we3, const float* __restrict__ be3,
                          int e) {
    extern __shared__ __half smh[];
    __half* es  = smh;
    __half* w1b = smh + 2048;
    __half* w2b = smh + 3200;
    __half* w3b = smh + 8960;
    __half* h1h = smh + 14720;
    __half* h2h = smh + 25984;
    float*  fb  = (float*)(smh + 37248);

    int tid = threadIdx.x;
    int pb = blockIdx.x * 128;

    for (int i = tid; i < 1152; i += 256) {
        int r = i / 72, c = i - r * 72;
        float v = 0.f;
        if (c < 64) v = (r < 8) ? __ldg(&we1[r * 64 + c]) : ((r == 8) ? __ldg(&be1[c]) : 0.f);
        w1b[i] = __float2half(v);
    }
    for (int i = tid; i < 5760; i += 256) {
        int r = i / 72, c = i - r * 72;
        float v2 = 0.f, v3 = 0.f;
        if (c < 64) {
            if (r < 64)      { v2 = __ldg(&we2[r * 64 + c]); v3 = __ldg(&we3[r * 64 + c]); }
            else if (r == 64){ v2 = __ldg(&be2[c]);          v3 = __ldg(&be3[c]); }
        }
        w2b[i] = __float2half(v2);
        w3b[i] = __float2half(v3);
    }
    for (int i = tid; i < 2048; i += 256) {
        int r = i >> 4, c = i & 15;
        float v = 0.f;
        if (c < 8) {
            int p = pb + r;
            if (p < e) v = __ldg(&eattr[g_eid[p] * 8 + c]);
        } else if (c == 8) v = 1.0f;
        es[i] = __float2half(v);
    }
    for (int i = tid; i < 3072; i += 256) {
        int r = i / 24, c = 64 + (i - r * 24);
        __half v = __float2half((c == 64) ? 1.0f : 0.f);
        h1h[r * 88 + c] = v;
        h2h[r * 88 + c] = v;
    }
    __syncthreads();

    int w = tid >> 5;

    // ---- layer 1 (k=16) ----
    {
        HFragA a;
        wmma::load_matrix_sync(a, &es[w * 16 * 16], 16);
        #pragma unroll
        for (int nf = 0; nf < 4; nf++) {
            HFragC acc;
            wmma::fill_fragment(acc, 0.f);
            HFragB b;
            wmma::load_matrix_sync(b, &w1b[nf * 16], 72);
            wmma::mma_sync(acc, a, b, acc);
            wmma::store_matrix_sync(&fb[w * 16 * 72 + nf * 16], acc, 72, wmma::mem_row_major);
        }
    }
    __syncthreads();
    for (int i = tid; i < 8192; i += 256) {
        int r = i >> 6, c = i & 63;
        h1h[r * 88 + c] = __float2half(fmaxf(fb[r * 72 + c], 0.f));
    }
    __syncthreads();

    // ---- layer 2 (k=80) ----
    {
        HFragA a[5];
        #pragma unroll
        for (int k = 0; k < 5; k++)
            wmma::load_matrix_sync(a[k], &h1h[w * 16 * 88 + k * 16], 88);
        #pragma unroll
        for (int nf = 0; nf < 4; nf++) {
            HFragC acc;
            wmma::fill_fragment(acc, 0.f);
            #pragma unroll
            for (int k = 0; k < 5; k++) {
                HFragB b;
                wmma::load_matrix_sync(b, &w2b[k * 16 * 72 + nf * 16], 72);
                wmma::mma_sync(acc, a[k], b, acc);
            }
            wmma::store_matrix_sync(&fb[w * 16 * 72 + nf * 16], acc, 72, wmma::mem_row_major);
        }
    }
    __syncthreads();
    for (int i = tid; i < 8192; i += 256) {
        int r = i >> 6, c = i & 63;
        h2h[r * 88 + c] = __float2half(fmaxf(fb[r * 72 + c], 0.f));
    }
    __syncthreads();

    // ---- layer 3 (k=80) -> relu -> fp16 g_eh ----
    {
        HFragA a[5];
        #pragma unroll
        for (int k = 0; k < 5; k++)
            wmma::load_matrix_sync(a[k], &h2h[w * 16 * 88 + k * 16], 88);
        #pragma unroll
        for (int nf = 0; nf < 4; nf++) {
            HFragC acc;
            wmma::fill_fragment(acc, 0.f);
            #pragma unroll
            for (int k = 0; k < 5; k++) {
                HFragB b;
                wmma::load_matrix_sync(b, &w3b[k * 16 * 72 + nf * 16], 72);
                wmma::mma_sync(acc, a[k], b, acc);
            }
            wmma::store_matrix_sync(&fb[w * 16 * 72 + nf * 16], acc, 72, wmma::mem_row_major);
        }
    }
    __syncthreads();
    {
        int nrows = min(128, e - pb);
        for (int i = tid * 2; i < nrows * 64; i += 512) {
            int r = i >> 6, c = i & 63;
            __half2 hv = __floats2half2_rn(fmaxf(fb[r * 72 + c], 0.f),
                                           fmaxf(fb[r * 72 + c + 1], 0.f));
            *(__half2*)&g_eh[(pb + r) * 64 + c] = hv;
        }
    }
}

// ---------------- attention: warp per node, 4-edge unroll, v prefetch ------
__device__ __forceinline__ float dot4(float4 a, float4 b) {
    return a.x * b.x + a.y * b.y + a.z * b.z + a.w * b.w;
}
__device__ __forceinline__ void ldh8(const __half* p, float4& a, float4& b) {
    uint4 u = *(const uint4*)p;
    float2 f0 = __half22float2(*(__half2*)&u.x);
    float2 f1 = __half22float2(*(__half2*)&u.y);
    float2 f2 = __half22float2(*(__half2*)&u.z);
    float2 f3 = __half22float2(*(__half2*)&u.w);
    a = make_float4(f0.x, f0.y, f1.x, f1.y);
    b = make_float4(f2.x, f2.y, f3.x, f3.y);
}

__global__ void __launch_bounds__(256) k_attn(int n) {
    int gw = (blockIdx.x * blockDim.x + threadIdx.x) >> 5;
    int lane = threadIdx.x & 31;
    if (gw >= n) return;
    int node = gw;
    int beg = g_rowptr[node], end = g_rowptr[node + 1];

    int h = lane >> 3;
    int c8 = (lane & 7) * 8;
    int chan = h * 64 + c8;

    float4 q0 = *(const float4*)&g_q[node * HC + chan];
    float4 q1 = *(const float4*)&g_q[node * HC + chan + 4];
    float4 gg0 = *(const float4*)&g_g[node * HC + chan];
    float4 gg1 = *(const float4*)&g_g[node * HC + chan + 4];
    float qb = g_qb[node * 4 + h];

    float s = 0.f;
    float4 av0 = {0,0,0,0}, av1 = {0,0,0,0};
    float4 at0 = {0,0,0,0}, at1 = {0,0,0,0};

    int p = beg;
    for (; p + 4 <= end; p += 4) {
        int src[4];
        #pragma unroll
        for (int u = 0; u < 4; u++) src[u] = g_src[p + u];

        float d[4];
        float4 e0[4], e1[4], v0[4], v1[4];
        #pragma unroll
        for (int u = 0; u < 4; u++) {
            float4 k0, k1;
            ldh8(&g_kh[src[u] * HC + chan], k0, k1);
            ldh8(&g_eh[(p + u) * 64 + c8], e0[u], e1[u]);
            ldh8(&g_vh[src[u] * HC + chan], v0[u], v1[u]);
            d[u] = dot4(q0, k0) + dot4(q1, k1) + dot4(gg0, e0[u]) + dot4(gg1, e1[u]);
        }
        #pragma unroll
        for (int off = 1; off < 8; off <<= 1) {
            #pragma unroll
            for (int u = 0; u < 4; u++)
                d[u] += __shfl_xor_sync(0xffffffffu, d[u], off);
        }
        float pe[4];
        #pragma unroll
        for (int u = 0; u < 4; u++) {
            pe[u] = __expf((d[u] + qb) * 0.125f);
            s += pe[u];
        }
        #pragma unroll
        for (int u = 0; u < 4; u++) {
            av0.x += pe[u] * v0[u].x;  av0.y += pe[u] * v0[u].y;
            av0.z += pe[u] * v0[u].z;  av0.w += pe[u] * v0[u].w;
            av1.x += pe[u] * v1[u].x;  av1.y += pe[u] * v1[u].y;
            av1.z += pe[u] * v1[u].z;  av1.w += pe[u] * v1[u].w;
            at0.x += pe[u] * e0[u].x;  at0.y += pe[u] * e0[u].y;
            at0.z += pe[u] * e0[u].z;  at0.w += pe[u] * e0[u].w;
            at1.x += pe[u] * e1[u].x;  at1.y += pe[u] * e1[u].y;
            at1.z += pe[u] * e1[u].z;  at1.w += pe[u] * e1[u].w;
        }
    }
    for (; p < end; p++) {
        int src = g_src[p];
        float4 k0, k1, e0, e1, v0, v1;
        ldh8(&g_kh[src * HC + chan], k0, k1);
        ldh8(&g_eh[p * 64 + c8],     e0, e1);
        ldh8(&g_vh[src * HC + chan], v0, v1);
        float d = dot4(q0, k0) + dot4(q1, k1) + dot4(gg0, e0) + dot4(gg1, e1);
        d += __shfl_xor_sync(0xffffffffu, d, 1);
        d += __shfl_xor_sync(0xffffffffu, d, 2);
        d += __shfl_xor_sync(0xffffffffu, d, 4);
        float pe = __expf((d + qb) * 0.125f);
        s += pe;
        av0.x += pe * v0.x; av0.y += pe * v0.y; av0.z += pe * v0.z; av0.w += pe * v0.w;
        av1.x += pe * v1.x; av1.y += pe * v1.y; av1.z += pe * v1.z; av1.w += pe * v1.w;
        at0.x += pe * e0.x; at0.y += pe * e0.y; at0.z += pe * e0.z; at0.w += pe * e0.w;
        at1.x += pe * e1.x; at1.y += pe * e1.y; at1.z += pe * e1.z; at1.w += pe * e1.w;
    }

    float sinv = 1.f / (s + 1e-16f);
    float4 o0 = {av0.x * sinv, av0.y * sinv, av0.z * sinv, av0.w * sinv};
    float4 o1 = {av1.x * sinv, av1.y * sinv, av1.z * sinv, av1.w * sinv};
    float4 t0 = {at0.x * sinv, at0.y * sinv, at0.z * sinv, at0.w * sinv};
    float4 t1 = {at1.x * sinv, at1.y * sinv, at1.z * sinv, at1.w * sinv};
    *(float4*)&g_outv[node * HC + chan]     = o0;
    *(float4*)&g_outv[node * HC + chan + 4] = o1;
    *(float4*)&g_t   [node * HC + chan]     = t0;
    *(float4*)&g_t   [node * HC + chan + 4] = t1;
    if ((lane & 7) == 0) g_suma[node * 4 + h] = s * sinv;
}

// ---------------- fused epilogue (R9 version: 16 nodes/block) --------------
__global__ void k_posthead(const float* __restrict__ wedge, const float* __restrict__ bedge,
                           const float* __restrict__ ln_g, const float* __restrict__ ln_b,
                           const float* __restrict__ w1, const float* __restrict__ b1,
                           const float* __restrict__ w2, const float* __restrict__ b2,
                           float* __restrict__ out, int n) {
    __shared__ float ts[16 * HC];
    __shared__ float os[16 * HC];
    __shared__ float hs[16 * 128];
    __shared__ float ls[16][NCLS];
    int tid = threadIdx.x;
    int nb = blockIdx.x * 16;
    for (int i = tid; i < 16 * HC; i += 256) {
        int nn = nb + (i >> 8);
        ts[i] = (nn < n) ? g_t[nn * HC + (i & 255)] : 0.f;
    }
    __syncthreads();

    int h = tid >> 6;
    float acc[16];
    #pragma unroll
    for (int m = 0; m < 16; m++) acc[m] = 0.f;
    for (int i = 0; i < 64; i++) {
        float w = __ldg(&wedge[i * HC + tid]);
        #pragma unroll
        for (int m = 0; m < 16; m++) acc[m] += ts[m * HC + h * 64 + i] * w;
    }
    float be = __ldg(&bedge[tid]);
    #pragma unroll
    for (int m = 0; m < 16; m++) {
        int nn = nb + m;
        if (nn < n) {
            os[m * HC + tid] = g_outv[nn * HC + tid] + g_suma[nn * 4 + h] * be
                             + g_skip[nn * HC + tid] + acc[m];
        }
    }
    __syncthreads();

    int wid = tid >> 5, lane = tid & 31;
    for (int m = wid; m < 16; m += 8) {
        int nn = nb + m;
        if (nn >= n) continue;
        float sum = 0.f, sq = 0.f;
        #pragma unroll
        for (int u = 0; u < 8; u++) {
            float v = os[m * HC + u * 32 + lane];
            sum += v; sq += v * v;
        }
        #pragma unroll
        for (int off = 16; off; off >>= 1) {
            sum += __shfl_xor_sync(0xffffffffu, sum, off);
            sq  += __shfl_xor_sync(0xffffffffu, sq,  off);
        }
        float mu = sum * (1.f / 256.f);
        float var = sq * (1.f / 256.f) - mu * mu;
        float rs = rsqrtf(var + 1e-5f);
        #pragma unroll
        for (int u = 0; u < 8; u++) {
            int j = u * 32 + lane;
            float v = (os[m * HC + j] - mu) * rs * __ldg(&ln_g[j]) + __ldg(&ln_b[j]);
            ts[m * HC + j] = fmaxf(v, 0.f);
        }
    }
    __syncthreads();

    {
        int col = tid & 127, rg = tid >> 7;
        float a8[8];
        float bb = __ldg(&b1[col]);
        #pragma unroll
        for (int r = 0; r < 8; r++) a8[r] = bb;
        for (int i = 0; i < HC; i++) {
            float w = __ldg(&w1[i * 128 + col]);
            #pragma unroll
            for (int r = 0; r < 8; r++) a8[r] += ts[(rg * 8 + r) * HC + i] * w;
        }
        #pragma unroll
        for (int r = 0; r < 8; r++) hs[(rg * 8 + r) * 128 + col] = fmaxf(a8[r], 0.f);
    }
    __syncthreads();

    if (tid < 64) {
        int m = tid >> 2, c = tid & 3;
        float a = __ldg(&b2[c]);
        for (int i = 0; i < 128; i++) a += hs[m * 128 + i] * __ldg(&w2[i * NCLS + c]);
        ls[m][c] = a;
    }
    __syncthreads();
    if (tid < 16) {
        int nn = nb + tid;
        if (nn < n) {
            float l0 = ls[tid][0], l1 = ls[tid][1], l2 = ls[tid][2], l3 = ls[tid][3];
            float mx = fmaxf(fmaxf(l0, l1), fmaxf(l2, l3));
            float se = expf(l0 - mx) + expf(l1 - mx) + expf(l2 - mx) + expf(l3 - mx);
            float lse = mx + logf(se);
            out[nn * NCLS + 0] = l0 - lse;
            out[nn * NCLS + 1] = l1 - lse;
            out[nn * NCLS + 2] = l2 - lse;
            out[nn * NCLS + 3] = l3 - lse;
        }
    }
}

// ---------------- launcher ----------------
extern "C" void kernel_launch(void* const* d_in, const int* in_sizes, int n_in,
                              void* d_out, int out_size) {
    const float* x     = (const float*)d_in[0];
    const int*   ei    = (const int*)  d_in[1];
    const float* eattr = (const float*)d_in[2];
    const float* w00   = (const float*)d_in[3];
    const float* b00   = (const float*)d_in[4];
    const float* we1   = (const float*)d_in[5];
    const float* be1   = (const float*)d_in[6];
    const float* we2   = (const float*)d_in[7];
    const float* be2   = (const float*)d_in[8];
    const float* we3   = (const float*)d_in[9];
    const float* be3   = (const float*)d_in[10];
    const float* wq    = (const float*)d_in[11];
    const float* bq    = (const float*)d_in[12];
    const float* wk    = (const float*)d_in[13];
    const float* bk    = (const float*)d_in[14];
    const float* wv    = (const float*)d_in[15];
    const float* bv    = (const float*)d_in[16];
    const float* wedge = (const float*)d_in[17];
    const float* bedge = (const float*)d_in[18];
    const float* wskip = (const float*)d_in[19];
    const float* bskip = (const float*)d_in[20];
    const float* ln_g  = (const float*)d_in[21];
    const float* ln_b  = (const float*)d_in[22];
    const float* w1    = (const float*)d_in[23];
    const float* b1    = (const float*)d_in[24];
    const float* w2    = (const float*)d_in[25];
    const float* b2    = (const float*)d_in[26];
    float* out = (float*)d_out;

    int n = in_sizes[0] / NFEAT;
    int e = in_sizes[1] / 2;
    int nblk = (n + 255) / 256;

    static const int EDGE_SMEM = 111360;
    static const int PROJ_SMEM = (5632 + 21120) * 2;
    cudaFuncSetAttribute(k_edgemlp, cudaFuncAttributeMaxDynamicSharedMemorySize, EDGE_SMEM);
    cudaFuncSetAttribute(k_proj,    cudaFuncAttributeMaxDynamicSharedMemorySize, PROJ_SMEM);

    k_zero_deg<<<(n + 255) / 256, 256>>>(n);
    k_hist<<<(e + 255) / 256, 256>>>(ei, e);
    k_blocksum<<<nblk, 256>>>(n);
    k_scanpart<<<1, 256>>>(nblk);
    k_scanfinal<<<nblk, 256>>>(n);
    k_scatter<<<(e + 255) / 256, 256>>>(ei, e);
    k_wtt<<<64, 256>>>(wedge);

    k_node_embed<<<(n + 63) / 64, 256>>>(x, w00, b00, n);
    {
        dim3 grid((n + 63) / 64, 4);
        k_proj<<<grid, 256, PROJ_SMEM>>>(wq, bq, wk, bk, wv, bv, wskip, bskip, n);
    }
    k_g<<<(n + 31) / 32, 256>>>(bedge, n);

    k_edgemlp<<<(e + 127) / 128, 256, EDGE_SMEM>>>(eattr, we1, be1, we2, be2, we3, be3, e);

    k_attn<<<(n + 7) / 8, 256>>>(n);

    k_posthead<<<(n + 15) / 16, 256>>>(wedge, bedge, ln_g, ln_b, w1, b1, w2, b2, out, n);
}

// round 12
// speedup vs baseline: 1.1284x; 1.0366x over previous
#include <cuda_runtime.h>
#include <cuda_fp16.h>
#include <mma.h>
#include <math.h>

using namespace nvcuda;

#define NFEAT 16
#define EFEAT 8
#define HC    256
#define NCLS  4

static const int MAXN = 50000;
static const int NPAD = 50048;
static const int MAXE = 800000;

typedef wmma::fragment<wmma::matrix_a, 16, 16, 16, __half, wmma::row_major> HFragA;
typedef wmma::fragment<wmma::matrix_b, 16, 16, 16, __half, wmma::row_major> HFragB;
typedef wmma::fragment<wmma::accumulator, 16, 16, 16, float> HFragC;

// ---------------- scratch ----------------
__device__ float  g_x1  [MAXN * 64];
__device__ float  g_q   [NPAD * HC];
__device__ __half g_kh  [NPAD * HC];
__device__ __half g_vh  [NPAD * HC];
__device__ float  g_skip[NPAD * HC];
__device__ float  g_g   [MAXN * HC];
__device__ float  g_qb  [MAXN * 4];
__device__ __half g_eh  [MAXE * 64];
__device__ float  g_outv[MAXN * HC];
__device__ float  g_t   [MAXN * HC];
__device__ float  g_suma[MAXN * 4];
__device__ float  g_wtt [HC * 64];
__device__ int    g_deg [MAXN];
__device__ int    g_rowptr[MAXN + 1];
__device__ int    g_cursor[MAXN];
__device__ int    g_eid [MAXE];
__device__ int    g_src [MAXE];
__device__ int    g_part[256];
__device__ int    g_partoff[256];

// ---------------- CSR build ----------------
__global__ void k_zero_deg(int n) {
    int i = blockIdx.x * blockDim.x + threadIdx.x;
    if (i < n) g_deg[i] = 0;
}
__global__ void k_hist(const int* __restrict__ ei, int e) {
    int i = blockIdx.x * blockDim.x + threadIdx.x;
    if (i < e) atomicAdd(&g_deg[ei[e + i]], 1);
}
__global__ void k_blocksum(int n) {
    __shared__ int sh[256];
    int tid = threadIdx.x;
    int i = blockIdx.x * 256 + tid;
    sh[tid] = (i < n) ? g_deg[i] : 0;
    __syncthreads();
    for (int off = 128; off; off >>= 1) {
        if (tid < off) sh[tid] += sh[tid + off];
        __syncthreads();
    }
    if (tid == 0) g_part[blockIdx.x] = sh[0];
}
__global__ void k_scanpart(int nb) {
    __shared__ int sh[256];
    int tid = threadIdx.x;
    int v = (tid < nb) ? g_part[tid] : 0;
    sh[tid] = v;
    __syncthreads();
    for (int off = 1; off < 256; off <<= 1) {
        int y = (tid >= off) ? sh[tid - off] : 0;
        __syncthreads();
        sh[tid] += y;
        __syncthreads();
    }
    g_partoff[tid] = sh[tid] - v;
}
__global__ void k_scanfinal(int n) {
    __shared__ int sh[256];
    int tid = threadIdx.x;
    int i = blockIdx.x * 256 + tid;
    int v = (i < n) ? g_deg[i] : 0;
    sh[tid] = v;
    __syncthreads();
    for (int off = 1; off < 256; off <<= 1) {
        int y = (tid >= off) ? sh[tid - off] : 0;
        __syncthreads();
        sh[tid] += y;
        __syncthreads();
    }
    int base = g_partoff[blockIdx.x];
    if (i < n) {
        int incl = base + sh[tid];
        g_rowptr[i + 1] = incl;
        g_cursor[i]     = incl - v;
    }
    if (i == 0) g_rowptr[0] = 0;
}
__global__ void k_scatter(const int* __restrict__ ei, int e) {
    int i = blockIdx.x * blockDim.x + threadIdx.x;
    if (i < e) {
        int dst = ei[e + i];
        int pos = atomicAdd(&g_cursor[dst], 1);
        g_eid[pos] = i;
        g_src[pos] = ei[i];
    }
}

// ---------------- wedge transpose ----------------
__global__ void k_wtt(const float* __restrict__ wedge) {
    int idx = blockIdx.x * 256 + threadIdx.x;
    int cg = idx >> 6, ii = idx & 63;
    g_wtt[cg * 64 + ii] = wedge[ii * HC + cg];
}

// ---------------- node embed ----------------
__global__ void k_node_embed(const float* __restrict__ x,
                             const float* __restrict__ w00,
                             const float* __restrict__ b00, int n) {
    __shared__ float ws[NFEAT * 64];
    __shared__ float xs[64][NFEAT];
    int tid = threadIdx.x;
    for (int i = tid; i < NFEAT * 64; i += 256) ws[i] = w00[i];
    int nb = blockIdx.x * 64;
    for (int i = tid; i < 64 * NFEAT; i += 256) {
        int nn = nb + i / NFEAT;
        xs[i / NFEAT][i % NFEAT] = (nn < n) ? x[nn * NFEAT + (i % NFEAT)] : 0.f;
    }
    __syncthreads();
    int ln = tid >> 2;
    int node = nb + ln;
    int c0 = (tid & 3) * 16;
    if (node < n) {
        #pragma unroll
        for (int j = 0; j < 16; j++) {
            float acc = __ldg(&b00[c0 + j]);
            #pragma unroll
            for (int i = 0; i < NFEAT; i++) acc += xs[ln][i] * ws[i * 64 + c0 + j];
            g_x1[node * 64 + c0 + j] = fmaxf(acc, 0.f);
        }
    }
}

// ---------------- projections: fp16 wmma; k/v stored as fp16 --------------
__global__ void k_proj(const float* __restrict__ W0, const float* __restrict__ B0,
                       const float* __restrict__ W1, const float* __restrict__ B1,
                       const float* __restrict__ W2, const float* __restrict__ B2,
                       const float* __restrict__ W3, const float* __restrict__ B3,
                       int n) {
    int sel = blockIdx.y;
    const float* W = (sel == 0) ? W0 : (sel == 1) ? W1 : (sel == 2) ? W2 : W3;
    const float* B = (sel == 0) ? B0 : (sel == 1) ? B1 : (sel == 2) ? B2 : B3;
    bool half_out = (sel == 1 || sel == 2);
    float*  outf = (sel == 0) ? g_q : g_skip;
    __half* outh = (sel == 1) ? g_kh : g_vh;

    extern __shared__ __half smh[];
    __half* xsh = smh;            // [64][88]
    __half* wsh = smh + 5632;     // [80][264]
    __shared__ float fbp[8][256];

    int tid = threadIdx.x;
    int nb = blockIdx.x * 64;

    for (int i = tid; i < 64 * 88; i += 256) {
        int r = i / 88, c = i - r * 88;
        float v = 0.f;
        if (c < 64) {
            int node = nb + r;
            if (node < n) v = __ldg(&g_x1[node * 64 + c]);
        } else if (c == 64) v = 1.0f;
        xsh[i] = __float2half(v);
    }
    for (int i = tid; i < 80 * 264; i += 256) {
        int r = i / 264, c = i - r * 264;
        float v = 0.f;
        if (c < 256) {
            if (r < 64) v = __ldg(&W[r * 256 + c]);
            else if (r == 64) v = __ldg(&B[c]);
        }
        wsh[i] = __float2half(v);
    }
    __syncthreads();

    int w = tid >> 5, lane = tid & 31;
    int rt = w >> 1;
    int ch = w & 1;

    HFragA a[5];
    #pragma unroll
    for (int k = 0; k < 5; k++)
        wmma::load_matrix_sync(a[k], &xsh[rt * 16 * 88 + k * 16], 88);

    #pragma unroll
    for (int nf = 0; nf < 8; nf++) {
        int c0 = ch * 128 + nf * 16;
        HFragC acc;
        wmma::fill_fragment(acc, 0.f);
        #pragma unroll
        for (int k = 0; k < 5; k++) {
            HFragB b;
            wmma::load_matrix_sync(b, &wsh[k * 16 * 264 + c0], 264);
            wmma::mma_sync(acc, a[k], b, acc);
        }
        if (!half_out) {
            wmma::store_matrix_sync(&outf[(nb + rt * 16) * HC + c0], acc, HC, wmma::mem_row_major);
        } else {
            wmma::store_matrix_sync(&fbp[w][0], acc, 16, wmma::mem_row_major);
            __syncwarp();
            int r = lane >> 1, cf = (lane & 1) * 8;
            const float* src = &fbp[w][r * 16 + cf];
            __half hb[8];
            #pragma unroll
            for (int j = 0; j < 8; j++) hb[j] = __float2half(src[j]);
            *(uint4*)&outh[(nb + rt * 16 + r) * HC + c0 + cf] = *(uint4*)hb;
            __syncwarp();
        }
    }
}

// ---------------- g = per-head wedge^T @ q (coalesced via g_wtt) -----------
__global__ void k_g(const float* __restrict__ bedge, int n) {
    __shared__ float qs[32 * HC];
    int tid = threadIdx.x;
    int nb = blockIdx.x * 32;
    for (int i = tid; i < 2048; i += 256) {
        int row = i >> 6, q4 = i & 63;
        int node = nb + row;
        float4 v = make_float4(0.f, 0.f, 0.f, 0.f);
        if (node < n) v = *(const float4*)&g_q[node * HC + q4 * 4];
        *(float4*)&qs[row * HC + q4 * 4] = v;
    }
    __syncthreads();
    int h = tid >> 6, ii = tid & 63;
    float acc[32];
    #pragma unroll
    for (int m = 0; m < 32; m++) acc[m] = 0.f;
    for (int c = 0; c < 64; c++) {
        float w = __ldg(&g_wtt[(h * 64 + c) * 64 + ii]);
        #pragma unroll
        for (int m = 0; m < 32; m++) acc[m] += qs[m * HC + h * 64 + c] * w;
    }
    #pragma unroll
    for (int m = 0; m < 32; m++) {
        int nn = nb + m;
        if (nn < n) g_g[nn * HC + tid] = acc[m];
    }
    if (tid < 128) {
        int m = tid >> 2, h2 = tid & 3;
        int nn = nb + m;
        if (nn < n) {
            float s = 0.f;
            for (int c = 0; c < 64; c++) s += qs[m * HC + h2 * 64 + c] * __ldg(&bedge[h2 * 64 + c]);
            g_qb[nn * 4 + h2] = s;
        }
    }
}

// ---------------- edge MLP: fp16 wmma, 128 edges/block ---------------------
__global__ void k_edgemlp(const float* __restrict__ eattr,
                          const float* __restrict__ we1, const float* __restrict__ be1,
                          const float* __restrict__ we2, const float* __restrict__ be2,
                          const float* __restrict__ we3, const float* __restrict__ be3,
                          int e) {
    extern __shared__ __half smh[];
    __half* es  = smh;
    __half* w1b = smh + 2048;
    __half* w2b = smh + 3200;
    __half* w3b = smh + 8960;
    __half* h1h = smh + 14720;
    __half* h2h = smh + 25984;
    float*  fb  = (float*)(smh + 37248);

    int tid = threadIdx.x;
    int pb = blockIdx.x * 128;

    for (int i = tid; i < 1152; i += 256) {
        int r = i / 72, c = i - r * 72;
        float v = 0.f;
        if (c < 64) v = (r < 8) ? __ldg(&we1[r * 64 + c]) : ((r == 8) ? __ldg(&be1[c]) : 0.f);
        w1b[i] = __float2half(v);
    }
    for (int i = tid; i < 5760; i += 256) {
        int r = i / 72, c = i - r * 72;
        float v2 = 0.f, v3 = 0.f;
        if (c < 64) {
            if (r < 64)      { v2 = __ldg(&we2[r * 64 + c]); v3 = __ldg(&we3[r * 64 + c]); }
            else if (r == 64){ v2 = __ldg(&be2[c]);          v3 = __ldg(&be3[c]); }
        }
        w2b[i] = __float2half(v2);
        w3b[i] = __float2half(v3);
    }
    for (int i = tid; i < 2048; i += 256) {
        int r = i >> 4, c = i & 15;
        float v = 0.f;
        if (c < 8) {
            int p = pb + r;
            if (p < e) v = __ldg(&eattr[g_eid[p] * 8 + c]);
        } else if (c == 8) v = 1.0f;
        es[i] = __float2half(v);
    }
    for (int i = tid; i < 3072; i += 256) {
        int r = i / 24, c = 64 + (i - r * 24);
        __half v = __float2half((c == 64) ? 1.0f : 0.f);
        h1h[r * 88 + c] = v;
        h2h[r * 88 + c] = v;
    }
    __syncthreads();

    int w = tid >> 5;

    // ---- layer 1 (k=16) ----
    {
        HFragA a;
        wmma::load_matrix_sync(a, &es[w * 16 * 16], 16);
        #pragma unroll
        for (int nf = 0; nf < 4; nf++) {
            HFragC acc;
            wmma::fill_fragment(acc, 0.f);
            HFragB b;
            wmma::load_matrix_sync(b, &w1b[nf * 16], 72);
            wmma::mma_sync(acc, a, b, acc);
            wmma::store_matrix_sync(&fb[w * 16 * 72 + nf * 16], acc, 72, wmma::mem_row_major);
        }
    }
    __syncthreads();
    for (int i = tid; i < 8192; i += 256) {
        int r = i >> 6, c = i & 63;
        h1h[r * 88 + c] = __float2half(fmaxf(fb[r * 72 + c], 0.f));
    }
    __syncthreads();

    // ---- layer 2 (k=80) ----
    {
        HFragA a[5];
        #pragma unroll
        for (int k = 0; k < 5; k++)
            wmma::load_matrix_sync(a[k], &h1h[w * 16 * 88 + k * 16], 88);
        #pragma unroll
        for (int nf = 0; nf < 4; nf++) {
            HFragC acc;
            wmma::fill_fragment(acc, 0.f);
            #pragma unroll
            for (int k = 0; k < 5; k++) {
                HFragB b;
                wmma::load_matrix_sync(b, &w2b[k * 16 * 72 + nf * 16], 72);
                wmma::mma_sync(acc, a[k], b, acc);
            }
            wmma::store_matrix_sync(&fb[w * 16 * 72 + nf * 16], acc, 72, wmma::mem_row_major);
        }
    }
    __syncthreads();
    for (int i = tid; i < 8192; i += 256) {
        int r = i >> 6, c = i & 63;
        h2h[r * 88 + c] = __float2half(fmaxf(fb[r * 72 + c], 0.f));
    }
    __syncthreads();

    // ---- layer 3 (k=80) -> relu -> fp16 g_eh ----
    {
        HFragA a[5];
        #pragma unroll
        for (int k = 0; k < 5; k++)
            wmma::load_matrix_sync(a[k], &h2h[w * 16 * 88 + k * 16], 88);
        #pragma unroll
        for (int nf = 0; nf < 4; nf++) {
            HFragC acc;
            wmma::fill_fragment(acc, 0.f);
            #pragma unroll
            for (int k = 0; k < 5; k++) {
                HFragB b;
                wmma::load_matrix_sync(b, &w3b[k * 16 * 72 + nf * 16], 72);
                wmma::mma_sync(acc, a[k], b, acc);
            }
            wmma::store_matrix_sync(&fb[w * 16 * 72 + nf * 16], acc, 72, wmma::mem_row_major);
        }
    }
    __syncthreads();
    {
        int nrows = min(128, e - pb);
        for (int i = tid * 2; i < nrows * 64; i += 512) {
            int r = i >> 6, c = i & 63;
            __half2 hv = __floats2half2_rn(fmaxf(fb[r * 72 + c], 0.f),
                                           fmaxf(fb[r * 72 + c + 1], 0.f));
            *(__half2*)&g_eh[(pb + r) * 64 + c] = hv;
        }
    }
}

// ---------------- attention ----------------
__device__ __forceinline__ float dot4(float4 a, float4 b) {
    return a.x * b.x + a.y * b.y + a.z * b.z + a.w * b.w;
}
__device__ __forceinline__ void ldh8(const __half* p, float4& a, float4& b) {
    uint4 u = *(const uint4*)p;
    float2 f0 = __half22float2(*(__half2*)&u.x);
    float2 f1 = __half22float2(*(__half2*)&u.y);
    float2 f2 = __half22float2(*(__half2*)&u.z);
    float2 f3 = __half22float2(*(__half2*)&u.w);
    a = make_float4(f0.x, f0.y, f1.x, f1.y);
    b = make_float4(f2.x, f2.y, f3.x, f3.y);
}

__global__ void __launch_bounds__(256) k_attn(int n) {
    int gw = (blockIdx.x * blockDim.x + threadIdx.x) >> 5;
    int lane = threadIdx.x & 31;
    if (gw >= n) return;
    int node = gw;
    int beg = g_rowptr[node], end = g_rowptr[node + 1];

    int h = lane >> 3;
    int c8 = (lane & 7) * 8;
    int chan = h * 64 + c8;

    float4 q0 = *(const float4*)&g_q[node * HC + chan];
    float4 q1 = *(const float4*)&g_q[node * HC + chan + 4];
    float4 gg0 = *(const float4*)&g_g[node * HC + chan];
    float4 gg1 = *(const float4*)&g_g[node * HC + chan + 4];
    float qb = g_qb[node * 4 + h];

    float s = 0.f;
    float4 av0 = {0,0,0,0}, av1 = {0,0,0,0};
    float4 at0 = {0,0,0,0}, at1 = {0,0,0,0};

    int p = beg;
    for (; p + 4 <= end; p += 4) {
        int src[4];
        #pragma unroll
        for (int u = 0; u < 4; u++) src[u] = g_src[p + u];

        float d[4];
        float4 e0[4], e1[4], v0[4], v1[4];
        #pragma unroll
        for (int u = 0; u < 4; u++) {
            float4 k0, k1;
            ldh8(&g_kh[src[u] * HC + chan], k0, k1);
            ldh8(&g_eh[(p + u) * 64 + c8], e0[u], e1[u]);
            ldh8(&g_vh[src[u] * HC + chan], v0[u], v1[u]);
            d[u] = dot4(q0, k0) + dot4(q1, k1) + dot4(gg0, e0[u]) + dot4(gg1, e1[u]);
        }
        #pragma unroll
        for (int off = 1; off < 8; off <<= 1) {
            #pragma unroll
            for (int u = 0; u < 4; u++)
                d[u] += __shfl_xor_sync(0xffffffffu, d[u], off);
        }
        float pe[4];
        #pragma unroll
        for (int u = 0; u < 4; u++) {
            pe[u] = __expf((d[u] + qb) * 0.125f);
            s += pe[u];
        }
        #pragma unroll
        for (int u = 0; u < 4; u++) {
            av0.x += pe[u] * v0[u].x;  av0.y += pe[u] * v0[u].y;
            av0.z += pe[u] * v0[u].z;  av0.w += pe[u] * v0[u].w;
            av1.x += pe[u] * v1[u].x;  av1.y += pe[u] * v1[u].y;
            av1.z += pe[u] * v1[u].z;  av1.w += pe[u] * v1[u].w;
            at0.x += pe[u] * e0[u].x;  at0.y += pe[u] * e0[u].y;
            at0.z += pe[u] * e0[u].z;  at0.w += pe[u] * e0[u].w;
            at1.x += pe[u] * e1[u].x;  at1.y += pe[u] * e1[u].y;
            at1.z += pe[u] * e1[u].z;  at1.w += pe[u] * e1[u].w;
        }
    }
    for (; p < end; p++) {
        int src = g_src[p];
        float4 k0, k1, e0, e1, v0, v1;
        ldh8(&g_kh[src * HC + chan], k0, k1);
        ldh8(&g_eh[p * 64 + c8],     e0, e1);
        ldh8(&g_vh[src * HC + chan], v0, v1);
        float d = dot4(q0, k0) + dot4(q1, k1) + dot4(gg0, e0) + dot4(gg1, e1);
        d += __shfl_xor_sync(0xffffffffu, d, 1);
        d += __shfl_xor_sync(0xffffffffu, d, 2);
        d += __shfl_xor_sync(0xffffffffu, d, 4);
        float pe = __expf((d + qb) * 0.125f);
        s += pe;
        av0.x += pe * v0.x; av0.y += pe * v0.y; av0.z += pe * v0.z; av0.w += pe * v0.w;
        av1.x += pe * v1.x; av1.y += pe * v1.y; av1.z += pe * v1.z; av1.w += pe * v1.w;
        at0.x += pe * e0.x; at0.y += pe * e0.y; at0.z += pe * e0.z; at0.w += pe * e0.w;
        at1.x += pe * e1.x; at1.y += pe * e1.y; at1.z += pe * e1.z; at1.w += pe * e1.w;
    }

    float sinv = 1.f / (s + 1e-16f);
    float4 o0 = {av0.x * sinv, av0.y * sinv, av0.z * sinv, av0.w * sinv};
    float4 o1 = {av1.x * sinv, av1.y * sinv, av1.z * sinv, av1.w * sinv};
    float4 t0 = {at0.x * sinv, at0.y * sinv, at0.z * sinv, at0.w * sinv};
    float4 t1 = {at1.x * sinv, at1.y * sinv, at1.z * sinv, at1.w * sinv};
    *(float4*)&g_outv[node * HC + chan]     = o0;
    *(float4*)&g_outv[node * HC + chan + 4] = o1;
    *(float4*)&g_t   [node * HC + chan]     = t0;
    *(float4*)&g_t   [node * HC + chan + 4] = t1;
    if ((lane & 7) == 0) g_suma[node * 4 + h] = s * sinv;
}

// ---------------- fused epilogue (16 nodes/block) --------------------------
__global__ void k_posthead(const float* __restrict__ wedge, const float* __restrict__ bedge,
                           const float* __restrict__ ln_g, const float* __restrict__ ln_b,
                           const float* __restrict__ w1, const float* __restrict__ b1,
                           const float* __restrict__ w2, const float* __restrict__ b2,
                           float* __restrict__ out, int n) {
    __shared__ float ts[16 * HC];
    __shared__ float os[16 * HC];
    __shared__ float hs[16 * 128];
    __shared__ float ls[16][NCLS];
    int tid = threadIdx.x;
    int nb = blockIdx.x * 16;
    for (int i = tid; i < 16 * HC; i += 256) {
        int nn = nb + (i >> 8);
        ts[i] = (nn < n) ? g_t[nn * HC + (i & 255)] : 0.f;
    }
    __syncthreads();

    int h = tid >> 6;
    float acc[16];
    #pragma unroll
    for (int m = 0; m < 16; m++) acc[m] = 0.f;
    for (int i = 0; i < 64; i++) {
        float w = __ldg(&wedge[i * HC + tid]);
        #pragma unroll
        for (int m = 0; m < 16; m++) acc[m] += ts[m * HC + h * 64 + i] * w;
    }
    float be = __ldg(&bedge[tid]);
    #pragma unroll
    for (int m = 0; m < 16; m++) {
        int nn = nb + m;
        if (nn < n) {
            os[m * HC + tid] = g_outv[nn * HC + tid] + g_suma[nn * 4 + h] * be
                             + g_skip[nn * HC + tid] + acc[m];
        }
    }
    __syncthreads();

    int wid = tid >> 5, lane = tid & 31;
    for (int m = wid; m < 16; m += 8) {
        int nn = nb + m;
        if (nn >= n) continue;
        float sum = 0.f, sq = 0.f;
        #pragma unroll
        for (int u = 0; u < 8; u++) {
            float v = os[m * HC + u * 32 + lane];
            sum += v; sq += v * v;
        }
        #pragma unroll
        for (int off = 16; off; off >>= 1) {
            sum += __shfl_xor_sync(0xffffffffu, sum, off);
            sq  += __shfl_xor_sync(0xffffffffu, sq,  off);
        }
        float mu = sum * (1.f / 256.f);
        float var = sq * (1.f / 256.f) - mu * mu;
        float rs = rsqrtf(var + 1e-5f);
        #pragma unroll
        for (int u = 0; u < 8; u++) {
            int j = u * 32 + lane;
            float v = (os[m * HC + j] - mu) * rs * __ldg(&ln_g[j]) + __ldg(&ln_b[j]);
            ts[m * HC + j] = fmaxf(v, 0.f);
        }
    }
    __syncthreads();

    {
        int col = tid & 127, rg = tid >> 7;
        float a8[8];
        float bb = __ldg(&b1[col]);
        #pragma unroll
        for (int r = 0; r < 8; r++) a8[r] = bb;
        for (int i = 0; i < HC; i++) {
            float w = __ldg(&w1[i * 128 + col]);
            #pragma unroll
            for (int r = 0; r < 8; r++) a8[r] += ts[(rg * 8 + r) * HC + i] * w;
        }
        #pragma unroll
        for (int r = 0; r < 8; r++) hs[(rg * 8 + r) * 128 + col] = fmaxf(a8[r], 0.f);
    }
    __syncthreads();

    if (tid < 64) {
        int m = tid >> 2, c = tid & 3;
        float a = __ldg(&b2[c]);
        for (int i = 0; i < 128; i++) a += hs[m * 128 + i] * __ldg(&w2[i * NCLS + c]);
        ls[m][c] = a;
    }
    __syncthreads();
    if (tid < 16) {
        int nn = nb + tid;
        if (nn < n) {
            float l0 = ls[tid][0], l1 = ls[tid][1], l2 = ls[tid][2], l3 = ls[tid][3];
            float mx = fmaxf(fmaxf(l0, l1), fmaxf(l2, l3));
            float se = expf(l0 - mx) + expf(l1 - mx) + expf(l2 - mx) + expf(l3 - mx);
            float lse = mx + logf(se);
            out[nn * NCLS + 0] = l0 - lse;
            out[nn * NCLS + 1] = l1 - lse;
            out[nn * NCLS + 2] = l2 - lse;
            out[nn * NCLS + 3] = l3 - lse;
        }
    }
}

// ---------------- launcher: fork node pipeline onto stream B ---------------
extern "C" void kernel_launch(void* const* d_in, const int* in_sizes, int n_in,
                              void* d_out, int out_size) {
    const float* x     = (const float*)d_in[0];
    const int*   ei    = (const int*)  d_in[1];
    const float* eattr = (const float*)d_in[2];
    const float* w00   = (const float*)d_in[3];
    const float* b00   = (const float*)d_in[4];
    const float* we1   = (const float*)d_in[5];
    const float* be1   = (const float*)d_in[6];
    const float* we2   = (const float*)d_in[7];
    const float* be2   = (const float*)d_in[8];
    const float* we3   = (const float*)d_in[9];
    const float* be3   = (const float*)d_in[10];
    const float* wq    = (const float*)d_in[11];
    const float* bq    = (const float*)d_in[12];
    const float* wk    = (const float*)d_in[13];
    const float* bk    = (const float*)d_in[14];
    const float* wv    = (const float*)d_in[15];
    const float* bv    = (const float*)d_in[16];
    const float* wedge = (const float*)d_in[17];
    const float* bedge = (const float*)d_in[18];
    const float* wskip = (const float*)d_in[19];
    const float* bskip = (const float*)d_in[20];
    const float* ln_g  = (const float*)d_in[21];
    const float* ln_b  = (const float*)d_in[22];
    const float* w1    = (const float*)d_in[23];
    const float* b1    = (const float*)d_in[24];
    const float* w2    = (const float*)d_in[25];
    const float* b2    = (const float*)d_in[26];
    float* out = (float*)d_out;

    int n = in_sizes[0] / NFEAT;
    int e = in_sizes[1] / 2;
    int nblk = (n + 255) / 256;

    static cudaStream_t sB = nullptr;
    static cudaEvent_t evF = nullptr, evJ = nullptr;
    static bool attrs_set = false;
    if (sB == nullptr) {
        cudaStreamCreateWithFlags(&sB, cudaStreamNonBlocking);
        cudaEventCreateWithFlags(&evF, cudaEventDisableTiming);
        cudaEventCreateWithFlags(&evJ, cudaEventDisableTiming);
    }
    static const int EDGE_SMEM = 111360;
    static const int PROJ_SMEM = (5632 + 21120) * 2;
    if (!attrs_set) {
        cudaFuncSetAttribute(k_edgemlp, cudaFuncAttributeMaxDynamicSharedMemorySize, EDGE_SMEM);
        cudaFuncSetAttribute(k_proj,    cudaFuncAttributeMaxDynamicSharedMemorySize, PROJ_SMEM);
        attrs_set = true;
    }

    // fork: stream B joins the capture DAG at this point
    cudaEventRecord(evF, 0);
    cudaStreamWaitEvent(sB, evF, 0);

    // ---- stream B: node pipeline (independent of CSR/edge) ----
    k_wtt<<<64, 256, 0, sB>>>(wedge);
    k_node_embed<<<(n + 63) / 64, 256, 0, sB>>>(x, w00, b00, n);
    {
        dim3 grid((n + 63) / 64, 4);
        k_proj<<<grid, 256, PROJ_SMEM, sB>>>(wq, bq, wk, bk, wv, bv, wskip, bskip, n);
    }
    k_g<<<(n + 31) / 32, 256, 0, sB>>>(bedge, n);
    cudaEventRecord(evJ, sB);

    // ---- capture stream: CSR build + edge MLP ----
    k_zero_deg<<<(n + 255) / 256, 256>>>(n);
    k_hist<<<(e + 255) / 256, 256>>>(ei, e);
    k_blocksum<<<nblk, 256>>>(n);
    k_scanpart<<<1, 256>>>(nblk);
    k_scanfinal<<<nblk, 256>>>(n);
    k_scatter<<<(e + 255) / 256, 256>>>(ei, e);
    k_edgemlp<<<(e + 127) / 128, 256, EDGE_SMEM>>>(eattr, we1, be1, we2, be2, we3, be3, e);

    // join: attention needs both pipelines
    cudaStreamWaitEvent(0, evJ, 0);

    k_attn<<<(n + 7) / 8, 256>>>(n);
    k_posthead<<<(n + 15) / 16, 256>>>(wedge, bedge, ln_g, ln_b, w1, b1, w2, b2, out, n);
}

// round 13
// speedup vs baseline: 1.1697x; 1.0366x over previous
#include <cuda_runtime.h>
#include <cuda_fp16.h>
#include <mma.h>
#include <math.h>

using namespace nvcuda;

#define NFEAT 16
#define EFEAT 8
#define HC    256
#define NCLS  4

static const int MAXN = 50000;
static const int NPAD = 50048;
static const int MAXE = 800000;

typedef wmma::fragment<wmma::matrix_a, 16, 16, 16, __half, wmma::row_major> HFragA;
typedef wmma::fragment<wmma::matrix_b, 16, 16, 16, __half, wmma::row_major> HFragB;
typedef wmma::fragment<wmma::accumulator, 16, 16, 16, float> HFragC;

// ---------------- scratch ----------------
__device__ float  g_x1  [MAXN * 64];
__device__ float  g_q   [NPAD * HC];
__device__ __half g_kh  [NPAD * HC];
__device__ __half g_vh  [NPAD * HC];
__device__ float  g_skip[NPAD * HC];
__device__ float  g_g   [NPAD * HC];
__device__ float  g_qb  [MAXN * 4];
__device__ __half g_eh  [MAXE * 64];
__device__ float  g_outv[MAXN * HC];
__device__ float  g_t   [MAXN * HC];
__device__ float  g_suma[MAXN * 4];
__device__ float  g_wg  [64 * HC];    // folded: wq @ wedgeT (per-head)
__device__ float  g_bg  [HC];
__device__ float  g_wqb [64 * 4];
__device__ float  g_cb  [4];
__device__ int    g_deg [MAXN];
__device__ int    g_rowptr[MAXN + 1];
__device__ int    g_cursor[MAXN];
__device__ int    g_eid [MAXE];
__device__ int    g_src [MAXE];
__device__ int    g_part[256];
__device__ int    g_partoff[256];

// ---------------- CSR build ----------------
__global__ void k_zero_deg(int n) {
    int i = blockIdx.x * blockDim.x + threadIdx.x;
    if (i < n) g_deg[i] = 0;
}
__global__ void k_hist(const int* __restrict__ ei, int e) {
    int i = blockIdx.x * blockDim.x + threadIdx.x;
    if (i < e) atomicAdd(&g_deg[ei[e + i]], 1);
}
__global__ void k_blocksum(int n) {
    __shared__ int sh[256];
    int tid = threadIdx.x;
    int i = blockIdx.x * 256 + tid;
    sh[tid] = (i < n) ? g_deg[i] : 0;
    __syncthreads();
    for (int off = 128; off; off >>= 1) {
        if (tid < off) sh[tid] += sh[tid + off];
        __syncthreads();
    }
    if (tid == 0) g_part[blockIdx.x] = sh[0];
}
__global__ void k_scanpart(int nb) {
    __shared__ int sh[256];
    int tid = threadIdx.x;
    int v = (tid < nb) ? g_part[tid] : 0;
    sh[tid] = v;
    __syncthreads();
    for (int off = 1; off < 256; off <<= 1) {
        int y = (tid >= off) ? sh[tid - off] : 0;
        __syncthreads();
        sh[tid] += y;
        __syncthreads();
    }
    g_partoff[tid] = sh[tid] - v;
}
__global__ void k_scanfinal(int n) {
    __shared__ int sh[256];
    int tid = threadIdx.x;
    int i = blockIdx.x * 256 + tid;
    int v = (i < n) ? g_deg[i] : 0;
    sh[tid] = v;
    __syncthreads();
    for (int off = 1; off < 256; off <<= 1) {
        int y = (tid >= off) ? sh[tid - off] : 0;
        __syncthreads();
        sh[tid] += y;
        __syncthreads();
    }
    int base = g_partoff[blockIdx.x];
    if (i < n) {
        int incl = base + sh[tid];
        g_rowptr[i + 1] = incl;
        g_cursor[i]     = incl - v;
    }
    if (i == 0) g_rowptr[0] = 0;
}
__global__ void k_scatter(const int* __restrict__ ei, int e) {
    int i = blockIdx.x * blockDim.x + threadIdx.x;
    if (i < e) {
        int dst = ei[e + i];
        int pos = atomicAdd(&g_cursor[dst], 1);
        g_eid[pos] = i;
        g_src[pos] = ei[i];
    }
}

// ---------------- weight folding (one-time, tiny) ----------------
// Wg[f, h*64+ii] = sum_c wq[f, h*64+c] * wedge[ii, h*64+c] ; row 64 folds bq -> bg
__global__ void k_foldw(const float* __restrict__ wq, const float* __restrict__ bq,
                        const float* __restrict__ wedge) {
    int f = blockIdx.x;          // 0..64 (64 = bias row)
    int j = threadIdx.x;         // 0..255
    int h = j >> 6, ii = j & 63;
    const float* src = (f < 64) ? &wq[f * HC] : bq;
    float s = 0.f;
    for (int c = 0; c < 64; c++)
        s += src[h * 64 + c] * __ldg(&wedge[ii * HC + h * 64 + c]);
    if (f < 64) g_wg[f * HC + j] = s;
    else        g_bg[j] = s;
}
// wqb[f,h] = sum_c wq[f, h*64+c]*bedge[h*64+c] ; cb[h] = sum_c bq*bedge
__global__ void k_foldqb(const float* __restrict__ wq, const float* __restrict__ bq,
                         const float* __restrict__ bedge) {
    int j = threadIdx.x;         // 256
    int f = j >> 2, h = j & 3;
    float s = 0.f;
    for (int c = 0; c < 64; c++)
        s += wq[f * HC + h * 64 + c] * __ldg(&bedge[h * 64 + c]);
    g_wqb[f * 4 + h] = s;
    if (j < 4) {
        float cb = 0.f;
        for (int c = 0; c < 64; c++) cb += bq[j * 64 + c] * bedge[j * 64 + c];
        g_cb[j] = cb;
    }
}

// ---------------- node embed ----------------
__global__ void k_node_embed(const float* __restrict__ x,
                             const float* __restrict__ w00,
                             const float* __restrict__ b00, int n) {
    __shared__ float ws[NFEAT * 64];
    __shared__ float xs[64][NFEAT];
    int tid = threadIdx.x;
    for (int i = tid; i < NFEAT * 64; i += 256) ws[i] = w00[i];
    int nb = blockIdx.x * 64;
    for (int i = tid; i < 64 * NFEAT; i += 256) {
        int nn = nb + i / NFEAT;
        xs[i / NFEAT][i % NFEAT] = (nn < n) ? x[nn * NFEAT + (i % NFEAT)] : 0.f;
    }
    __syncthreads();
    int ln = tid >> 2;
    int node = nb + ln;
    int c0 = (tid & 3) * 16;
    if (node < n) {
        #pragma unroll
        for (int j = 0; j < 16; j++) {
            float acc = __ldg(&b00[c0 + j]);
            #pragma unroll
            for (int i = 0; i < NFEAT; i++) acc += xs[ln][i] * ws[i * 64 + c0 + j];
            g_x1[node * 64 + c0 + j] = fmaxf(acc, 0.f);
        }
    }
}

// ---------------- qb = x1 @ wqb + cb ----------------
__global__ void k_qb(int n) {
    __shared__ float ws[64 * 4];
    int tid = threadIdx.x;
    ws[tid] = g_wqb[tid];
    __syncthreads();
    int idx = blockIdx.x * 64 + (tid >> 2);
    int h = tid & 3;
    if (idx < n) {
        float s = g_cb[h];
        const float* xr = &g_x1[idx * 64];
        #pragma unroll 16
        for (int f = 0; f < 64; f++) s += xr[f] * ws[f * 4 + h];
        g_qb[idx * 4 + h] = s;
    }
}

// ---------------- projections: fp16 wmma; 5 slices (q,k,v,skip,g) ---------
__global__ void k_proj(const float* __restrict__ W0, const float* __restrict__ B0,
                       const float* __restrict__ W1, const float* __restrict__ B1,
                       const float* __restrict__ W2, const float* __restrict__ B2,
                       const float* __restrict__ W3, const float* __restrict__ B3,
                       int n) {
    int sel = blockIdx.y;
    const float* W = (sel == 0) ? W0 : (sel == 1) ? W1 : (sel == 2) ? W2 :
                     (sel == 3) ? W3 : g_wg;
    const float* B = (sel == 0) ? B0 : (sel == 1) ? B1 : (sel == 2) ? B2 :
                     (sel == 3) ? B3 : g_bg;
    bool half_out = (sel == 1 || sel == 2);
    float*  outf = (sel == 0) ? g_q : (sel == 3) ? g_skip : g_g;
    __half* outh = (sel == 1) ? g_kh : g_vh;

    extern __shared__ __half smh[];
    __half* xsh = smh;            // [64][88]
    __half* wsh = smh + 5632;     // [80][264]
    __shared__ float fbp[8][256];

    int tid = threadIdx.x;
    int nb = blockIdx.x * 64;

    for (int i = tid; i < 64 * 88; i += 256) {
        int r = i / 88, c = i - r * 88;
        float v = 0.f;
        if (c < 64) {
            int node = nb + r;
            if (node < n) v = __ldg(&g_x1[node * 64 + c]);
        } else if (c == 64) v = 1.0f;
        xsh[i] = __float2half(v);
    }
    for (int i = tid; i < 80 * 264; i += 256) {
        int r = i / 264, c = i - r * 264;
        float v = 0.f;
        if (c < 256) {
            if (r < 64) v = __ldg(&W[r * 256 + c]);
            else if (r == 64) v = __ldg(&B[c]);
        }
        wsh[i] = __float2half(v);
    }
    __syncthreads();

    int w = tid >> 5, lane = tid & 31;
    int rt = w >> 1;
    int ch = w & 1;

    HFragA a[5];
    #pragma unroll
    for (int k = 0; k < 5; k++)
        wmma::load_matrix_sync(a[k], &xsh[rt * 16 * 88 + k * 16], 88);

    #pragma unroll
    for (int nf = 0; nf < 8; nf++) {
        int c0 = ch * 128 + nf * 16;
        HFragC acc;
        wmma::fill_fragment(acc, 0.f);
        #pragma unroll
        for (int k = 0; k < 5; k++) {
            HFragB b;
            wmma::load_matrix_sync(b, &wsh[k * 16 * 264 + c0], 264);
            wmma::mma_sync(acc, a[k], b, acc);
        }
        if (!half_out) {
            wmma::store_matrix_sync(&outf[(nb + rt * 16) * HC + c0], acc, HC, wmma::mem_row_major);
        } else {
            wmma::store_matrix_sync(&fbp[w][0], acc, 16, wmma::mem_row_major);
            __syncwarp();
            int r = lane >> 1, cf = (lane & 1) * 8;
            const float* src = &fbp[w][r * 16 + cf];
            __half hb[8];
            #pragma unroll
            for (int j = 0; j < 8; j++) hb[j] = __float2half(src[j]);
            *(uint4*)&outh[(nb + rt * 16 + r) * HC + c0 + cf] = *(uint4*)hb;
            __syncwarp();
        }
    }
}

// ---------------- edge MLP: fp16 wmma, 128 edges/block ---------------------
__global__ void k_edgemlp(const float* __restrict__ eattr,
                          const float* __restrict__ we1, const float* __restrict__ be1,
                          const float* __restrict__ we2, const float* __restrict__ be2,
                          const float* __restrict__ we3, const float* __restrict__ be3,
                          int e) {
    extern __shared__ __half smh[];
    __half* es  = smh;
    __half* w1b = smh + 2048;
    __half* w2b = smh + 3200;
    __half* w3b = smh + 8960;
    __half* h1h = smh + 14720;
    __half* h2h = smh + 25984;
    float*  fb  = (float*)(smh + 37248);

    int tid = threadIdx.x;
    int pb = blockIdx.x * 128;

    for (int i = tid; i < 1152; i += 256) {
        int r = i / 72, c = i - r * 72;
        float v = 0.f;
        if (c < 64) v = (r < 8) ? __ldg(&we1[r * 64 + c]) : ((r == 8) ? __ldg(&be1[c]) : 0.f);
        w1b[i] = __float2half(v);
    }
    for (int i = tid; i < 5760; i += 256) {
        int r = i / 72, c = i - r * 72;
        float v2 = 0.f, v3 = 0.f;
        if (c < 64) {
            if (r < 64)      { v2 = __ldg(&we2[r * 64 + c]); v3 = __ldg(&we3[r * 64 + c]); }
            else if (r == 64){ v2 = __ldg(&be2[c]);          v3 = __ldg(&be3[c]); }
        }
        w2b[i] = __float2half(v2);
        w3b[i] = __float2half(v3);
    }
    for (int i = tid; i < 2048; i += 256) {
        int r = i >> 4, c = i & 15;
        float v = 0.f;
        if (c < 8) {
            int p = pb + r;
            if (p < e) v = __ldg(&eattr[g_eid[p] * 8 + c]);
        } else if (c == 8) v = 1.0f;
        es[i] = __float2half(v);
    }
    for (int i = tid; i < 3072; i += 256) {
        int r = i / 24, c = 64 + (i - r * 24);
        __half v = __float2half((c == 64) ? 1.0f : 0.f);
        h1h[r * 88 + c] = v;
        h2h[r * 88 + c] = v;
    }
    __syncthreads();

    int w = tid >> 5;

    {
        HFragA a;
        wmma::load_matrix_sync(a, &es[w * 16 * 16], 16);
        #pragma unroll
        for (int nf = 0; nf < 4; nf++) {
            HFragC acc;
            wmma::fill_fragment(acc, 0.f);
            HFragB b;
            wmma::load_matrix_sync(b, &w1b[nf * 16], 72);
            wmma::mma_sync(acc, a, b, acc);
            wmma::store_matrix_sync(&fb[w * 16 * 72 + nf * 16], acc, 72, wmma::mem_row_major);
        }
    }
    __syncthreads();
    for (int i = tid; i < 8192; i += 256) {
        int r = i >> 6, c = i & 63;
        h1h[r * 88 + c] = __float2half(fmaxf(fb[r * 72 + c], 0.f));
    }
    __syncthreads();

    {
        HFragA a[5];
        #pragma unroll
        for (int k = 0; k < 5; k++)
            wmma::load_matrix_sync(a[k], &h1h[w * 16 * 88 + k * 16], 88);
        #pragma unroll
        for (int nf = 0; nf < 4; nf++) {
            HFragC acc;
            wmma::fill_fragment(acc, 0.f);
            #pragma unroll
            for (int k = 0; k < 5; k++) {
                HFragB b;
                wmma::load_matrix_sync(b, &w2b[k * 16 * 72 + nf * 16], 72);
                wmma::mma_sync(acc, a[k], b, acc);
            }
            wmma::store_matrix_sync(&fb[w * 16 * 72 + nf * 16], acc, 72, wmma::mem_row_major);
        }
    }
    __syncthreads();
    for (int i = tid; i < 8192; i += 256) {
        int r = i >> 6, c = i & 63;
        h2h[r * 88 + c] = __float2half(fmaxf(fb[r * 72 + c], 0.f));
    }
    __syncthreads();

    {
        HFragA a[5];
        #pragma unroll
        for (int k = 0; k < 5; k++)
            wmma::load_matrix_sync(a[k], &h2h[w * 16 * 88 + k * 16], 88);
        #pragma unroll
        for (int nf = 0; nf < 4; nf++) {
            HFragC acc;
            wmma::fill_fragment(acc, 0.f);
            #pragma unroll
            for (int k = 0; k < 5; k++) {
                HFragB b;
                wmma::load_matrix_sync(b, &w3b[k * 16 * 72 + nf * 16], 72);
                wmma::mma_sync(acc, a[k], b, acc);
            }
            wmma::store_matrix_sync(&fb[w * 16 * 72 + nf * 16], acc, 72, wmma::mem_row_major);
        }
    }
    __syncthreads();
    {
        int nrows = min(128, e - pb);
        for (int i = tid * 2; i < nrows * 64; i += 512) {
            int r = i >> 6, c = i & 63;
            __half2 hv = __floats2half2_rn(fmaxf(fb[r * 72 + c], 0.f),
                                           fmaxf(fb[r * 72 + c + 1], 0.f));
            *(__half2*)&g_eh[(pb + r) * 64 + c] = hv;
        }
    }
}

// ---------------- attention ----------------
__device__ __forceinline__ float dot4(float4 a, float4 b) {
    return a.x * b.x + a.y * b.y + a.z * b.z + a.w * b.w;
}
__device__ __forceinline__ void ldh8(const __half* p, float4& a, float4& b) {
    uint4 u = *(const uint4*)p;
    float2 f0 = __half22float2(*(__half2*)&u.x);
    float2 f1 = __half22float2(*(__half2*)&u.y);
    float2 f2 = __half22float2(*(__half2*)&u.z);
    float2 f3 = __half22float2(*(__half2*)&u.w);
    a = make_float4(f0.x, f0.y, f1.x, f1.y);
    b = make_float4(f2.x, f2.y, f3.x, f3.y);
}

__global__ void __launch_bounds__(256) k_attn(int n) {
    int gw = (blockIdx.x * blockDim.x + threadIdx.x) >> 5;
    int lane = threadIdx.x & 31;
    if (gw >= n) return;
    int node = gw;
    int beg = g_rowptr[node], end = g_rowptr[node + 1];

    int h = lane >> 3;
    int c8 = (lane & 7) * 8;
    int chan = h * 64 + c8;

    float4 q0 = *(const float4*)&g_q[node * HC + chan];
    float4 q1 = *(const float4*)&g_q[node * HC + chan + 4];
    float4 gg0 = *(const float4*)&g_g[node * HC + chan];
    float4 gg1 = *(const float4*)&g_g[node * HC + chan + 4];
    float qb = g_qb[node * 4 + h];

    float s = 0.f;
    float4 av0 = {0,0,0,0}, av1 = {0,0,0,0};
    float4 at0 = {0,0,0,0}, at1 = {0,0,0,0};

    int p = beg;
    for (; p + 4 <= end; p += 4) {
        int src[4];
        #pragma unroll
        for (int u = 0; u < 4; u++) src[u] = g_src[p + u];

        float d[4];
        float4 e0[4], e1[4], v0[4], v1[4];
        #pragma unroll
        for (int u = 0; u < 4; u++) {
            float4 k0, k1;
            ldh8(&g_kh[src[u] * HC + chan], k0, k1);
            ldh8(&g_eh[(p + u) * 64 + c8], e0[u], e1[u]);
            ldh8(&g_vh[src[u] * HC + chan], v0[u], v1[u]);
            d[u] = dot4(q0, k0) + dot4(q1, k1) + dot4(gg0, e0[u]) + dot4(gg1, e1[u]);
        }
        #pragma unroll
        for (int off = 1; off < 8; off <<= 1) {
            #pragma unroll
            for (int u = 0; u < 4; u++)
                d[u] += __shfl_xor_sync(0xffffffffu, d[u], off);
        }
        float pe[4];
        #pragma unroll
        for (int u = 0; u < 4; u++) {
            pe[u] = __expf((d[u] + qb) * 0.125f);
            s += pe[u];
        }
        #pragma unroll
        for (int u = 0; u < 4; u++) {
            av0.x += pe[u] * v0[u].x;  av0.y += pe[u] * v0[u].y;
            av0.z += pe[u] * v0[u].z;  av0.w += pe[u] * v0[u].w;
            av1.x += pe[u] * v1[u].x;  av1.y += pe[u] * v1[u].y;
            av1.z += pe[u] * v1[u].z;  av1.w += pe[u] * v1[u].w;
            at0.x += pe[u] * e0[u].x;  at0.y += pe[u] * e0[u].y;
            at0.z += pe[u] * e0[u].z;  at0.w += pe[u] * e0[u].w;
            at1.x += pe[u] * e1[u].x;  at1.y += pe[u] * e1[u].y;
            at1.z += pe[u] * e1[u].z;  at1.w += pe[u] * e1[u].w;
        }
    }
    for (; p < end; p++) {
        int src = g_src[p];
        float4 k0, k1, e0, e1, v0, v1;
        ldh8(&g_kh[src * HC + chan], k0, k1);
        ldh8(&g_eh[p * 64 + c8],     e0, e1);
        ldh8(&g_vh[src * HC + chan], v0, v1);
        float d = dot4(q0, k0) + dot4(q1, k1) + dot4(gg0, e0) + dot4(gg1, e1);
        d += __shfl_xor_sync(0xffffffffu, d, 1);
        d += __shfl_xor_sync(0xffffffffu, d, 2);
        d += __shfl_xor_sync(0xffffffffu, d, 4);
        float pe = __expf((d + qb) * 0.125f);
        s += pe;
        av0.x += pe * v0.x; av0.y += pe * v0.y; av0.z += pe * v0.z; av0.w += pe * v0.w;
        av1.x += pe * v1.x; av1.y += pe * v1.y; av1.z += pe * v1.z; av1.w += pe * v1.w;
        at0.x += pe * e0.x; at0.y += pe * e0.y; at0.z += pe * e0.z; at0.w += pe * e0.w;
        at1.x += pe * e1.x; at1.y += pe * e1.y; at1.z += pe * e1.z; at1.w += pe * e1.w;
    }

    float sinv = 1.f / (s + 1e-16f);
    float4 o0 = {av0.x * sinv, av0.y * sinv, av0.z * sinv, av0.w * sinv};
    float4 o1 = {av1.x * sinv, av1.y * sinv, av1.z * sinv, av1.w * sinv};
    float4 t0 = {at0.x * sinv, at0.y * sinv, at0.z * sinv, at0.w * sinv};
    float4 t1 = {at1.x * sinv, at1.y * sinv, at1.z * sinv, at1.w * sinv};
    *(float4*)&g_outv[node * HC + chan]     = o0;
    *(float4*)&g_outv[node * HC + chan + 4] = o1;
    *(float4*)&g_t   [node * HC + chan]     = t0;
    *(float4*)&g_t   [node * HC + chan + 4] = t1;
    if ((lane & 7) == 0) g_suma[node * 4 + h] = s * sinv;
}

// ---------------- fused epilogue (16 nodes/block) --------------------------
__global__ void k_posthead(const float* __restrict__ wedge, const float* __restrict__ bedge,
                           const float* __restrict__ ln_g, const float* __restrict__ ln_b,
                           const float* __restrict__ w1, const float* __restrict__ b1,
                           const float* __restrict__ w2, const float* __restrict__ b2,
                           float* __restrict__ out, int n) {
    __shared__ float ts[16 * HC];
    __shared__ float os[16 * HC];
    __shared__ float hs[16 * 128];
    __shared__ float ls[16][NCLS];
    int tid = threadIdx.x;
    int nb = blockIdx.x * 16;
    for (int i = tid; i < 16 * HC; i += 256) {
        int nn = nb + (i >> 8);
        ts[i] = (nn < n) ? g_t[nn * HC + (i & 255)] : 0.f;
    }
    __syncthreads();

    int h = tid >> 6;
    float acc[16];
    #pragma unroll
    for (int m = 0; m < 16; m++) acc[m] = 0.f;
    for (int i = 0; i < 64; i++) {
        float w = __ldg(&wedge[i * HC + tid]);
        #pragma unroll
        for (int m = 0; m < 16; m++) acc[m] += ts[m * HC + h * 64 + i] * w;
    }
    float be = __ldg(&bedge[tid]);
    #pragma unroll
    for (int m = 0; m < 16; m++) {
        int nn = nb + m;
        if (nn < n) {
            os[m * HC + tid] = g_outv[nn * HC + tid] + g_suma[nn * 4 + h] * be
                             + g_skip[nn * HC + tid] + acc[m];
        }
    }
    __syncthreads();

    int wid = tid >> 5, lane = tid & 31;
    for (int m = wid; m < 16; m += 8) {
        int nn = nb + m;
        if (nn >= n) continue;
        float sum = 0.f, sq = 0.f;
        #pragma unroll
        for (int u = 0; u < 8; u++) {
            float v = os[m * HC + u * 32 + lane];
            sum += v; sq += v * v;
        }
        #pragma unroll
        for (int off = 16; off; off >>= 1) {
            sum += __shfl_xor_sync(0xffffffffu, sum, off);
            sq  += __shfl_xor_sync(0xffffffffu, sq,  off);
        }
        float mu = sum * (1.f / 256.f);
        float var = sq * (1.f / 256.f) - mu * mu;
        float rs = rsqrtf(var + 1e-5f);
        #pragma unroll
        for (int u = 0; u < 8; u++) {
            int j = u * 32 + lane;
            float v = (os[m * HC + j] - mu) * rs * __ldg(&ln_g[j]) + __ldg(&ln_b[j]);
            ts[m * HC + j] = fmaxf(v, 0.f);
        }
    }
    __syncthreads();

    {
        int col = tid & 127, rg = tid >> 7;
        float a8[8];
        float bb = __ldg(&b1[col]);
        #pragma unroll
        for (int r = 0; r < 8; r++) a8[r] = bb;
        for (int i = 0; i < HC; i++) {
            float w = __ldg(&w1[i * 128 + col]);
            #pragma unroll
            for (int r = 0; r < 8; r++) a8[r] += ts[(rg * 8 + r) * HC + i] * w;
        }
        #pragma unroll
        for (int r = 0; r < 8; r++) hs[(rg * 8 + r) * 128 + col] = fmaxf(a8[r], 0.f);
    }
    __syncthreads();

    if (tid < 64) {
        int m = tid >> 2, c = tid & 3;
        float a = __ldg(&b2[c]);
        for (int i = 0; i < 128; i++) a += hs[m * 128 + i] * __ldg(&w2[i * NCLS + c]);
        ls[m][c] = a;
    }
    __syncthreads();
    if (tid < 16) {
        int nn = nb + tid;
        if (nn < n) {
            float l0 = ls[tid][0], l1 = ls[tid][1], l2 = ls[tid][2], l3 = ls[tid][3];
            float mx = fmaxf(fmaxf(l0, l1), fmaxf(l2, l3));
            float se = expf(l0 - mx) + expf(l1 - mx) + expf(l2 - mx) + expf(l3 - mx);
            float lse = mx + logf(se);
            out[nn * NCLS + 0] = l0 - lse;
            out[nn * NCLS + 1] = l1 - lse;
            out[nn * NCLS + 2] = l2 - lse;
            out[nn * NCLS + 3] = l3 - lse;
        }
    }
}

// ---------------- launcher: fork node pipeline onto stream B ---------------
extern "C" void kernel_launch(void* const* d_in, const int* in_sizes, int n_in,
                              void* d_out, int out_size) {
    const float* x     = (const float*)d_in[0];
    const int*   ei    = (const int*)  d_in[1];
    const float* eattr = (const float*)d_in[2];
    const float* w00   = (const float*)d_in[3];
    const float* b00   = (const float*)d_in[4];
    const float* we1   = (const float*)d_in[5];
    const float* be1   = (const float*)d_in[6];
    const float* we2   = (const float*)d_in[7];
    const float* be2   = (const float*)d_in[8];
    const float* we3   = (const float*)d_in[9];
    const float* be3   = (const float*)d_in[10];
    const float* wq    = (const float*)d_in[11];
    const float* bq    = (const float*)d_in[12];
    const float* wk    = (const float*)d_in[13];
    const float* bk    = (const float*)d_in[14];
    const float* wv    = (const float*)d_in[15];
    const float* bv    = (const float*)d_in[16];
    const float* wedge = (const float*)d_in[17];
    const float* bedge = (const float*)d_in[18];
    const float* wskip = (const float*)d_in[19];
    const float* bskip = (const float*)d_in[20];
    const float* ln_g  = (const float*)d_in[21];
    const float* ln_b  = (const float*)d_in[22];
    const float* w1    = (const float*)d_in[23];
    const float* b1    = (const float*)d_in[24];
    const float* w2    = (const float*)d_in[25];
    const float* b2    = (const float*)d_in[26];
    float* out = (float*)d_out;

    int n = in_sizes[0] / NFEAT;
    int e = in_sizes[1] / 2;
    int nblk = (n + 255) / 256;

    static cudaStream_t sB = nullptr;
    static cudaEvent_t evF = nullptr, evJ = nullptr;
    static bool attrs_set = false;
    if (sB == nullptr) {
        cudaStreamCreateWithFlags(&sB, cudaStreamNonBlocking);
        cudaEventCreateWithFlags(&evF, cudaEventDisableTiming);
        cudaEventCreateWithFlags(&evJ, cudaEventDisableTiming);
    }
    static const int EDGE_SMEM = 111360;
    static const int PROJ_SMEM = (5632 + 21120) * 2;
    if (!attrs_set) {
        cudaFuncSetAttribute(k_edgemlp, cudaFuncAttributeMaxDynamicSharedMemorySize, EDGE_SMEM);
        cudaFuncSetAttribute(k_proj,    cudaFuncAttributeMaxDynamicSharedMemorySize, PROJ_SMEM);
        attrs_set = true;
    }

    // fork
    cudaEventRecord(evF, 0);
    cudaStreamWaitEvent(sB, evF, 0);

    // ---- stream B: node pipeline ----
    k_foldw<<<65, 256, 0, sB>>>(wq, bq, wedge);
    k_foldqb<<<1, 256, 0, sB>>>(wq, bq, bedge);
    k_node_embed<<<(n + 63) / 64, 256, 0, sB>>>(x, w00, b00, n);
    {
        dim3 grid((n + 63) / 64, 5);
        k_proj<<<grid, 256, PROJ_SMEM, sB>>>(wq, bq, wk, bk, wv, bv, wskip, bskip, n);
    }
    k_qb<<<(n + 63) / 64, 256, 0, sB>>>(n);
    cudaEventRecord(evJ, sB);

    // ---- capture stream: CSR build + edge MLP ----
    k_zero_deg<<<(n + 255) / 256, 256>>>(n);
    k_hist<<<(e + 255) / 256, 256>>>(ei, e);
    k_blocksum<<<nblk, 256>>>(n);
    k_scanpart<<<1, 256>>>(nblk);
    k_scanfinal<<<nblk, 256>>>(n);
    k_scatter<<<(e + 255) / 256, 256>>>(ei, e);
    k_edgemlp<<<(e + 127) / 128, 256, EDGE_SMEM>>>(eattr, we1, be1, we2, be2, we3, be3, e);

    // join
    cudaStreamWaitEvent(0, evJ, 0);

    k_attn<<<(n + 7) / 8, 256>>>(n);
    k_posthead<<<(n + 15) / 16, 256>>>(wedge, bedge, ln_g, ln_b, w1, b1, w2, b2, out, n);
}

// round 15
// speedup vs baseline: 1.3613x; 1.1638x over previous
#include <cuda_runtime.h>
#include <cuda_fp16.h>
#include <mma.h>
#include <math.h>
#include <stdint.h>

using namespace nvcuda;

#define NFEAT 16
#define EFEAT 8
#define HC    256
#define NCLS  4

static const int MAXN = 50000;
static const int NPAD = 50048;
static const int MAXE = 800000;

typedef wmma::fragment<wmma::matrix_a, 16, 16, 16, __half, wmma::row_major> HFragA;
typedef wmma::fragment<wmma::matrix_b, 16, 16, 16, __half, wmma::row_major> HFragB;
typedef wmma::fragment<wmma::accumulator, 16, 16, 16, float> HFragC;

// ---------------- scratch ----------------
__device__ float  g_x1  [MAXN * 64];
__device__ float  g_q   [NPAD * HC];
__device__ __half g_kh  [NPAD * HC];
__device__ __half g_vh  [NPAD * HC];
__device__ float  g_skip[NPAD * HC];
__device__ float  g_g   [NPAD * HC];
__device__ float  g_qb  [MAXN * 4];
__device__ __half g_eh  [MAXE * 64];
__device__ float  g_outv[MAXN * HC];
__device__ float  g_t   [MAXN * HC];
__device__ float  g_suma[MAXN * 4];
__device__ float  g_wg  [64 * HC];
__device__ float  g_bg  [HC];
__device__ float  g_wqb [64 * 4];
__device__ float  g_cb  [4];
__device__ __half g_pw  [5 * 80 * 264];   // fp16 proj weight panels
__device__ __half g_ew1 [16 * 72];
__device__ __half g_ew2 [80 * 72];
__device__ __half g_ew3 [80 * 72];
__device__ int    g_deg [MAXN];
__device__ int    g_rowptr[MAXN + 1];
__device__ int    g_cursor[MAXN];
__device__ int    g_eid [MAXE];
__device__ int    g_src [MAXE];
__device__ int    g_part[256];
__device__ int    g_partoff[256];

// ---------------- CSR build ----------------
__global__ void k_zero_deg(int n) {
    int i = blockIdx.x * blockDim.x + threadIdx.x;
    if (i < n) g_deg[i] = 0;
}
__global__ void k_hist(const int* __restrict__ ei, int e) {
    int i = blockIdx.x * blockDim.x + threadIdx.x;
    if (i < e) atomicAdd(&g_deg[ei[e + i]], 1);
}
__global__ void k_blocksum(int n) {
    __shared__ int sh[256];
    int tid = threadIdx.x;
    int i = blockIdx.x * 256 + tid;
    sh[tid] = (i < n) ? g_deg[i] : 0;
    __syncthreads();
    for (int off = 128; off; off >>= 1) {
        if (tid < off) sh[tid] += sh[tid + off];
        __syncthreads();
    }
    if (tid == 0) g_part[blockIdx.x] = sh[0];
}
__global__ void k_scanpart(int nb) {
    __shared__ int sh[256];
    int tid = threadIdx.x;
    int v = (tid < nb) ? g_part[tid] : 0;
    sh[tid] = v;
    __syncthreads();
    for (int off = 1; off < 256; off <<= 1) {
        int y = (tid >= off) ? sh[tid - off] : 0;
        __syncthreads();
        sh[tid] += y;
        __syncthreads();
    }
    g_partoff[tid] = sh[tid] - v;
}
__global__ void k_scanfinal(int n) {
    __shared__ int sh[256];
    int tid = threadIdx.x;
    int i = blockIdx.x * 256 + tid;
    int v = (i < n) ? g_deg[i] : 0;
    sh[tid] = v;
    __syncthreads();
    for (int off = 1; off < 256; off <<= 1) {
        int y = (tid >= off) ? sh[tid - off] : 0;
        __syncthreads();
        sh[tid] += y;
        __syncthreads();
    }
    int base = g_partoff[blockIdx.x];
    if (i < n) {
        int incl = base + sh[tid];
        g_rowptr[i + 1] = incl;
        g_cursor[i]     = incl - v;
    }
    if (i == 0) g_rowptr[0] = 0;
}
__global__ void k_scatter(const int* __restrict__ ei, int e) {
    int i = blockIdx.x * blockDim.x + threadIdx.x;
    if (i < e) {
        int dst = ei[e + i];
        int pos = atomicAdd(&g_cursor[dst], 1);
        g_eid[pos] = i;
        g_src[pos] = ei[i];
    }
}

// ---------------- weight folding (one-time, tiny) ----------------
__global__ void k_foldw(const float* __restrict__ wq, const float* __restrict__ bq,
                        const float* __restrict__ wedge) {
    int f = blockIdx.x;
    int j = threadIdx.x;
    int h = j >> 6, ii = j & 63;
    const float* src = (f < 64) ? &wq[f * HC] : bq;
    float s = 0.f;
    for (int c = 0; c < 64; c++)
        s += src[h * 64 + c] * __ldg(&wedge[ii * HC + h * 64 + c]);
    if (f < 64) g_wg[f * HC + j] = s;
    else        g_bg[j] = s;
}
__global__ void k_foldqb(const float* __restrict__ wq, const float* __restrict__ bq,
                         const float* __restrict__ bedge) {
    int j = threadIdx.x;
    int f = j >> 2, h = j & 3;
    float s = 0.f;
    for (int c = 0; c < 64; c++)
        s += wq[f * HC + h * 64 + c] * __ldg(&bedge[h * 64 + c]);
    g_wqb[f * 4 + h] = s;
    if (j < 4) {
        float cb = 0.f;
        for (int c = 0; c < 64; c++) cb += bq[j * 64 + c] * bedge[j * 64 + c];
        g_cb[j] = cb;
    }
}

// ---------------- one-time fp16 weight panel conversion --------------------
__global__ void k_cvtw(const float* __restrict__ W0, const float* __restrict__ B0,
                       const float* __restrict__ W1, const float* __restrict__ B1,
                       const float* __restrict__ W2, const float* __restrict__ B2,
                       const float* __restrict__ W3, const float* __restrict__ B3) {
    int sel = blockIdx.y;
    const float* W = (sel == 0) ? W0 : (sel == 1) ? W1 : (sel == 2) ? W2 :
                     (sel == 3) ? W3 : g_wg;
    const float* B = (sel == 0) ? B0 : (sel == 1) ? B1 : (sel == 2) ? B2 :
                     (sel == 3) ? B3 : g_bg;
    int idx = blockIdx.x * 256 + threadIdx.x;
    if (idx >= 80 * 264) return;
    int r = idx / 264, c = idx - r * 264;
    float v = 0.f;
    if (c < 256) {
        if (r < 64) v = __ldg(&W[r * 256 + c]);
        else if (r == 64) v = __ldg(&B[c]);
    }
    g_pw[sel * (80 * 264) + idx] = __float2half(v);
}
__global__ void k_cvte(const float* __restrict__ we1, const float* __restrict__ be1,
                       const float* __restrict__ we2, const float* __restrict__ be2,
                       const float* __restrict__ we3, const float* __restrict__ be3) {
    int idx = blockIdx.x * 256 + threadIdx.x;
    if (idx < 1152) {
        int r = idx / 72, c = idx - r * 72;
        float v = 0.f;
        if (c < 64) v = (r < 8) ? __ldg(&we1[r * 64 + c]) : ((r == 8) ? __ldg(&be1[c]) : 0.f);
        g_ew1[idx] = __float2half(v);
    } else if (idx < 1152 + 5760) {
        int k = idx - 1152;
        int r = k / 72, c = k - r * 72;
        float v = 0.f;
        if (c < 64) {
            if (r < 64) v = __ldg(&we2[r * 64 + c]);
            else if (r == 64) v = __ldg(&be2[c]);
        }
        g_ew2[k] = __float2half(v);
    } else if (idx < 1152 + 11520) {
        int k = idx - 1152 - 5760;
        int r = k / 72, c = k - r * 72;
        float v = 0.f;
        if (c < 64) {
            if (r < 64) v = __ldg(&we3[r * 64 + c]);
            else if (r == 64) v = __ldg(&be3[c]);
        }
        g_ew3[k] = __float2half(v);
    }
}

// ---------------- node embed ----------------
__global__ void k_node_embed(const float* __restrict__ x,
                             const float* __restrict__ w00,
                             const float* __restrict__ b00, int n) {
    __shared__ float ws[NFEAT * 64];
    __shared__ float xs[64][NFEAT];
    int tid = threadIdx.x;
    for (int i = tid; i < NFEAT * 64; i += 256) ws[i] = w00[i];
    int nb = blockIdx.x * 64;
    for (int i = tid; i < 64 * NFEAT; i += 256) {
        int nn = nb + i / NFEAT;
        xs[i / NFEAT][i % NFEAT] = (nn < n) ? x[nn * NFEAT + (i % NFEAT)] : 0.f;
    }
    __syncthreads();
    int ln = tid >> 2;
    int node = nb + ln;
    int c0 = (tid & 3) * 16;
    if (node < n) {
        #pragma unroll
        for (int j = 0; j < 16; j++) {
            float acc = __ldg(&b00[c0 + j]);
            #pragma unroll
            for (int i = 0; i < NFEAT; i++) acc += xs[ln][i] * ws[i * 64 + c0 + j];
            g_x1[node * 64 + c0 + j] = fmaxf(acc, 0.f);
        }
    }
}

// ---------------- qb = x1 @ wqb + cb ----------------
__global__ void k_qb(int n) {
    __shared__ float ws[64 * 4];
    int tid = threadIdx.x;
    ws[tid] = g_wqb[tid];
    __syncthreads();
    int idx = blockIdx.x * 64 + (tid >> 2);
    int h = tid & 3;
    if (idx < n) {
        float s = g_cb[h];
        const float* xr = &g_x1[idx * 64];
        #pragma unroll 16
        for (int f = 0; f < 64; f++) s += xr[f] * ws[f * 4 + h];
        g_qb[idx * 4 + h] = s;
    }
}

// ---------------- projections: fp16 wmma; B frags from global panels ------
__global__ void k_proj(int n) {
    int sel = blockIdx.y;
    bool half_out = (sel == 1 || sel == 2);
    float*  outf = (sel == 0) ? g_q : (sel == 3) ? g_skip : g_g;
    __half* outh = (sel == 1) ? g_kh : g_vh;
    const __half* gw = &g_pw[sel * (80 * 264)];

    __shared__ __half xsh[64 * 88];
    __shared__ float fbp[8][256];

    int tid = threadIdx.x;
    int nb = blockIdx.x * 64;

    for (int i = tid; i < 64 * 88; i += 256) {
        int r = i / 88, c = i - r * 88;
        float v = 0.f;
        if (c < 64) {
            int node = nb + r;
            if (node < n) v = __ldg(&g_x1[node * 64 + c]);
        } else if (c == 64) v = 1.0f;
        xsh[i] = __float2half(v);
    }
    __syncthreads();

    int w = tid >> 5, lane = tid & 31;
    int rt = w >> 1;
    int ch = w & 1;

    HFragA a[5];
    #pragma unroll
    for (int k = 0; k < 5; k++)
        wmma::load_matrix_sync(a[k], &xsh[rt * 16 * 88 + k * 16], 88);

    #pragma unroll
    for (int nf = 0; nf < 8; nf++) {
        int c0 = ch * 128 + nf * 16;
        HFragC acc;
        wmma::fill_fragment(acc, 0.f);
        #pragma unroll
        for (int k = 0; k < 5; k++) {
            HFragB b;
            wmma::load_matrix_sync(b, gw + k * 16 * 264 + c0, 264);
            wmma::mma_sync(acc, a[k], b, acc);
        }
        if (!half_out) {
            wmma::store_matrix_sync(&outf[(nb + rt * 16) * HC + c0], acc, HC, wmma::mem_row_major);
        } else {
            wmma::store_matrix_sync(&fbp[w][0], acc, 16, wmma::mem_row_major);
            __syncwarp();
            int r = lane >> 1, cf = (lane & 1) * 8;
            const float* src = &fbp[w][r * 16 + cf];
            __half hb[8];
            #pragma unroll
            for (int j = 0; j < 8; j++) hb[j] = __float2half(src[j]);
            *(uint4*)&outh[(nb + rt * 16 + r) * HC + c0 + cf] = *(uint4*)hb;
            __syncwarp();
        }
    }
}

// ---------------- edge MLP: fp16 wmma, 128 edges/block ---------------------
__global__ void k_edgemlp(const float* __restrict__ eattr, int e) {
    extern __shared__ __half smh[];
    __half* es  = smh;
    __half* w1b = smh + 2048;
    __half* w2b = smh + 3200;
    __half* w3b = smh + 8960;
    __half* h1h = smh + 14720;
    __half* h2h = smh + 25984;
    float*  fb  = (float*)(smh + 37248);

    int tid = threadIdx.x;
    int pb = blockIdx.x * 128;

    // raw copies from pre-converted panels
    for (int i = tid; i < 576; i += 256)
        ((unsigned int*)w1b)[i] = ((const unsigned int*)g_ew1)[i];
    for (int i = tid; i < 2880; i += 256) {
        ((unsigned int*)w2b)[i] = ((const unsigned int*)g_ew2)[i];
        ((unsigned int*)w3b)[i] = ((const unsigned int*)g_ew3)[i];
    }
    for (int i = tid; i < 2048; i += 256) {
        int r = i >> 4, c = i & 15;
        float v = 0.f;
        if (c < 8) {
            int p = pb + r;
            if (p < e) v = __ldg(&eattr[g_eid[p] * 8 + c]);
        } else if (c == 8) v = 1.0f;
        es[i] = __float2half(v);
    }
    for (int i = tid; i < 3072; i += 256) {
        int r = i / 24, c = 64 + (i - r * 24);
        __half v = __float2half((c == 64) ? 1.0f : 0.f);
        h1h[r * 88 + c] = v;
        h2h[r * 88 + c] = v;
    }
    __syncthreads();

    int w = tid >> 5;

    {
        HFragA a;
        wmma::load_matrix_sync(a, &es[w * 16 * 16], 16);
        #pragma unroll
        for (int nf = 0; nf < 4; nf++) {
            HFragC acc;
            wmma::fill_fragment(acc, 0.f);
            HFragB b;
            wmma::load_matrix_sync(b, &w1b[nf * 16], 72);
            wmma::mma_sync(acc, a, b, acc);
            wmma::store_matrix_sync(&fb[w * 16 * 72 + nf * 16], acc, 72, wmma::mem_row_major);
        }
    }
    __syncthreads();
    for (int i = tid; i < 8192; i += 256) {
        int r = i >> 6, c = i & 63;
        h1h[r * 88 + c] = __float2half(fmaxf(fb[r * 72 + c], 0.f));
    }
    __syncthreads();

    {
        HFragA a[5];
        #pragma unroll
        for (int k = 0; k < 5; k++)
            wmma::load_matrix_sync(a[k], &h1h[w * 16 * 88 + k * 16], 88);
        #pragma unroll
        for (int nf = 0; nf < 4; nf++) {
            HFragC acc;
            wmma::fill_fragment(acc, 0.f);
            #pragma unroll
            for (int k = 0; k < 5; k++) {
                HFragB b;
                wmma::load_matrix_sync(b, &w2b[k * 16 * 72 + nf * 16], 72);
                wmma::mma_sync(acc, a[k], b, acc);
            }
            wmma::store_matrix_sync(&fb[w * 16 * 72 + nf * 16], acc, 72, wmma::mem_row_major);
        }
    }
    __syncthreads();
    for (int i = tid; i < 8192; i += 256) {
        int r = i >> 6, c = i & 63;
        h2h[r * 88 + c] = __float2half(fmaxf(fb[r * 72 + c], 0.f));
    }
    __syncthreads();

    {
        HFragA a[5];
        #pragma unroll
        for (int k = 0; k < 5; k++)
            wmma::load_matrix_sync(a[k], &h2h[w * 16 * 88 + k * 16], 88);
        #pragma unroll
        for (int nf = 0; nf < 4; nf++) {
            HFragC acc;
            wmma::fill_fragment(acc, 0.f);
            #pragma unroll
            for (int k = 0; k < 5; k++) {
                HFragB b;
                wmma::load_matrix_sync(b, &w3b[k * 16 * 72 + nf * 16], 72);
                wmma::mma_sync(acc, a[k], b, acc);
            }
            wmma::store_matrix_sync(&fb[w * 16 * 72 + nf * 16], acc, 72, wmma::mem_row_major);
        }
    }
    __syncthreads();
    {
        int nrows = min(128, e - pb);
        for (int i = tid * 2; i < nrows * 64; i += 512) {
            int r = i >> 6, c = i & 63;
            __half2 hv = __floats2half2_rn(fmaxf(fb[r * 72 + c], 0.f),
                                           fmaxf(fb[r * 72 + c + 1], 0.f));
            *(__half2*)&g_eh[(pb + r) * 64 + c] = hv;
        }
    }
}

// ---------------- attention ----------------
__device__ __forceinline__ float dot4(float4 a, float4 b) {
    return a.x * b.x + a.y * b.y + a.z * b.z + a.w * b.w;
}
__device__ __forceinline__ void ldh8(const __half* p, float4& a, float4& b) {
    uint4 u = *(const uint4*)p;
    float2 f0 = __half22float2(*(__half2*)&u.x);
    float2 f1 = __half22float2(*(__half2*)&u.y);
    float2 f2 = __half22float2(*(__half2*)&u.z);
    float2 f3 = __half22float2(*(__half2*)&u.w);
    a = make_float4(f0.x, f0.y, f1.x, f1.y);
    b = make_float4(f2.x, f2.y, f3.x, f3.y);
}

__global__ void __launch_bounds__(256) k_attn(int n) {
    int gw = (blockIdx.x * blockDim.x + threadIdx.x) >> 5;
    int lane = threadIdx.x & 31;
    if (gw >= n) return;
    int node = gw;
    int beg = g_rowptr[node], end = g_rowptr[node + 1];

    int h = lane >> 3;
    int c8 = (lane & 7) * 8;
    int chan = h * 64 + c8;

    float4 q0 = *(const float4*)&g_q[node * HC + chan];
    float4 q1 = *(const float4*)&g_q[node * HC + chan + 4];
    float4 gg0 = *(const float4*)&g_g[node * HC + chan];
    float4 gg1 = *(const float4*)&g_g[node * HC + chan + 4];
    float qb = g_qb[node * 4 + h];

    float s = 0.f;
    float4 av0 = {0,0,0,0}, av1 = {0,0,0,0};
    float4 at0 = {0,0,0,0}, at1 = {0,0,0,0};

    int p = beg;
    for (; p + 4 <= end; p += 4) {
        int src[4];
        #pragma unroll
        for (int u = 0; u < 4; u++) src[u] = g_src[p + u];

        float d[4];
        float4 e0[4], e1[4], v0[4], v1[4];
        #pragma unroll
        for (int u = 0; u < 4; u++) {
            float4 k0, k1;
            ldh8(&g_kh[src[u] * HC + chan], k0, k1);
            ldh8(&g_eh[(p + u) * 64 + c8], e0[u], e1[u]);
            ldh8(&g_vh[src[u] * HC + chan], v0[u], v1[u]);
            d[u] = dot4(q0, k0) + dot4(q1, k1) + dot4(gg0, e0[u]) + dot4(gg1, e1[u]);
        }
        #pragma unroll
        for (int off = 1; off < 8; off <<= 1) {
            #pragma unroll
            for (int u = 0; u < 4; u++)
                d[u] += __shfl_xor_sync(0xffffffffu, d[u], off);
        }
        float pe[4];
        #pragma unroll
        for (int u = 0; u < 4; u++) {
            pe[u] = __expf((d[u] + qb) * 0.125f);
            s += pe[u];
        }
        #pragma unroll
        for (int u = 0; u < 4; u++) {
            av0.x += pe[u] * v0[u].x;  av0.y += pe[u] * v0[u].y;
            av0.z += pe[u] * v0[u].z;  av0.w += pe[u] * v0[u].w;
            av1.x += pe[u] * v1[u].x;  av1.y += pe[u] * v1[u].y;
            av1.z += pe[u] * v1[u].z;  av1.w += pe[u] * v1[u].w;
            at0.x += pe[u] * e0[u].x;  at0.y += pe[u] * e0[u].y;
            at0.z += pe[u] * e0[u].z;  at0.w += pe[u] * e0[u].w;
            at1.x += pe[u] * e1[u].x;  at1.y += pe[u] * e1[u].y;
            at1.z += pe[u] * e1[u].z;  at1.w += pe[u] * e1[u].w;
        }
    }
    for (; p < end; p++) {
        int src = g_src[p];
        float4 k0, k1, e0, e1, v0, v1;
        ldh8(&g_kh[src * HC + chan], k0, k1);
        ldh8(&g_eh[p * 64 + c8],     e0, e1);
        ldh8(&g_vh[src * HC + chan], v0, v1);
        float d = dot4(q0, k0) + dot4(q1, k1) + dot4(gg0, e0) + dot4(gg1, e1);
        d += __shfl_xor_sync(0xffffffffu, d, 1);
        d += __shfl_xor_sync(0xffffffffu, d, 2);
        d += __shfl_xor_sync(0xffffffffu, d, 4);
        float pe = __expf((d + qb) * 0.125f);
        s += pe;
        av0.x += pe * v0.x; av0.y += pe * v0.y; av0.z += pe * v0.z; av0.w += pe * v0.w;
        av1.x += pe * v1.x; av1.y += pe * v1.y; av1.z += pe * v1.z; av1.w += pe * v1.w;
        at0.x += pe * e0.x; at0.y += pe * e0.y; at0.z += pe * e0.z; at0.w += pe * e0.w;
        at1.x += pe * e1.x; at1.y += pe * e1.y; at1.z += pe * e1.z; at1.w += pe * e1.w;
    }

    float sinv = 1.f / (s + 1e-16f);
    float4 o0 = {av0.x * sinv, av0.y * sinv, av0.z * sinv, av0.w * sinv};
    float4 o1 = {av1.x * sinv, av1.y * sinv, av1.z * sinv, av1.w * sinv};
    float4 t0 = {at0.x * sinv, at0.y * sinv, at0.z * sinv, at0.w * sinv};
    float4 t1 = {at1.x * sinv, at1.y * sinv, at1.z * sinv, at1.w * sinv};
    *(float4*)&g_outv[node * HC + chan]     = o0;
    *(float4*)&g_outv[node * HC + chan + 4] = o1;
    *(float4*)&g_t   [node * HC + chan]     = t0;
    *(float4*)&g_t   [node * HC + chan + 4] = t1;
    if ((lane & 7) == 0) g_suma[node * 4 + h] = s * sinv;
}

// ---------------- fused epilogue (16 nodes/block) --------------------------
__global__ void k_posthead(const float* __restrict__ wedge, const float* __restrict__ bedge,
                           const float* __restrict__ ln_g, const float* __restrict__ ln_b,
                           const float* __restrict__ w1, const float* __restrict__ b1,
                           const float* __restrict__ w2, const float* __restrict__ b2,
                           float* __restrict__ out, int n) {
    __shared__ float ts[16 * HC];
    __shared__ float os[16 * HC];
    __shared__ float hs[16 * 128];
    __shared__ float ls[16][NCLS];
    int tid = threadIdx.x;
    int nb = blockIdx.x * 16;
    for (int i = tid; i < 16 * HC; i += 256) {
        int nn = nb + (i >> 8);
        ts[i] = (nn < n) ? g_t[nn * HC + (i & 255)] : 0.f;
    }
    __syncthreads();

    int h = tid >> 6;
    float acc[16];
    #pragma unroll
    for (int m = 0; m < 16; m++) acc[m] = 0.f;
    for (int i = 0; i < 64; i++) {
        float w = __ldg(&wedge[i * HC + tid]);
        #pragma unroll
        for (int m = 0; m < 16; m++) acc[m] += ts[m * HC + h * 64 + i] * w;
    }
    float be = __ldg(&bedge[tid]);
    #pragma unroll
    for (int m = 0; m < 16; m++) {
        int nn = nb + m;
        if (nn < n) {
            os[m * HC + tid] = g_outv[nn * HC + tid] + g_suma[nn * 4 + h] * be
                             + g_skip[nn * HC + tid] + acc[m];
        }
    }
    __syncthreads();

    int wid = tid >> 5, lane = tid & 31;
    for (int m = wid; m < 16; m += 8) {
        int nn = nb + m;
        if (nn >= n) continue;
        float sum = 0.f, sq = 0.f;
        #pragma unroll
        for (int u = 0; u < 8; u++) {
            float v = os[m * HC + u * 32 + lane];
            sum += v; sq += v * v;
        }
        #pragma unroll
        for (int off = 16; off; off >>= 1) {
            sum += __shfl_xor_sync(0xffffffffu, sum, off);
            sq  += __shfl_xor_sync(0xffffffffu, sq,  off);
        }
        float mu = sum * (1.f / 256.f);
        float var = sq * (1.f / 256.f) - mu * mu;
        float rs = rsqrtf(var + 1e-5f);
        #pragma unroll
        for (int u = 0; u < 8; u++) {
            int j = u * 32 + lane;
            float v = (os[m * HC + j] - mu) * rs * __ldg(&ln_g[j]) + __ldg(&ln_b[j]);
            ts[m * HC + j] = fmaxf(v, 0.f);
        }
    }
    __syncthreads();

    {
        int col = tid & 127, rg = tid >> 7;
        float a8[8];
        float bb = __ldg(&b1[col]);
        #pragma unroll
        for (int r = 0; r < 8; r++) a8[r] = bb;
        for (int i = 0; i < HC; i++) {
            float w = __ldg(&w1[i * 128 + col]);
            #pragma unroll
            for (int r = 0; r < 8; r++) a8[r] += ts[(rg * 8 + r) * HC + i] * w;
        }
        #pragma unroll
        for (int r = 0; r < 8; r++) hs[(rg * 8 + r) * 128 + col] = fmaxf(a8[r], 0.f);
    }
    __syncthreads();

    if (tid < 64) {
        int m = tid >> 2, c = tid & 3;
        float a = __ldg(&b2[c]);
        for (int i = 0; i < 128; i++) a += hs[m * 128 + i] * __ldg(&w2[i * NCLS + c]);
        ls[m][c] = a;
    }
    __syncthreads();
    if (tid < 16) {
        int nn = nb + tid;
        if (nn < n) {
            float l0 = ls[tid][0], l1 = ls[tid][1], l2 = ls[tid][2], l3 = ls[tid][3];
            float mx = fmaxf(fmaxf(l0, l1), fmaxf(l2, l3));
            float se = expf(l0 - mx) + expf(l1 - mx) + expf(l2 - mx) + expf(l3 - mx);
            float lse = mx + logf(se);
            out[nn * NCLS + 0] = l0 - lse;
            out[nn * NCLS + 1] = l1 - lse;
            out[nn * NCLS + 2] = l2 - lse;
            out[nn * NCLS + 3] = l3 - lse;
        }
    }
}

// ---------------- launcher ----------------
extern "C" void kernel_launch(void* const* d_in, const int* in_sizes, int n_in,
                              void* d_out, int out_size) {
    const float* x     = (const float*)d_in[0];
    const int*   ei    = (const int*)  d_in[1];
    const float* eattr = (const float*)d_in[2];
    const float* w00   = (const float*)d_in[3];
    const float* b00   = (const float*)d_in[4];
    const float* we1   = (const float*)d_in[5];
    const float* be1   = (const float*)d_in[6];
    const float* we2   = (const float*)d_in[7];
    const float* be2   = (const float*)d_in[8];
    const float* we3   = (const float*)d_in[9];
    const float* be3   = (const float*)d_in[10];
    const float* wq    = (const float*)d_in[11];
    const float* bq    = (const float*)d_in[12];
    const float* wk    = (const float*)d_in[13];
    const float* bk    = (const float*)d_in[14];
    const float* wv    = (const float*)d_in[15];
    const float* bv    = (const float*)d_in[16];
    const float* wedge = (const float*)d_in[17];
    const float* bedge = (const float*)d_in[18];
    const float* wskip = (const float*)d_in[19];
    const float* bskip = (const float*)d_in[20];
    const float* ln_g  = (const float*)d_in[21];
    const float* ln_b  = (const float*)d_in[22];
    const float* w1    = (const float*)d_in[23];
    const float* b1    = (const float*)d_in[24];
    const float* w2    = (const float*)d_in[25];
    const float* b2    = (const float*)d_in[26];
    float* out = (float*)d_out;

    int n = in_sizes[0] / NFEAT;
    int e = in_sizes[1] / 2;
    int nblk = (n + 255) / 256;

    static cudaStream_t sB = nullptr;
    static cudaEvent_t evF = nullptr, evJ = nullptr;
    static bool attrs_set = false;
    if (sB == nullptr) {
        cudaStreamCreateWithFlags(&sB, cudaStreamNonBlocking);
        cudaEventCreateWithFlags(&evF, cudaEventDisableTiming);
        cudaEventCreateWithFlags(&evJ, cudaEventDisableTiming);
    }
    static const int EDGE_SMEM = 111360;
    if (!attrs_set) {
        cudaFuncSetAttribute(k_edgemlp, cudaFuncAttributeMaxDynamicSharedMemorySize, EDGE_SMEM);
        attrs_set = true;
    }

    // fork
    cudaEventRecord(evF, 0);
    cudaStreamWaitEvent(sB, evF, 0);

    // ---- stream B: node pipeline ----
    k_foldw<<<65, 256, 0, sB>>>(wq, bq, wedge);
    k_foldqb<<<1, 256, 0, sB>>>(wq, bq, bedge);
    {
        dim3 gridc((80 * 264 + 255) / 256, 5);
        k_cvtw<<<gridc, 256, 0, sB>>>(wq, bq, wk, bk, wv, bv, wskip, bskip);
    }
    k_node_embed<<<(n + 63) / 64, 256, 0, sB>>>(x, w00, b00, n);
    {
        dim3 grid((n + 63) / 64, 5);
        k_proj<<<grid, 256, 0, sB>>>(n);
    }
    k_qb<<<(n + 63) / 64, 256, 0, sB>>>(n);
    cudaEventRecord(evJ, sB);

    // ---- capture stream: CSR build + edge MLP ----
    k_cvte<<<(12672 + 255) / 256, 256>>>(we1, be1, we2, be2, we3, be3);
    k_zero_deg<<<(n + 255) / 256, 256>>>(n);
    k_hist<<<(e + 255) / 256, 256>>>(ei, e);
    k_blocksum<<<nblk, 256>>>(n);
    k_scanpart<<<1, 256>>>(nblk);
    k_scanfinal<<<nblk, 256>>>(n);
    k_scatter<<<(e + 255) / 256, 256>>>(ei, e);
    k_edgemlp<<<(e + 127) / 128, 256, EDGE_SMEM>>>(eattr, e);

    // join
    cudaStreamWaitEvent(0, evJ, 0);

    k_attn<<<(n + 7) / 8, 256>>>(n);
    k_posthead<<<(n + 15) / 16, 256>>>(wedge, bedge, ln_g, ln_b, w1, b1, w2, b2, out, n);
}

// round 16
// speedup vs baseline: 1.3658x; 1.0033x over previous
#include <cuda_runtime.h>
#include <cuda_fp16.h>
#include <mma.h>
#include <math.h>
#include <stdint.h>

using namespace nvcuda;

#define NFEAT 16
#define EFEAT 8
#define HC    256
#define NCLS  4

static const int MAXN = 50000;
static const int NPAD = 50048;
static const int MAXE = 800000;

typedef wmma::fragment<wmma::matrix_a, 16, 16, 16, __half, wmma::row_major> HFragA;
typedef wmma::fragment<wmma::matrix_b, 16, 16, 16, __half, wmma::row_major> HFragB;
typedef wmma::fragment<wmma::accumulator, 16, 16, 16, float> HFragC;

// ---------------- scratch ----------------
__device__ float  g_x1   [MAXN * 64];
__device__ __half g_qh   [NPAD * HC];
__device__ __half g_kh   [NPAD * HC];
__device__ __half g_vh   [NPAD * HC];
__device__ __half g_skiph[NPAD * HC];
__device__ __half g_gh   [NPAD * HC];
__device__ float  g_qb   [MAXN * 4];
__device__ __half g_eh   [MAXE * 64];
__device__ __half g_outvh[MAXN * HC];
__device__ __half g_th   [MAXN * HC];
__device__ float  g_suma [MAXN * 4];
__device__ float  g_wg   [64 * HC];
__device__ float  g_bg   [HC];
__device__ float  g_wqb  [64 * 4];
__device__ float  g_cb   [4];
__device__ __half g_pw   [5 * 80 * 264];
__device__ __half g_ew1  [16 * 72];
__device__ __half g_ew2  [80 * 72];
__device__ __half g_ew3  [80 * 72];
__device__ int    g_deg  [MAXN];
__device__ int    g_rowptr[MAXN + 1];
__device__ int    g_cursor[MAXN];
__device__ int    g_eid  [MAXE];
__device__ int    g_src  [MAXE];
__device__ int    g_part [256];
__device__ int    g_partoff[256];

// ---------------- CSR build ----------------
__global__ void k_zero_deg(int n) {
    int i = blockIdx.x * blockDim.x + threadIdx.x;
    if (i < n) g_deg[i] = 0;
}
__global__ void k_hist(const int* __restrict__ ei, int e) {
    int i = blockIdx.x * blockDim.x + threadIdx.x;
    if (i < e) atomicAdd(&g_deg[ei[e + i]], 1);
}
__global__ void k_blocksum(int n) {
    __shared__ int sh[256];
    int tid = threadIdx.x;
    int i = blockIdx.x * 256 + tid;
    sh[tid] = (i < n) ? g_deg[i] : 0;
    __syncthreads();
    for (int off = 128; off; off >>= 1) {
        if (tid < off) sh[tid] += sh[tid + off];
        __syncthreads();
    }
    if (tid == 0) g_part[blockIdx.x] = sh[0];
}
__global__ void k_scanpart(int nb) {
    __shared__ int sh[256];
    int tid = threadIdx.x;
    int v = (tid < nb) ? g_part[tid] : 0;
    sh[tid] = v;
    __syncthreads();
    for (int off = 1; off < 256; off <<= 1) {
        int y = (tid >= off) ? sh[tid - off] : 0;
        __syncthreads();
        sh[tid] += y;
        __syncthreads();
    }
    g_partoff[tid] = sh[tid] - v;
}
__global__ void k_scanfinal(int n) {
    __shared__ int sh[256];
    int tid = threadIdx.x;
    int i = blockIdx.x * 256 + tid;
    int v = (i < n) ? g_deg[i] : 0;
    sh[tid] = v;
    __syncthreads();
    for (int off = 1; off < 256; off <<= 1) {
        int y = (tid >= off) ? sh[tid - off] : 0;
        __syncthreads();
        sh[tid] += y;
        __syncthreads();
    }
    int base = g_partoff[blockIdx.x];
    if (i < n) {
        int incl = base + sh[tid];
        g_rowptr[i + 1] = incl;
        g_cursor[i]     = incl - v;
    }
    if (i == 0) g_rowptr[0] = 0;
}
__global__ void k_scatter(const int* __restrict__ ei, int e) {
    int i = blockIdx.x * blockDim.x + threadIdx.x;
    if (i < e) {
        int dst = ei[e + i];
        int pos = atomicAdd(&g_cursor[dst], 1);
        g_eid[pos] = i;
        g_src[pos] = ei[i];
    }
}

// ---------------- weight folding ----------------
__global__ void k_foldw(const float* __restrict__ wq, const float* __restrict__ bq,
                        const float* __restrict__ wedge) {
    int f = blockIdx.x;
    int j = threadIdx.x;
    int h = j >> 6, ii = j & 63;
    const float* src = (f < 64) ? &wq[f * HC] : bq;
    float s = 0.f;
    for (int c = 0; c < 64; c++)
        s += src[h * 64 + c] * __ldg(&wedge[ii * HC + h * 64 + c]);
    if (f < 64) g_wg[f * HC + j] = s;
    else        g_bg[j] = s;
}
__global__ void k_foldqb(const float* __restrict__ wq, const float* __restrict__ bq,
                         const float* __restrict__ bedge) {
    int j = threadIdx.x;
    int f = j >> 2, h = j & 3;
    float s = 0.f;
    for (int c = 0; c < 64; c++)
        s += wq[f * HC + h * 64 + c] * __ldg(&bedge[h * 64 + c]);
    g_wqb[f * 4 + h] = s;
    if (j < 4) {
        float cb = 0.f;
        for (int c = 0; c < 64; c++) cb += bq[j * 64 + c] * bedge[j * 64 + c];
        g_cb[j] = cb;
    }
}

// ---------------- one-time fp16 weight panel conversion --------------------
__global__ void k_cvtw(const float* __restrict__ W0, const float* __restrict__ B0,
                       const float* __restrict__ W1, const float* __restrict__ B1,
                       const float* __restrict__ W2, const float* __restrict__ B2,
                       const float* __restrict__ W3, const float* __restrict__ B3) {
    int sel = blockIdx.y;
    const float* W = (sel == 0) ? W0 : (sel == 1) ? W1 : (sel == 2) ? W2 :
                     (sel == 3) ? W3 : g_wg;
    const float* B = (sel == 0) ? B0 : (sel == 1) ? B1 : (sel == 2) ? B2 :
                     (sel == 3) ? B3 : g_bg;
    int idx = blockIdx.x * 256 + threadIdx.x;
    if (idx >= 80 * 264) return;
    int r = idx / 264, c = idx - r * 264;
    float v = 0.f;
    if (c < 256) {
        if (r < 64) v = __ldg(&W[r * 256 + c]);
        else if (r == 64) v = __ldg(&B[c]);
    }
    g_pw[sel * (80 * 264) + idx] = __float2half(v);
}
__global__ void k_cvte(const float* __restrict__ we1, const float* __restrict__ be1,
                       const float* __restrict__ we2, const float* __restrict__ be2,
                       const float* __restrict__ we3, const float* __restrict__ be3) {
    int idx = blockIdx.x * 256 + threadIdx.x;
    if (idx < 1152) {
        int r = idx / 72, c = idx - r * 72;
        float v = 0.f;
        if (c < 64) v = (r < 8) ? __ldg(&we1[r * 64 + c]) : ((r == 8) ? __ldg(&be1[c]) : 0.f);
        g_ew1[idx] = __float2half(v);
    } else if (idx < 1152 + 5760) {
        int k = idx - 1152;
        int r = k / 72, c = k - r * 72;
        float v = 0.f;
        if (c < 64) {
            if (r < 64) v = __ldg(&we2[r * 64 + c]);
            else if (r == 64) v = __ldg(&be2[c]);
        }
        g_ew2[k] = __float2half(v);
    } else if (idx < 1152 + 11520) {
        int k = idx - 1152 - 5760;
        int r = k / 72, c = k - r * 72;
        float v = 0.f;
        if (c < 64) {
            if (r < 64) v = __ldg(&we3[r * 64 + c]);
            else if (r == 64) v = __ldg(&be3[c]);
        }
        g_ew3[k] = __float2half(v);
    }
}

// ---------------- node embed ----------------
__global__ void k_node_embed(const float* __restrict__ x,
                             const float* __restrict__ w00,
                             const float* __restrict__ b00, int n) {
    __shared__ float ws[NFEAT * 64];
    __shared__ float xs[64][NFEAT];
    int tid = threadIdx.x;
    for (int i = tid; i < NFEAT * 64; i += 256) ws[i] = w00[i];
    int nb = blockIdx.x * 64;
    for (int i = tid; i < 64 * NFEAT; i += 256) {
        int nn = nb + i / NFEAT;
        xs[i / NFEAT][i % NFEAT] = (nn < n) ? x[nn * NFEAT + (i % NFEAT)] : 0.f;
    }
    __syncthreads();
    int ln = tid >> 2;
    int node = nb + ln;
    int c0 = (tid & 3) * 16;
    if (node < n) {
        #pragma unroll
        for (int j = 0; j < 16; j++) {
            float acc = __ldg(&b00[c0 + j]);
            #pragma unroll
            for (int i = 0; i < NFEAT; i++) acc += xs[ln][i] * ws[i * 64 + c0 + j];
            g_x1[node * 64 + c0 + j] = fmaxf(acc, 0.f);
        }
    }
}

// ---------------- qb = x1 @ wqb + cb ----------------
__global__ void k_qb(int n) {
    __shared__ float ws[64 * 4];
    int tid = threadIdx.x;
    ws[tid] = g_wqb[tid];
    __syncthreads();
    int idx = blockIdx.x * 64 + (tid >> 2);
    int h = tid & 3;
    if (idx < n) {
        float s = g_cb[h];
        const float* xr = &g_x1[idx * 64];
        #pragma unroll 16
        for (int f = 0; f < 64; f++) s += xr[f] * ws[f * 4 + h];
        g_qb[idx * 4 + h] = s;
    }
}

// ---------------- projections: fp16 wmma; all outputs fp16 -----------------
__global__ void k_proj(int n) {
    int sel = blockIdx.y;
    __half* outh = (sel == 0) ? g_qh : (sel == 1) ? g_kh : (sel == 2) ? g_vh :
                   (sel == 3) ? g_skiph : g_gh;
    const __half* gw = &g_pw[sel * (80 * 264)];

    __shared__ __half xsh[64 * 88];
    __shared__ float fbp[8][256];

    int tid = threadIdx.x;
    int nb = blockIdx.x * 64;

    for (int i = tid; i < 64 * 88; i += 256) {
        int r = i / 88, c = i - r * 88;
        float v = 0.f;
        if (c < 64) {
            int node = nb + r;
            if (node < n) v = __ldg(&g_x1[node * 64 + c]);
        } else if (c == 64) v = 1.0f;
        xsh[i] = __float2half(v);
    }
    __syncthreads();

    int w = tid >> 5, lane = tid & 31;
    int rt = w >> 1;
    int ch = w & 1;

    HFragA a[5];
    #pragma unroll
    for (int k = 0; k < 5; k++)
        wmma::load_matrix_sync(a[k], &xsh[rt * 16 * 88 + k * 16], 88);

    #pragma unroll
    for (int nf = 0; nf < 8; nf++) {
        int c0 = ch * 128 + nf * 16;
        HFragC acc;
        wmma::fill_fragment(acc, 0.f);
        #pragma unroll
        for (int k = 0; k < 5; k++) {
            HFragB b;
            wmma::load_matrix_sync(b, gw + k * 16 * 264 + c0, 264);
            wmma::mma_sync(acc, a[k], b, acc);
        }
        wmma::store_matrix_sync(&fbp[w][0], acc, 16, wmma::mem_row_major);
        __syncwarp();
        int r = lane >> 1, cf = (lane & 1) * 8;
        const float* src = &fbp[w][r * 16 + cf];
        __half hb[8];
        #pragma unroll
        for (int j = 0; j < 8; j++) hb[j] = __float2half(src[j]);
        *(uint4*)&outh[(nb + rt * 16 + r) * HC + c0 + cf] = *(uint4*)hb;
        __syncwarp();
    }
}

// ---------------- edge MLP: fp16 wmma, 128 edges/block ---------------------
__global__ void k_edgemlp(const float* __restrict__ eattr, int e) {
    extern __shared__ __half smh[];
    __half* es  = smh;
    __half* w1b = smh + 2048;
    __half* w2b = smh + 3200;
    __half* w3b = smh + 8960;
    __half* h1h = smh + 14720;
    __half* h2h = smh + 25984;
    float*  fb  = (float*)(smh + 37248);

    int tid = threadIdx.x;
    int pb = blockIdx.x * 128;

    for (int i = tid; i < 576; i += 256)
        ((unsigned int*)w1b)[i] = ((const unsigned int*)g_ew1)[i];
    for (int i = tid; i < 2880; i += 256) {
        ((unsigned int*)w2b)[i] = ((const unsigned int*)g_ew2)[i];
        ((unsigned int*)w3b)[i] = ((const unsigned int*)g_ew3)[i];
    }
    for (int i = tid; i < 2048; i += 256) {
        int r = i >> 4, c = i & 15;
        float v = 0.f;
        if (c < 8) {
            int p = pb + r;
            if (p < e) v = __ldg(&eattr[g_eid[p] * 8 + c]);
        } else if (c == 8) v = 1.0f;
        es[i] = __float2half(v);
    }
    for (int i = tid; i < 3072; i += 256) {
        int r = i / 24, c = 64 + (i - r * 24);
        __half v = __float2half((c == 64) ? 1.0f : 0.f);
        h1h[r * 88 + c] = v;
        h2h[r * 88 + c] = v;
    }
    __syncthreads();

    int w = tid >> 5;

    {
        HFragA a;
        wmma::load_matrix_sync(a, &es[w * 16 * 16], 16);
        #pragma unroll
        for (int nf = 0; nf < 4; nf++) {
            HFragC acc;
            wmma::fill_fragment(acc, 0.f);
            HFragB b;
            wmma::load_matrix_sync(b, &w1b[nf * 16], 72);
            wmma::mma_sync(acc, a, b, acc);
            wmma::store_matrix_sync(&fb[w * 16 * 72 + nf * 16], acc, 72, wmma::mem_row_major);
        }
    }
    __syncthreads();
    for (int i = tid; i < 8192; i += 256) {
        int r = i >> 6, c = i & 63;
        h1h[r * 88 + c] = __float2half(fmaxf(fb[r * 72 + c], 0.f));
    }
    __syncthreads();

    {
        HFragA a[5];
        #pragma unroll
        for (int k = 0; k < 5; k++)
            wmma::load_matrix_sync(a[k], &h1h[w * 16 * 88 + k * 16], 88);
        #pragma unroll
        for (int nf = 0; nf < 4; nf++) {
            HFragC acc;
            wmma::fill_fragment(acc, 0.f);
            #pragma unroll
            for (int k = 0; k < 5; k++) {
                HFragB b;
                wmma::load_matrix_sync(b, &w2b[k * 16 * 72 + nf * 16], 72);
                wmma::mma_sync(acc, a[k], b, acc);
            }
            wmma::store_matrix_sync(&fb[w * 16 * 72 + nf * 16], acc, 72, wmma::mem_row_major);
        }
    }
    __syncthreads();
    for (int i = tid; i < 8192; i += 256) {
        int r = i >> 6, c = i & 63;
        h2h[r * 88 + c] = __float2half(fmaxf(fb[r * 72 + c], 0.f));
    }
    __syncthreads();

    {
        HFragA a[5];
        #pragma unroll
        for (int k = 0; k < 5; k++)
            wmma::load_matrix_sync(a[k], &h2h[w * 16 * 88 + k * 16], 88);
        #pragma unroll
        for (int nf = 0; nf < 4; nf++) {
            HFragC acc;
            wmma::fill_fragment(acc, 0.f);
            #pragma unroll
            for (int k = 0; k < 5; k++) {
                HFragB b;
                wmma::load_matrix_sync(b, &w3b[k * 16 * 72 + nf * 16], 72);
                wmma::mma_sync(acc, a[k], b, acc);
            }
            wmma::store_matrix_sync(&fb[w * 16 * 72 + nf * 16], acc, 72, wmma::mem_row_major);
        }
    }
    __syncthreads();
    {
        int nrows = min(128, e - pb);
        for (int i = tid * 2; i < nrows * 64; i += 512) {
            int r = i >> 6, c = i & 63;
            __half2 hv = __floats2half2_rn(fmaxf(fb[r * 72 + c], 0.f),
                                           fmaxf(fb[r * 72 + c + 1], 0.f));
            *(__half2*)&g_eh[(pb + r) * 64 + c] = hv;
        }
    }
}

// ---------------- attention ----------------
__device__ __forceinline__ float dot4(float4 a, float4 b) {
    return a.x * b.x + a.y * b.y + a.z * b.z + a.w * b.w;
}
__device__ __forceinline__ void ldh8(const __half* p, float4& a, float4& b) {
    uint4 u = *(const uint4*)p;
    float2 f0 = __half22float2(*(__half2*)&u.x);
    float2 f1 = __half22float2(*(__half2*)&u.y);
    float2 f2 = __half22float2(*(__half2*)&u.z);
    float2 f3 = __half22float2(*(__half2*)&u.w);
    a = make_float4(f0.x, f0.y, f1.x, f1.y);
    b = make_float4(f2.x, f2.y, f3.x, f3.y);
}
__device__ __forceinline__ void sth8(__half* p, float4 a, float4 b) {
    __half hb[8];
    hb[0] = __float2half(a.x); hb[1] = __float2half(a.y);
    hb[2] = __float2half(a.z); hb[3] = __float2half(a.w);
    hb[4] = __float2half(b.x); hb[5] = __float2half(b.y);
    hb[6] = __float2half(b.z); hb[7] = __float2half(b.w);
    *(uint4*)p = *(uint4*)hb;
}

__global__ void __launch_bounds__(256) k_attn(int n) {
    int gw = (blockIdx.x * blockDim.x + threadIdx.x) >> 5;
    int lane = threadIdx.x & 31;
    if (gw >= n) return;
    int node = gw;
    int beg = g_rowptr[node], end = g_rowptr[node + 1];

    int h = lane >> 3;
    int c8 = (lane & 7) * 8;
    int chan = h * 64 + c8;

    float4 q0, q1, gg0, gg1;
    ldh8(&g_qh[node * HC + chan], q0, q1);
    ldh8(&g_gh[node * HC + chan], gg0, gg1);
    float qb = g_qb[node * 4 + h];

    float s = 0.f;
    float4 av0 = {0,0,0,0}, av1 = {0,0,0,0};
    float4 at0 = {0,0,0,0}, at1 = {0,0,0,0};

    int p = beg;
    for (; p + 4 <= end; p += 4) {
        int src[4];
        #pragma unroll
        for (int u = 0; u < 4; u++) src[u] = g_src[p + u];

        float d[4];
        float4 e0[4], e1[4], v0[4], v1[4];
        #pragma unroll
        for (int u = 0; u < 4; u++) {
            float4 k0, k1;
            ldh8(&g_kh[src[u] * HC + chan], k0, k1);
            ldh8(&g_eh[(p + u) * 64 + c8], e0[u], e1[u]);
            ldh8(&g_vh[src[u] * HC + chan], v0[u], v1[u]);
            d[u] = dot4(q0, k0) + dot4(q1, k1) + dot4(gg0, e0[u]) + dot4(gg1, e1[u]);
        }
        #pragma unroll
        for (int off = 1; off < 8; off <<= 1) {
            #pragma unroll
            for (int u = 0; u < 4; u++)
                d[u] += __shfl_xor_sync(0xffffffffu, d[u], off);
        }
        float pe[4];
        #pragma unroll
        for (int u = 0; u < 4; u++) {
            pe[u] = __expf((d[u] + qb) * 0.125f);
            s += pe[u];
        }
        #pragma unroll
        for (int u = 0; u < 4; u++) {
            av0.x += pe[u] * v0[u].x;  av0.y += pe[u] * v0[u].y;
            av0.z += pe[u] * v0[u].z;  av0.w += pe[u] * v0[u].w;
            av1.x += pe[u] * v1[u].x;  av1.y += pe[u] * v1[u].y;
            av1.z += pe[u] * v1[u].z;  av1.w += pe[u] * v1[u].w;
            at0.x += pe[u] * e0[u].x;  at0.y += pe[u] * e0[u].y;
            at0.z += pe[u] * e0[u].z;  at0.w += pe[u] * e0[u].w;
            at1.x += pe[u] * e1[u].x;  at1.y += pe[u] * e1[u].y;
            at1.z += pe[u] * e1[u].z;  at1.w += pe[u] * e1[u].w;
        }
    }
    for (; p < end; p++) {
        int src = g_src[p];
        float4 k0, k1, e0, e1, v0, v1;
        ldh8(&g_kh[src * HC + chan], k0, k1);
        ldh8(&g_eh[p * 64 + c8],     e0, e1);
        ldh8(&g_vh[src * HC + chan], v0, v1);
        float d = dot4(q0, k0) + dot4(q1, k1) + dot4(gg0, e0) + dot4(gg1, e1);
        d += __shfl_xor_sync(0xffffffffu, d, 1);
        d += __shfl_xor_sync(0xffffffffu, d, 2);
        d += __shfl_xor_sync(0xffffffffu, d, 4);
        float pe = __expf((d + qb) * 0.125f);
        s += pe;
        av0.x += pe * v0.x; av0.y += pe * v0.y; av0.z += pe * v0.z; av0.w += pe * v0.w;
        av1.x += pe * v1.x; av1.y += pe * v1.y; av1.z += pe * v1.z; av1.w += pe * v1.w;
        at0.x += pe * e0.x; at0.y += pe * e0.y; at0.z += pe * e0.z; at0.w += pe * e0.w;
        at1.x += pe * e1.x; at1.y += pe * e1.y; at1.z += pe * e1.z; at1.w += pe * e1.w;
    }

    float sinv = 1.f / (s + 1e-16f);
    float4 o0 = {av0.x * sinv, av0.y * sinv, av0.z * sinv, av0.w * sinv};
    float4 o1 = {av1.x * sinv, av1.y * sinv, av1.z * sinv, av1.w * sinv};
    float4 t0 = {at0.x * sinv, at0.y * sinv, at0.z * sinv, at0.w * sinv};
    float4 t1 = {at1.x * sinv, at1.y * sinv, at1.z * sinv, at1.w * sinv};
    sth8(&g_outvh[node * HC + chan], o0, o1);
    sth8(&g_th   [node * HC + chan], t0, t1);
    if ((lane & 7) == 0) g_suma[node * 4 + h] = s * sinv;
}

// ---------------- fused epilogue (16 nodes/block) --------------------------
__global__ void k_posthead(const float* __restrict__ wedge, const float* __restrict__ bedge,
                           const float* __restrict__ ln_g, const float* __restrict__ ln_b,
                           const float* __restrict__ w1, const float* __restrict__ b1,
                           const float* __restrict__ w2, const float* __restrict__ b2,
                           float* __restrict__ out, int n) {
    __shared__ float ts[16 * HC];
    __shared__ float os[16 * HC];
    __shared__ float hs[16 * 128];
    __shared__ float ls[16][NCLS];
    int tid = threadIdx.x;
    int nb = blockIdx.x * 16;
    for (int i = tid; i < 16 * HC; i += 256) {
        int nn = nb + (i >> 8);
        ts[i] = (nn < n) ? __half2float(g_th[nn * HC + (i & 255)]) : 0.f;
    }
    __syncthreads();

    int h = tid >> 6;
    float acc[16];
    #pragma unroll
    for (int m = 0; m < 16; m++) acc[m] = 0.f;
    for (int i = 0; i < 64; i++) {
        float w = __ldg(&wedge[i * HC + tid]);
        #pragma unroll
        for (int m = 0; m < 16; m++) acc[m] += ts[m * HC + h * 64 + i] * w;
    }
    float be = __ldg(&bedge[tid]);
    #pragma unroll
    for (int m = 0; m < 16; m++) {
        int nn = nb + m;
        if (nn < n) {
            os[m * HC + tid] = __half2float(g_outvh[nn * HC + tid])
                             + g_suma[nn * 4 + h] * be
                             + __half2float(g_skiph[nn * HC + tid]) + acc[m];
        }
    }
    __syncthreads();

    int wid = tid >> 5, lane = tid & 31;
    for (int m = wid; m < 16; m += 8) {
        int nn = nb + m;
        if (nn >= n) continue;
        float sum = 0.f, sq = 0.f;
        #pragma unroll
        for (int u = 0; u < 8; u++) {
            float v = os[m * HC + u * 32 + lane];
            sum += v; sq += v * v;
        }
        #pragma unroll
        for (int off = 16; off; off >>= 1) {
            sum += __shfl_xor_sync(0xffffffffu, sum, off);
            sq  += __shfl_xor_sync(0xffffffffu, sq,  off);
        }
        float mu = sum * (1.f / 256.f);
        float var = sq * (1.f / 256.f) - mu * mu;
        float rs = rsqrtf(var + 1e-5f);
        #pragma unroll
        for (int u = 0; u < 8; u++) {
            int j = u * 32 + lane;
            float v = (os[m * HC + j] - mu) * rs * __ldg(&ln_g[j]) + __ldg(&ln_b[j]);
            ts[m * HC + j] = fmaxf(v, 0.f);
        }
    }
    __syncthreads();

    {
        int col = tid & 127, rg = tid >> 7;
        float a8[8];
        float bb = __ldg(&b1[col]);
        #pragma unroll
        for (int r = 0; r < 8; r++) a8[r] = bb;
        for (int i = 0; i < HC; i++) {
            float w = __ldg(&w1[i * 128 + col]);
            #pragma unroll
            for (int r = 0; r < 8; r++) a8[r] += ts[(rg * 8 + r) * HC + i] * w;
        }
        #pragma unroll
        for (int r = 0; r < 8; r++) hs[(rg * 8 + r) * 128 + col] = fmaxf(a8[r], 0.f);
    }
    __syncthreads();

    if (tid < 64) {
        int m = tid >> 2, c = tid & 3;
        float a = __ldg(&b2[c]);
        for (int i = 0; i < 128; i++) a += hs[m * 128 + i] * __ldg(&w2[i * NCLS + c]);
        ls[m][c] = a;
    }
    __syncthreads();
    if (tid < 16) {
        int nn = nb + tid;
        if (nn < n) {
            float l0 = ls[tid][0], l1 = ls[tid][1], l2 = ls[tid][2], l3 = ls[tid][3];
            float mx = fmaxf(fmaxf(l0, l1), fmaxf(l2, l3));
            float se = expf(l0 - mx) + expf(l1 - mx) + expf(l2 - mx) + expf(l3 - mx);
            float lse = mx + logf(se);
            out[nn * NCLS + 0] = l0 - lse;
            out[nn * NCLS + 1] = l1 - lse;
            out[nn * NCLS + 2] = l2 - lse;
            out[nn * NCLS + 3] = l3 - lse;
        }
    }
}

// ---------------- launcher ----------------
extern "C" void kernel_launch(void* const* d_in, const int* in_sizes, int n_in,
                              void* d_out, int out_size) {
    const float* x     = (const float*)d_in[0];
    const int*   ei    = (const int*)  d_in[1];
    const float* eattr = (const float*)d_in[2];
    const float* w00   = (const float*)d_in[3];
    const float* b00   = (const float*)d_in[4];
    const float* we1   = (const float*)d_in[5];
    const float* be1   = (const float*)d_in[6];
    const float* we2   = (const float*)d_in[7];
    const float* be2   = (const float*)d_in[8];
    const float* we3   = (const float*)d_in[9];
    const float* be3   = (const float*)d_in[10];
    const float* wq    = (const float*)d_in[11];
    const float* bq    = (const float*)d_in[12];
    const float* wk    = (const float*)d_in[13];
    const float* bk    = (const float*)d_in[14];
    const float* wv    = (const float*)d_in[15];
    const float* bv    = (const float*)d_in[16];
    const float* wedge = (const float*)d_in[17];
    const float* bedge = (const float*)d_in[18];
    const float* wskip = (const float*)d_in[19];
    const float* bskip = (const float*)d_in[20];
    const float* ln_g  = (const float*)d_in[21];
    const float* ln_b  = (const float*)d_in[22];
    const float* w1    = (const float*)d_in[23];
    const float* b1    = (const float*)d_in[24];
    const float* w2    = (const float*)d_in[25];
    const float* b2    = (const float*)d_in[26];
    float* out = (float*)d_out;

    int n = in_sizes[0] / NFEAT;
    int e = in_sizes[1] / 2;
    int nblk = (n + 255) / 256;

    static cudaStream_t sB = nullptr;
    static cudaEvent_t evF = nullptr, evJ = nullptr;
    static bool attrs_set = false;
    if (sB == nullptr) {
        cudaStreamCreateWithFlags(&sB, cudaStreamNonBlocking);
        cudaEventCreateWithFlags(&evF, cudaEventDisableTiming);
        cudaEventCreateWithFlags(&evJ, cudaEventDisableTiming);
    }
    static const int EDGE_SMEM = 111360;
    if (!attrs_set) {
        cudaFuncSetAttribute(k_edgemlp, cudaFuncAttributeMaxDynamicSharedMemorySize, EDGE_SMEM);
        attrs_set = true;
    }

    // fork
    cudaEventRecord(evF, 0);
    cudaStreamWaitEvent(sB, evF, 0);

    // ---- stream B: node pipeline ----
    k_foldw<<<65, 256, 0, sB>>>(wq, bq, wedge);
    k_foldqb<<<1, 256, 0, sB>>>(wq, bq, bedge);
    {
        dim3 gridc((80 * 264 + 255) / 256, 5);
        k_cvtw<<<gridc, 256, 0, sB>>>(wq, bq, wk, bk, wv, bv, wskip, bskip);
    }
    k_node_embed<<<(n + 63) / 64, 256, 0, sB>>>(x, w00, b00, n);
    {
        dim3 grid((n + 63) / 64, 5);
        k_proj<<<grid, 256, 0, sB>>>(n);
    }
    k_qb<<<(n + 63) / 64, 256, 0, sB>>>(n);
    cudaEventRecord(evJ, sB);

    // ---- capture stream: CSR build + edge MLP ----
    k_cvte<<<(12672 + 255) / 256, 256>>>(we1, be1, we2, be2, we3, be3);
    k_zero_deg<<<(n + 255) / 256, 256>>>(n);
    k_hist<<<(e + 255) / 256, 256>>>(ei, e);
    k_blocksum<<<nblk, 256>>>(n);
    k_scanpart<<<1, 256>>>(nblk);
    k_scanfinal<<<nblk, 256>>>(n);
    k_scatter<<<(e + 255) / 256, 256>>>(ei, e);
    k_edgemlp<<<(e + 127) / 128, 256, EDGE_SMEM>>>(eattr, e);

    // join
    cudaStreamWaitEvent(0, evJ, 0);

    k_attn<<<(n + 7) / 8, 256>>>(n);
    k_posthead<<<(n + 15) / 16, 256>>>(wedge, bedge, ln_g, ln_b, w1, b1, w2, b2, out, n);
}

// round 17
// speedup vs baseline: 1.4618x; 1.0703x over previous
#include <cuda_runtime.h>
#include <cuda_fp16.h>
#include <mma.h>
#include <math.h>
#include <stdint.h>

using namespace nvcuda;

#define NFEAT 16
#define EFEAT 8
#define HC    256
#define NCLS  4

static const int MAXN = 50000;
static const int NPAD = 50048;
static const int MAXE = 800000;

typedef wmma::fragment<wmma::matrix_a, 16, 16, 16, __half, wmma::row_major> HFragA;
typedef wmma::fragment<wmma::matrix_b, 16, 16, 16, __half, wmma::row_major> HFragB;
typedef wmma::fragment<wmma::accumulator, 16, 16, 16, float> HFragC;

// ---------------- scratch ----------------
__device__ float  g_x1   [MAXN * 64];
__device__ __half g_qh   [NPAD * HC];
__device__ __half g_kh   [NPAD * HC];
__device__ __half g_vh   [NPAD * HC];
__device__ __half g_skiph[NPAD * HC];
__device__ __half g_gh   [NPAD * HC];
__device__ float  g_qb   [MAXN * 4];
__device__ __half g_eh   [(MAXE + 128) * 64];   // padded for full-tile stores
__device__ __half g_outvh[MAXN * HC];
__device__ __half g_th   [MAXN * HC];
__device__ float  g_suma [MAXN * 4];
__device__ float  g_wg   [64 * HC];
__device__ float  g_bg   [HC];
__device__ float  g_wqb  [64 * 4];
__device__ float  g_cb   [4];
__device__ __half g_pw   [5 * 80 * 264];
__device__ __half g_ew1  [16 * 72];
__device__ __half g_ew2  [80 * 72];
__device__ __half g_ew3  [80 * 72];
__device__ int    g_deg  [MAXN];
__device__ int    g_rowptr[MAXN + 1];
__device__ int    g_cursor[MAXN];
__device__ int    g_eid  [MAXE];
__device__ int    g_src  [MAXE];
__device__ int    g_part [256];
__device__ int    g_partoff[256];

// ---------------- CSR build ----------------
__global__ void k_zero_deg(int n) {
    int i = blockIdx.x * blockDim.x + threadIdx.x;
    if (i < n) g_deg[i] = 0;
}
__global__ void k_hist(const int* __restrict__ ei, int e) {
    int i = blockIdx.x * blockDim.x + threadIdx.x;
    if (i < e) atomicAdd(&g_deg[ei[e + i]], 1);
}
__global__ void k_blocksum(int n) {
    __shared__ int sh[256];
    int tid = threadIdx.x;
    int i = blockIdx.x * 256 + tid;
    sh[tid] = (i < n) ? g_deg[i] : 0;
    __syncthreads();
    for (int off = 128; off; off >>= 1) {
        if (tid < off) sh[tid] += sh[tid + off];
        __syncthreads();
    }
    if (tid == 0) g_part[blockIdx.x] = sh[0];
}
__global__ void k_scanpart(int nb) {
    __shared__ int sh[256];
    int tid = threadIdx.x;
    int v = (tid < nb) ? g_part[tid] : 0;
    sh[tid] = v;
    __syncthreads();
    for (int off = 1; off < 256; off <<= 1) {
        int y = (tid >= off) ? sh[tid - off] : 0;
        __syncthreads();
        sh[tid] += y;
        __syncthreads();
    }
    g_partoff[tid] = sh[tid] - v;
}
__global__ void k_scanfinal(int n) {
    __shared__ int sh[256];
    int tid = threadIdx.x;
    int i = blockIdx.x * 256 + tid;
    int v = (i < n) ? g_deg[i] : 0;
    sh[tid] = v;
    __syncthreads();
    for (int off = 1; off < 256; off <<= 1) {
        int y = (tid >= off) ? sh[tid - off] : 0;
        __syncthreads();
        sh[tid] += y;
        __syncthreads();
    }
    int base = g_partoff[blockIdx.x];
    if (i < n) {
        int incl = base + sh[tid];
        g_rowptr[i + 1] = incl;
        g_cursor[i]     = incl - v;
    }
    if (i == 0) g_rowptr[0] = 0;
}
__global__ void k_scatter(const int* __restrict__ ei, int e) {
    int i = blockIdx.x * blockDim.x + threadIdx.x;
    if (i < e) {
        int dst = ei[e + i];
        int pos = atomicAdd(&g_cursor[dst], 1);
        g_eid[pos] = i;
        g_src[pos] = ei[i];
    }
}

// ---------------- weight folding ----------------
__global__ void k_foldw(const float* __restrict__ wq, const float* __restrict__ bq,
                        const float* __restrict__ wedge) {
    int f = blockIdx.x;
    int j = threadIdx.x;
    int h = j >> 6, ii = j & 63;
    const float* src = (f < 64) ? &wq[f * HC] : bq;
    float s = 0.f;
    for (int c = 0; c < 64; c++)
        s += src[h * 64 + c] * __ldg(&wedge[ii * HC + h * 64 + c]);
    if (f < 64) g_wg[f * HC + j] = s;
    else        g_bg[j] = s;
}
__global__ void k_foldqb(const float* __restrict__ wq, const float* __restrict__ bq,
                         const float* __restrict__ bedge) {
    int j = threadIdx.x;
    int f = j >> 2, h = j & 3;
    float s = 0.f;
    for (int c = 0; c < 64; c++)
        s += wq[f * HC + h * 64 + c] * __ldg(&bedge[h * 64 + c]);
    g_wqb[f * 4 + h] = s;
    if (j < 4) {
        float cb = 0.f;
        for (int c = 0; c < 64; c++) cb += bq[j * 64 + c] * bedge[j * 64 + c];
        g_cb[j] = cb;
    }
}

// ---------------- one-time fp16 weight panel conversion --------------------
__global__ void k_cvtw(const float* __restrict__ W0, const float* __restrict__ B0,
                       const float* __restrict__ W1, const float* __restrict__ B1,
                       const float* __restrict__ W2, const float* __restrict__ B2,
                       const float* __restrict__ W3, const float* __restrict__ B3) {
    int sel = blockIdx.y;
    const float* W = (sel == 0) ? W0 : (sel == 1) ? W1 : (sel == 2) ? W2 :
                     (sel == 3) ? W3 : g_wg;
    const float* B = (sel == 0) ? B0 : (sel == 1) ? B1 : (sel == 2) ? B2 :
                     (sel == 3) ? B3 : g_bg;
    int idx = blockIdx.x * 256 + threadIdx.x;
    if (idx >= 80 * 264) return;
    int r = idx / 264, c = idx - r * 264;
    float v = 0.f;
    if (c < 256) {
        if (r < 64) v = __ldg(&W[r * 256 + c]);
        else if (r == 64) v = __ldg(&B[c]);
    }
    g_pw[sel * (80 * 264) + idx] = __float2half(v);
}
__global__ void k_cvte(const float* __restrict__ we1, const float* __restrict__ be1,
                       const float* __restrict__ we2, const float* __restrict__ be2,
                       const float* __restrict__ we3, const float* __restrict__ be3) {
    int idx = blockIdx.x * 256 + threadIdx.x;
    if (idx < 1152) {
        int r = idx / 72, c = idx - r * 72;
        float v = 0.f;
        if (c < 64) v = (r < 8) ? __ldg(&we1[r * 64 + c]) : ((r == 8) ? __ldg(&be1[c]) : 0.f);
        g_ew1[idx] = __float2half(v);
    } else if (idx < 1152 + 5760) {
        int k = idx - 1152;
        int r = k / 72, c = k - r * 72;
        float v = 0.f;
        if (c < 64) {
            if (r < 64) v = __ldg(&we2[r * 64 + c]);
            else if (r == 64) v = __ldg(&be2[c]);
        }
        g_ew2[k] = __float2half(v);
    } else if (idx < 1152 + 11520) {
        int k = idx - 1152 - 5760;
        int r = k / 72, c = k - r * 72;
        float v = 0.f;
        if (c < 64) {
            if (r < 64) v = __ldg(&we3[r * 64 + c]);
            else if (r == 64) v = __ldg(&be3[c]);
        }
        g_ew3[k] = __float2half(v);
    }
}

// ---------------- node embed ----------------
__global__ void k_node_embed(const float* __restrict__ x,
                             const float* __restrict__ w00,
                             const float* __restrict__ b00, int n) {
    __shared__ float ws[NFEAT * 64];
    __shared__ float xs[64][NFEAT];
    int tid = threadIdx.x;
    for (int i = tid; i < NFEAT * 64; i += 256) ws[i] = w00[i];
    int nb = blockIdx.x * 64;
    for (int i = tid; i < 64 * NFEAT; i += 256) {
        int nn = nb + i / NFEAT;
        xs[i / NFEAT][i % NFEAT] = (nn < n) ? x[nn * NFEAT + (i % NFEAT)] : 0.f;
    }
    __syncthreads();
    int ln = tid >> 2;
    int node = nb + ln;
    int c0 = (tid & 3) * 16;
    if (node < n) {
        #pragma unroll
        for (int j = 0; j < 16; j++) {
            float acc = __ldg(&b00[c0 + j]);
            #pragma unroll
            for (int i = 0; i < NFEAT; i++) acc += xs[ln][i] * ws[i * 64 + c0 + j];
            g_x1[node * 64 + c0 + j] = fmaxf(acc, 0.f);
        }
    }
}

// ---------------- qb ----------------
__global__ void k_qb(int n) {
    __shared__ float ws[64 * 4];
    int tid = threadIdx.x;
    ws[tid] = g_wqb[tid];
    __syncthreads();
    int idx = blockIdx.x * 64 + (tid >> 2);
    int h = tid & 3;
    if (idx < n) {
        float s = g_cb[h];
        const float* xr = &g_x1[idx * 64];
        #pragma unroll 16
        for (int f = 0; f < 64; f++) s += xr[f] * ws[f * 4 + h];
        g_qb[idx * 4 + h] = s;
    }
}

// ---------------- projections ----------------
__global__ void k_proj(int n) {
    int sel = blockIdx.y;
    __half* outh = (sel == 0) ? g_qh : (sel == 1) ? g_kh : (sel == 2) ? g_vh :
                   (sel == 3) ? g_skiph : g_gh;
    const __half* gw = &g_pw[sel * (80 * 264)];

    __shared__ __half xsh[64 * 88];
    __shared__ float fbp[8][256];

    int tid = threadIdx.x;
    int nb = blockIdx.x * 64;

    for (int i = tid; i < 64 * 88; i += 256) {
        int r = i / 88, c = i - r * 88;
        float v = 0.f;
        if (c < 64) {
            int node = nb + r;
            if (node < n) v = __ldg(&g_x1[node * 64 + c]);
        } else if (c == 64) v = 1.0f;
        xsh[i] = __float2half(v);
    }
    __syncthreads();

    int w = tid >> 5, lane = tid & 31;
    int rt = w >> 1;
    int ch = w & 1;

    HFragA a[5];
    #pragma unroll
    for (int k = 0; k < 5; k++)
        wmma::load_matrix_sync(a[k], &xsh[rt * 16 * 88 + k * 16], 88);

    #pragma unroll
    for (int nf = 0; nf < 8; nf++) {
        int c0 = ch * 128 + nf * 16;
        HFragC acc;
        wmma::fill_fragment(acc, 0.f);
        #pragma unroll
        for (int k = 0; k < 5; k++) {
            HFragB b;
            wmma::load_matrix_sync(b, gw + k * 16 * 264 + c0, 264);
            wmma::mma_sync(acc, a[k], b, acc);
        }
        wmma::store_matrix_sync(&fbp[w][0], acc, 16, wmma::mem_row_major);
        __syncwarp();
        int r = lane >> 1, cf = (lane & 1) * 8;
        const float* src = &fbp[w][r * 16 + cf];
        __half hb[8];
        #pragma unroll
        for (int j = 0; j < 8; j++) hb[j] = __float2half(src[j]);
        *(uint4*)&outh[(nb + rt * 16 + r) * HC + c0 + cf] = *(uint4*)hb;
        __syncwarp();
    }
}

// ---------------- edge MLP: per-warp pipeline, 2 blocks/SM -----------------
// smem halves: es   [128][16]  @0      2048
//              w1b  [16][72]   @2048   1152
//              w2b  [80][72]   @3200   5760
//              w3b  [80][72]   @8960   5760
//              hbuf [128][88]  @14720  11264  (end 25984 halves = 51968 B)
// fbw: 8 warps x 256 floats @51968 B (8192 B) => total 60160 B
__global__ void k_edgemlp(const float* __restrict__ eattr, int e) {
    extern __shared__ __half smh[];
    __half* es   = smh;
    __half* w1b  = smh + 2048;
    __half* w2b  = smh + 3200;
    __half* w3b  = smh + 8960;
    __half* hbuf = smh + 14720;
    float*  fbw  = (float*)(smh + 25984);

    int tid = threadIdx.x, w = tid >> 5, lane = tid & 31;
    float* fb = fbw + w * 256;
    int pb = blockIdx.x * 128;

    for (int i = tid; i < 576; i += 256)
        ((unsigned int*)w1b)[i] = ((const unsigned int*)g_ew1)[i];
    for (int i = tid; i < 2880; i += 256) {
        ((unsigned int*)w2b)[i] = ((const unsigned int*)g_ew2)[i];
        ((unsigned int*)w3b)[i] = ((const unsigned int*)g_ew3)[i];
    }
    for (int i = tid; i < 2048; i += 256) {
        int r = i >> 4, c = i & 15;
        float v = 0.f;
        if (c < 8) {
            int p = pb + r;
            if (p < e) v = __ldg(&eattr[g_eid[p] * 8 + c]);
        } else if (c == 8) v = 1.0f;
        es[i] = __float2half(v);
    }
    for (int i = tid; i < 3072; i += 256) {
        int r = i / 24, c = 64 + (i - r * 24);
        hbuf[r * 88 + c] = __float2half((c == 64) ? 1.0f : 0.f);
    }
    __syncthreads();

    int rowbase = w * 16;
    __half* hrow = &hbuf[rowbase * 88];
    int r = lane >> 1, cf = (lane & 1) * 8;

    // ---- layer 1 (k=16) ----
    {
        HFragA a;
        wmma::load_matrix_sync(a, &es[rowbase * 16], 16);
        #pragma unroll
        for (int nf = 0; nf < 4; nf++) {
            HFragC acc;
            wmma::fill_fragment(acc, 0.f);
            HFragB b;
            wmma::load_matrix_sync(b, &w1b[nf * 16], 72);
            wmma::mma_sync(acc, a, b, acc);
            wmma::store_matrix_sync(fb, acc, 16, wmma::mem_row_major);
            __syncwarp();
            const float* s = &fb[r * 16 + cf];
            __half h8[8];
            #pragma unroll
            for (int j = 0; j < 8; j++) h8[j] = __float2half(fmaxf(s[j], 0.f));
            *(uint2*)&hrow[r * 88 + nf * 16 + cf]     = *(uint2*)h8;
            *(uint2*)&hrow[r * 88 + nf * 16 + cf + 4] = *(uint2*)(h8 + 4);
            __syncwarp();
        }
    }

    // ---- layer 2 (k=80) ----
    {
        HFragA a[5];
        #pragma unroll
        for (int k = 0; k < 5; k++)
            wmma::load_matrix_sync(a[k], &hrow[k * 16], 88);
        #pragma unroll
        for (int nf = 0; nf < 4; nf++) {
            HFragC acc;
            wmma::fill_fragment(acc, 0.f);
            #pragma unroll
            for (int k = 0; k < 5; k++) {
                HFragB b;
                wmma::load_matrix_sync(b, &w2b[k * 16 * 72 + nf * 16], 72);
                wmma::mma_sync(acc, a[k], b, acc);
            }
            wmma::store_matrix_sync(fb, acc, 16, wmma::mem_row_major);
            __syncwarp();
            const float* s = &fb[r * 16 + cf];
            __half h8[8];
            #pragma unroll
            for (int j = 0; j < 8; j++) h8[j] = __float2half(fmaxf(s[j], 0.f));
            *(uint2*)&hrow[r * 88 + nf * 16 + cf]     = *(uint2*)h8;
            *(uint2*)&hrow[r * 88 + nf * 16 + cf + 4] = *(uint2*)(h8 + 4);
            __syncwarp();
        }
    }

    // ---- layer 3 (k=80) -> relu -> fp16 g_eh (direct) ----
    {
        HFragA a[5];
        #pragma unroll
        for (int k = 0; k < 5; k++)
            wmma::load_matrix_sync(a[k], &hrow[k * 16], 88);
        int grow = pb + rowbase + r;
        #pragma unroll
        for (int nf = 0; nf < 4; nf++) {
            HFragC acc;
            wmma::fill_fragment(acc, 0.f);
            #pragma unroll
            for (int k = 0; k < 5; k++) {
                HFragB b;
                wmma::load_matrix_sync(b, &w3b[k * 16 * 72 + nf * 16], 72);
                wmma::mma_sync(acc, a[k], b, acc);
            }
            wmma::store_matrix_sync(fb, acc, 16, wmma::mem_row_major);
            __syncwarp();
            const float* s = &fb[r * 16 + cf];
            __half h8[8];
            #pragma unroll
            for (int j = 0; j < 8; j++) h8[j] = __float2half(fmaxf(s[j], 0.f));
            *(uint4*)&g_eh[grow * 64 + nf * 16 + cf] = *(uint4*)h8;   // padded array
            __syncwarp();
        }
    }
}

// ---------------- attention ----------------
__device__ __forceinline__ float dot4(float4 a, float4 b) {
    return a.x * b.x + a.y * b.y + a.z * b.z + a.w * b.w;
}
__device__ __forceinline__ void ldh8(const __half* p, float4& a, float4& b) {
    uint4 u = *(const uint4*)p;
    float2 f0 = __half22float2(*(__half2*)&u.x);
    float2 f1 = __half22float2(*(__half2*)&u.y);
    float2 f2 = __half22float2(*(__half2*)&u.z);
    float2 f3 = __half22float2(*(__half2*)&u.w);
    a = make_float4(f0.x, f0.y, f1.x, f1.y);
    b = make_float4(f2.x, f2.y, f3.x, f3.y);
}
__device__ __forceinline__ void sth8(__half* p, float4 a, float4 b) {
    __half hb[8];
    hb[0] = __float2half(a.x); hb[1] = __float2half(a.y);
    hb[2] = __float2half(a.z); hb[3] = __float2half(a.w);
    hb[4] = __float2half(b.x); hb[5] = __float2half(b.y);
    hb[6] = __float2half(b.z); hb[7] = __float2half(b.w);
    *(uint4*)p = *(uint4*)hb;
}

__global__ void __launch_bounds__(256) k_attn(int n) {
    int gw = (blockIdx.x * blockDim.x + threadIdx.x) >> 5;
    int lane = threadIdx.x & 31;
    if (gw >= n) return;
    int node = gw;
    int beg = g_rowptr[node], end = g_rowptr[node + 1];

    int h = lane >> 3;
    int c8 = (lane & 7) * 8;
    int chan = h * 64 + c8;

    float4 q0, q1, gg0, gg1;
    ldh8(&g_qh[node * HC + chan], q0, q1);
    ldh8(&g_gh[node * HC + chan], gg0, gg1);
    float qb = g_qb[node * 4 + h];

    float s = 0.f;
    float4 av0 = {0,0,0,0}, av1 = {0,0,0,0};
    float4 at0 = {0,0,0,0}, at1 = {0,0,0,0};

    int p = beg;
    for (; p + 4 <= end; p += 4) {
        int src[4];
        #pragma unroll
        for (int u = 0; u < 4; u++) src[u] = g_src[p + u];

        float d[4];
        float4 e0[4], e1[4], v0[4], v1[4];
        #pragma unroll
        for (int u = 0; u < 4; u++) {
            float4 k0, k1;
            ldh8(&g_kh[src[u] * HC + chan], k0, k1);
            ldh8(&g_eh[(p + u) * 64 + c8], e0[u], e1[u]);
            ldh8(&g_vh[src[u] * HC + chan], v0[u], v1[u]);
            d[u] = dot4(q0, k0) + dot4(q1, k1) + dot4(gg0, e0[u]) + dot4(gg1, e1[u]);
        }
        #pragma unroll
        for (int off = 1; off < 8; off <<= 1) {
            #pragma unroll
            for (int u = 0; u < 4; u++)
                d[u] += __shfl_xor_sync(0xffffffffu, d[u], off);
        }
        float pe[4];
        #pragma unroll
        for (int u = 0; u < 4; u++) {
            pe[u] = __expf((d[u] + qb) * 0.125f);
            s += pe[u];
        }
        #pragma unroll
        for (int u = 0; u < 4; u++) {
            av0.x += pe[u] * v0[u].x;  av0.y += pe[u] * v0[u].y;
            av0.z += pe[u] * v0[u].z;  av0.w += pe[u] * v0[u].w;
            av1.x += pe[u] * v1[u].x;  av1.y += pe[u] * v1[u].y;
            av1.z += pe[u] * v1[u].z;  av1.w += pe[u] * v1[u].w;
            at0.x += pe[u] * e0[u].x;  at0.y += pe[u] * e0[u].y;
            at0.z += pe[u] * e0[u].z;  at0.w += pe[u] * e0[u].w;
            at1.x += pe[u] * e1[u].x;  at1.y += pe[u] * e1[u].y;
            at1.z += pe[u] * e1[u].z;  at1.w += pe[u] * e1[u].w;
        }
    }
    for (; p < end; p++) {
        int src = g_src[p];
        float4 k0, k1, e0, e1, v0, v1;
        ldh8(&g_kh[src * HC + chan], k0, k1);
        ldh8(&g_eh[p * 64 + c8],     e0, e1);
        ldh8(&g_vh[src * HC + chan], v0, v1);
        float d = dot4(q0, k0) + dot4(q1, k1) + dot4(gg0, e0) + dot4(gg1, e1);
        d += __shfl_xor_sync(0xffffffffu, d, 1);
        d += __shfl_xor_sync(0xffffffffu, d, 2);
        d += __shfl_xor_sync(0xffffffffu, d, 4);
        float pe = __expf((d + qb) * 0.125f);
        s += pe;
        av0.x += pe * v0.x; av0.y += pe * v0.y; av0.z += pe * v0.z; av0.w += pe * v0.w;
        av1.x += pe * v1.x; av1.y += pe * v1.y; av1.z += pe * v1.z; av1.w += pe * v1.w;
        at0.x += pe * e0.x; at0.y += pe * e0.y; at0.z += pe * e0.z; at0.w += pe * e0.w;
        at1.x += pe * e1.x; at1.y += pe * e1.y; at1.z += pe * e1.z; at1.w += pe * e1.w;
    }

    float sinv = 1.f / (s + 1e-16f);
    float4 o0 = {av0.x * sinv, av0.y * sinv, av0.z * sinv, av0.w * sinv};
    float4 o1 = {av1.x * sinv, av1.y * sinv, av1.z * sinv, av1.w * sinv};
    float4 t0 = {at0.x * sinv, at0.y * sinv, at0.z * sinv, at0.w * sinv};
    float4 t1 = {at1.x * sinv, at1.y * sinv, at1.z * sinv, at1.w * sinv};
    sth8(&g_outvh[node * HC + chan], o0, o1);
    sth8(&g_th   [node * HC + chan], t0, t1);
    if ((lane & 7) == 0) g_suma[node * 4 + h] = s * sinv;
}

// ---------------- fused epilogue (16 nodes/block) --------------------------
__global__ void k_posthead(const float* __restrict__ wedge, const float* __restrict__ bedge,
                           const float* __restrict__ ln_g, const float* __restrict__ ln_b,
                           const float* __restrict__ w1, const float* __restrict__ b1,
                           const float* __restrict__ w2, const float* __restrict__ b2,
                           float* __restrict__ out, int n) {
    __shared__ float ts[16 * HC];
    __shared__ float os[16 * HC];
    __shared__ float hs[16 * 128];
    __shared__ float ls[16][NCLS];
    int tid = threadIdx.x;
    int nb = blockIdx.x * 16;
    for (int i = tid; i < 16 * HC; i += 256) {
        int nn = nb + (i >> 8);
        ts[i] = (nn < n) ? __half2float(g_th[nn * HC + (i & 255)]) : 0.f;
    }
    __syncthreads();

    int h = tid >> 6;
    float acc[16];
    #pragma unroll
    for (int m = 0; m < 16; m++) acc[m] = 0.f;
    for (int i = 0; i < 64; i++) {
        float w = __ldg(&wedge[i * HC + tid]);
        #pragma unroll
        for (int m = 0; m < 16; m++) acc[m] += ts[m * HC + h * 64 + i] * w;
    }
    float be = __ldg(&bedge[tid]);
    #pragma unroll
    for (int m = 0; m < 16; m++) {
        int nn = nb + m;
        if (nn < n) {
            os[m * HC + tid] = __half2float(g_outvh[nn * HC + tid])
                             + g_suma[nn * 4 + h] * be
                             + __half2float(g_skiph[nn * HC + tid]) + acc[m];
        }
    }
    __syncthreads();

    int wid = tid >> 5, lane = tid & 31;
    for (int m = wid; m < 16; m += 8) {
        int nn = nb + m;
        if (nn >= n) continue;
        float sum = 0.f, sq = 0.f;
        #pragma unroll
        for (int u = 0; u < 8; u++) {
            float v = os[m * HC + u * 32 + lane];
            sum += v; sq += v * v;
        }
        #pragma unroll
        for (int off = 16; off; off >>= 1) {
            sum += __shfl_xor_sync(0xffffffffu, sum, off);
            sq  += __shfl_xor_sync(0xffffffffu, sq,  off);
        }
        float mu = sum * (1.f / 256.f);
        float var = sq * (1.f / 256.f) - mu * mu;
        float rs = rsqrtf(var + 1e-5f);
        #pragma unroll
        for (int u = 0; u < 8; u++) {
            int j = u * 32 + lane;
            float v = (os[m * HC + j] - mu) * rs * __ldg(&ln_g[j]) + __ldg(&ln_b[j]);
            ts[m * HC + j] = fmaxf(v, 0.f);
        }
    }
    __syncthreads();

    {
        int col = tid & 127, rg = tid >> 7;
        float a8[8];
        float bb = __ldg(&b1[col]);
        #pragma unroll
        for (int r = 0; r < 8; r++) a8[r] = bb;
        for (int i = 0; i < HC; i++) {
            float w = __ldg(&w1[i * 128 + col]);
            #pragma unroll
            for (int r = 0; r < 8; r++) a8[r] += ts[(rg * 8 + r) * HC + i] * w;
        }
        #pragma unroll
        for (int r = 0; r < 8; r++) hs[(rg * 8 + r) * 128 + col] = fmaxf(a8[r], 0.f);
    }
    __syncthreads();

    if (tid < 64) {
        int m = tid >> 2, c = tid & 3;
        float a = __ldg(&b2[c]);
        for (int i = 0; i < 128; i++) a += hs[m * 128 + i] * __ldg(&w2[i * NCLS + c]);
        ls[m][c] = a;
    }
    __syncthreads();
    if (tid < 16) {
        int nn = nb + tid;
        if (nn < n) {
            float l0 = ls[tid][0], l1 = ls[tid][1], l2 = ls[tid][2], l3 = ls[tid][3];
            float mx = fmaxf(fmaxf(l0, l1), fmaxf(l2, l3));
            float se = expf(l0 - mx) + expf(l1 - mx) + expf(l2 - mx) + expf(l3 - mx);
            float lse = mx + logf(se);
            out[nn * NCLS + 0] = l0 - lse;
            out[nn * NCLS + 1] = l1 - lse;
            out[nn * NCLS + 2] = l2 - lse;
            out[nn * NCLS + 3] = l3 - lse;
        }
    }
}

// ---------------- launcher ----------------
extern "C" void kernel_launch(void* const* d_in, const int* in_sizes, int n_in,
                              void* d_out, int out_size) {
    const float* x     = (const float*)d_in[0];
    const int*   ei    = (const int*)  d_in[1];
    const float* eattr = (const float*)d_in[2];
    const float* w00   = (const float*)d_in[3];
    const float* b00   = (const float*)d_in[4];
    const float* we1   = (const float*)d_in[5];
    const float* be1   = (const float*)d_in[6];
    const float* we2   = (const float*)d_in[7];
    const float* be2   = (const float*)d_in[8];
    const float* we3   = (const float*)d_in[9];
    const float* be3   = (const float*)d_in[10];
    const float* wq    = (const float*)d_in[11];
    const float* bq    = (const float*)d_in[12];
    const float* wk    = (const float*)d_in[13];
    const float* bk    = (const float*)d_in[14];
    const float* wv    = (const float*)d_in[15];
    const float* bv    = (const float*)d_in[16];
    const float* wedge = (const float*)d_in[17];
    const float* bedge = (const float*)d_in[18];
    const float* wskip = (const float*)d_in[19];
    const float* bskip = (const float*)d_in[20];
    const float* ln_g  = (const float*)d_in[21];
    const float* ln_b  = (const float*)d_in[22];
    const float* w1    = (const float*)d_in[23];
    const float* b1    = (const float*)d_in[24];
    const float* w2    = (const float*)d_in[25];
    const float* b2    = (const float*)d_in[26];
    float* out = (float*)d_out;

    int n = in_sizes[0] / NFEAT;
    int e = in_sizes[1] / 2;
    int nblk = (n + 255) / 256;

    static cudaStream_t sB = nullptr;
    static cudaEvent_t evF = nullptr, evJ = nullptr;
    static bool attrs_set = false;
    if (sB == nullptr) {
        cudaStreamCreateWithFlags(&sB, cudaStreamNonBlocking);
        cudaEventCreateWithFlags(&evF, cudaEventDisableTiming);
        cudaEventCreateWithFlags(&evJ, cudaEventDisableTiming);
    }
    static const int EDGE_SMEM = 60160;
    if (!attrs_set) {
        cudaFuncSetAttribute(k_edgemlp, cudaFuncAttributeMaxDynamicSharedMemorySize, EDGE_SMEM);
        attrs_set = true;
    }

    // fork
    cudaEventRecord(evF, 0);
    cudaStreamWaitEvent(sB, evF, 0);

    // ---- stream B: node pipeline ----
    k_foldw<<<65, 256, 0, sB>>>(wq, bq, wedge);
    k_foldqb<<<1, 256, 0, sB>>>(wq, bq, bedge);
    {
        dim3 gridc((80 * 264 + 255) / 256, 5);
        k_cvtw<<<gridc, 256, 0, sB>>>(wq, bq, wk, bk, wv, bv, wskip, bskip);
    }
    k_node_embed<<<(n + 63) / 64, 256, 0, sB>>>(x, w00, b00, n);
    {
        dim3 grid((n + 63) / 64, 5);
        k_proj<<<grid, 256, 0, sB>>>(n);
    }
    k_qb<<<(n + 63) / 64, 256, 0, sB>>>(n);
    cudaEventRecord(evJ, sB);

    // ---- capture stream: CSR build + edge MLP ----
    k_cvte<<<(12672 + 255) / 256, 256>>>(we1, be1, we2, be2, we3, be3);
    k_zero_deg<<<(n + 255) / 256, 256>>>(n);
    k_hist<<<(e + 255) / 256, 256>>>(ei, e);
    k_blocksum<<<nblk, 256>>>(n);
    k_scanpart<<<1, 256>>>(nblk);
    k_scanfinal<<<nblk, 256>>>(n);
    k_scatter<<<(e + 255) / 256, 256>>>(ei, e);
    k_edgemlp<<<(e + 127) / 128, 256, EDGE_SMEM>>>(eattr, e);

    // join
    cudaStreamWaitEvent(0, evJ, 0);

    k_attn<<<(n + 7) / 8, 256>>>(n);
    k_posthead<<<(n + 15) / 16, 256>>>(wedge, bedge, ln_g, ln_b, w1, b1, w2, b2, out, n);
}